// round 7
// baseline (speedup 1.0000x reference)
#include <cuda_runtime.h>
#include <cuda_bf16.h>
#include <math_constants.h>

#define B_  4
#define S_  4096
#define D_  256
#define H_  4
#define DH_ 64
#define MT_ (B_ * S_)
#define BH_ (B_ * H_)
#define LOG2E 1.4426950408889634f

typedef unsigned int       u32;
typedef unsigned long long u64;

// ---------------------------------------------------------------------------
// Scratch: bf16 hi/lo split, packed u32 = {hi16: odd col, lo16: even col}
// ---------------------------------------------------------------------------
#define QKV_WORDS ((size_t)BH_ * S_ * (DH_ / 2))
#define ROW_WORDS (D_ / 2)
__device__ u32 g_Qh[QKV_WORDS];  __device__ u32 g_Ql[QKV_WORDS];
__device__ u32 g_Kh[QKV_WORDS];  __device__ u32 g_Kl[QKV_WORDS];
__device__ u32 g_Vh[QKV_WORDS];  __device__ u32 g_Vl[QKV_WORDS];
__device__ u32 g_Xh[(size_t)MT_ * ROW_WORDS];
__device__ u32 g_Xl[(size_t)MT_ * ROW_WORDS];
__device__ u32 g_Ah[(size_t)MT_ * ROW_WORDS];
__device__ u32 g_Al[(size_t)MT_ * ROW_WORDS];
__device__ u32 g_Wth[4 * 256 * ROW_WORDS];
__device__ u32 g_Wtl[4 * 256 * ROW_WORDS];

// ---------------------------------------------------------------------------
// PTX helpers (baseline PTX only)
// ---------------------------------------------------------------------------
__device__ __forceinline__ u32 smem_u32(const void* p) {
    u32 a;
    asm("{ .reg .u64 t; cvta.to.shared.u64 t, %1; cvt.u32.u64 %0, t; }"
        : "=r"(a) : "l"(p));
    return a;
}
__device__ __forceinline__ u32 cvt2(float a, float b) {   // {hi=bf16(a), lo=bf16(b)}
    u32 r;
    asm("cvt.rn.bf16x2.f32 %0, %1, %2;" : "=r"(r) : "f"(a), "f"(b));
    return r;
}
__device__ __forceinline__ float bflo(u32 w) { return __uint_as_float(w << 16); }
__device__ __forceinline__ float bfhi(u32 w) { return __uint_as_float(w & 0xffff0000u); }
__device__ __forceinline__ float ex2f(float x) {
    float y; asm("ex2.approx.f32 %0, %1;" : "=f"(y) : "f"(x)); return y;
}
__device__ __forceinline__ void mma_bf16(float c[4], const u32 a[4], u32 b0, u32 b1) {
    asm volatile(
        "mma.sync.aligned.m16n8k16.row.col.f32.bf16.bf16.f32 "
        "{%0,%1,%2,%3},{%4,%5,%6,%7},{%8,%9},{%0,%1,%2,%3};"
        : "+f"(c[0]), "+f"(c[1]), "+f"(c[2]), "+f"(c[3])
        : "r"(a[0]), "r"(a[1]), "r"(a[2]), "r"(a[3]), "r"(b0), "r"(b1));
}
#define LDSM_X4(r0, r1, r2, r3, a) \
    asm volatile("ldmatrix.sync.aligned.m8n8.x4.shared.b16 {%0,%1,%2,%3}, [%4];" \
                 : "=r"(r0), "=r"(r1), "=r"(r2), "=r"(r3) : "r"(a))
#define LDSM_A(fr, a) LDSM_X4(fr[0], fr[1], fr[2], fr[3], a)
#define LDSM_X4T(r0, r1, r2, r3, a) \
    asm volatile("ldmatrix.sync.aligned.m8n8.x4.trans.shared.b16 {%0,%1,%2,%3}, [%4];" \
                 : "=r"(r0), "=r"(r1), "=r"(r2), "=r"(r3) : "r"(a))
__device__ __forceinline__ void cp16(u32 dst, const void* src) {
    asm volatile("cp.async.cg.shared.global [%0], [%1], 16;" :: "r"(dst), "l"(src));
}
#define CP_COMMIT() asm volatile("cp.async.commit_group;" ::: "memory")
#define CP_WAIT(n)  asm volatile("cp.async.wait_group %0;" :: "n"(n) : "memory")

__device__ __forceinline__ u32 swz(int row, int chunk) {
    return (u32)(row * 128 + (((chunk ^ row) & 7) << 4));
}

// ---------------------------------------------------------------------------
// Kernel 0: prep — split X; transpose+split W matrices.
// ---------------------------------------------------------------------------
#define XWORDS (2097152)
#define WWORDS (131072)
__global__ void __launch_bounds__(256) prep_kernel(
    const float* __restrict__ X,
    const float* __restrict__ Wq, const float* __restrict__ Wk,
    const float* __restrict__ Wv, const float* __restrict__ Wo)
{
    const int w = blockIdx.x * 256 + threadIdx.x;
    if (w < XWORDS) {
        float2 f = ((const float2*)X)[w];
        u32 hi = cvt2(f.y, f.x);
        g_Xh[w] = hi;
        g_Xl[w] = cvt2(f.y - bfhi(hi), f.x - bflo(hi));
    } else if (w < XWORDS + WWORDS) {
        int u = w - XWORDS;
        int z = u >> 15, r = u & 32767;
        int n = r >> 7, kp = r & 127;
        const float* Wm = (z == 0) ? Wq : (z == 1) ? Wk : (z == 2) ? Wv : Wo;
        float f0 = Wm[(size_t)(2 * kp)     * 256 + n];
        float f1 = Wm[(size_t)(2 * kp + 1) * 256 + n];
        u32 hi = cvt2(f1, f0);
        g_Wth[u] = hi;
        g_Wtl[u] = cvt2(f1 - bfhi(hi), f0 - bflo(hi));
    }
}

// ---------------------------------------------------------------------------
// HMMA GEMM core — 256 threads (8 warps x 16 rows), tile M=128 x N=64, K=256.
// smem: AH 16K | AL 16K | BH 8K | BL 8K = 48KB x 2 buffers = 96KB.
// ---------------------------------------------------------------------------
#define GB_AH 0
#define GB_AL 16384
#define GB_BH 32768
#define GB_BL 40960
#define GBUF  49152
#define GEMM_SMEM (2 * GBUF)

__device__ __forceinline__ void gemm_stage(u32 sb, int bufi, int kb,
                                           const u32* Ah, const u32* Al,
                                           const u32* Bh, const u32* Bl,
                                           int m0, int n0, int tid)
{
    const u32 bufb = sb + bufi * GBUF;
    #pragma unroll
    for (int i = 0; i < 4; i++) {
        int idx = tid + i * 256;           // < 1024
        int r = idx >> 3, c = idx & 7;
        const size_t go = (size_t)(m0 + r) * ROW_WORDS + kb * 32 + c * 4;
        cp16(bufb + GB_AH + swz(r, c), Ah + go);
        cp16(bufb + GB_AL + swz(r, c), Al + go);
    }
    #pragma unroll
    for (int i = 0; i < 2; i++) {
        int idx = tid + i * 256;           // < 512
        int r = idx >> 3, c = idx & 7;
        const size_t go = (size_t)(n0 + r) * ROW_WORDS + kb * 32 + c * 4;
        cp16(bufb + GB_BH + swz(r, c), Bh + go);
        cp16(bufb + GB_BL + swz(r, c), Bl + go);
    }
}

// acc[8][4] per warp (16 rows x 64 cols); caller zeroes.
__device__ __forceinline__ void gemm_main(u32 sb, float acc[8][4],
                                          const u32* Ah, const u32* Al,
                                          const u32* Bh, const u32* Bl,
                                          int m0, int n0, int tid)
{
    const int w  = tid >> 5;
    const int L  = tid & 31;
    const int rt = L & 7;
    const int lb = (L >> 3) & 1;
    const int lc = L >> 4;

    gemm_stage(sb, 0, 0, Ah, Al, Bh, Bl, m0, n0, tid);
    CP_COMMIT();
    gemm_stage(sb, 1, 1, Ah, Al, Bh, Bl, m0, n0, tid);
    CP_COMMIT();

    for (int kb = 0; kb < 4; kb++) {
        CP_WAIT(1);
        __syncthreads();
        const u32 bufb = sb + (kb & 1) * GBUF;
        const u32 aAH = bufb + GB_AH, aAL = bufb + GB_AL;
        const u32 aBH = bufb + GB_BH, aBL = bufb + GB_BL;

        #pragma unroll
        for (int j = 0; j < 4; j++) {
            u32 ah[4], al[4];
            int arow = w * 16 + rt + lb * 8;
            LDSM_A(ah, aAH + swz(arow, 2 * j + lc));
            LDSM_A(al, aAL + swz(arow, 2 * j + lc));
            #pragma unroll
            for (int p = 0; p < 4; p++) {
                int row = 16 * p + rt + lc * 8;
                int ch  = 2 * j + lb;
                u32 bh0, bh1, bh2, bh3, bl0, bl1, bl2, bl3;
                LDSM_X4(bh0, bh1, bh2, bh3, aBH + swz(row, ch));
                LDSM_X4(bl0, bl1, bl2, bl3, aBL + swz(row, ch));
                mma_bf16(acc[2*p],   ah, bh0, bh1);
                mma_bf16(acc[2*p+1], ah, bh2, bh3);
                mma_bf16(acc[2*p],   al, bh0, bh1);
                mma_bf16(acc[2*p+1], al, bh2, bh3);
                mma_bf16(acc[2*p],   ah, bl0, bl1);
                mma_bf16(acc[2*p+1], ah, bl2, bl3);
            }
        }
        __syncthreads();
        if (kb + 2 < 4)
            gemm_stage(sb, kb & 1, kb + 2, Ah, Al, Bh, Bl, m0, n0, tid);
        CP_COMMIT();
    }
}

// ---------------------------------------------------------------------------
// Kernel 1: QKV projection. grid (MT/128, H, 3), block 256.
// ---------------------------------------------------------------------------
__global__ void __launch_bounds__(256, 2) qkv_hmma(
    const float* __restrict__ bq, const float* __restrict__ bk,
    const float* __restrict__ bv)
{
    extern __shared__ char sm[];
    const u32 sb  = smem_u32(sm);
    const int tid = threadIdx.x;
    const int z   = blockIdx.z;
    const int h   = blockIdx.y;
    const int m0  = blockIdx.x * 128;
    const int n0  = h * 64;

    const float* bias = (z == 0) ? bq : (z == 1) ? bk : bv;
    u32* oh = (z == 0) ? g_Qh : (z == 1) ? g_Kh : g_Vh;
    u32* ol = (z == 0) ? g_Ql : (z == 1) ? g_Kl : g_Vl;
    const float qs = (z == 0) ? (0.125f * LOG2E) : 1.0f;

    float acc[8][4];
    #pragma unroll
    for (int t = 0; t < 8; t++)
        #pragma unroll
        for (int e = 0; e < 4; e++) acc[t][e] = 0.0f;

    gemm_main(sb, acc, g_Xh, g_Xl,
              g_Wth + (size_t)z * 256 * ROW_WORDS,
              g_Wtl + (size_t)z * 256 * ROW_WORDS, m0, n0, tid);

    const int w  = tid >> 5;
    const int L  = tid & 31;
    const int lr = L >> 2, lcq = L & 3;
    float b2[8][2];
    #pragma unroll
    for (int t = 0; t < 8; t++) {
        b2[t][0] = bias[n0 + 8 * t + lcq * 2];
        b2[t][1] = bias[n0 + 8 * t + lcq * 2 + 1];
    }
    const int bb = m0 >> 12;
    const int sbase = m0 & (S_ - 1);
    #pragma unroll
    for (int half = 0; half < 2; half++) {
        int s = sbase + w * 16 + lr + half * 8;
        size_t rw = ((size_t)(bb * H_ + h) * S_ + s) * 32 + lcq;
        #pragma unroll
        for (int t = 0; t < 8; t++) {
            float v0 = (acc[t][half * 2 + 0] + b2[t][0]) * qs;
            float v1 = (acc[t][half * 2 + 1] + b2[t][1]) * qs;
            u32 hi = cvt2(v1, v0);
            oh[rw + 4 * t] = hi;
            ol[rw + 4 * t] = cvt2(v1 - bfhi(hi), v0 - bflo(hi));
        }
    }
}

// ---------------------------------------------------------------------------
// Kernel 3: output projection. grid (MT/128, 4), block 256.
// ---------------------------------------------------------------------------
__global__ void __launch_bounds__(256, 2) out_hmma(
    const float* __restrict__ bo, float* __restrict__ out)
{
    extern __shared__ char sm[];
    const u32 sb  = smem_u32(sm);
    const int tid = threadIdx.x;
    const int m0  = blockIdx.x * 128;
    const int n0  = blockIdx.y * 64;

    float acc[8][4];
    #pragma unroll
    for (int t = 0; t < 8; t++)
        #pragma unroll
        for (int e = 0; e < 4; e++) acc[t][e] = 0.0f;

    gemm_main(sb, acc, g_Ah, g_Al,
              g_Wth + (size_t)3 * 256 * ROW_WORDS,
              g_Wtl + (size_t)3 * 256 * ROW_WORDS, m0, n0, tid);

    const int w  = tid >> 5;
    const int L  = tid & 31;
    const int lr = L >> 2, lcq = L & 3;
    float b2[8][2];
    #pragma unroll
    for (int t = 0; t < 8; t++) {
        b2[t][0] = bo[n0 + 8 * t + lcq * 2];
        b2[t][1] = bo[n0 + 8 * t + lcq * 2 + 1];
    }
    #pragma unroll
    for (int half = 0; half < 2; half++) {
        int m = m0 + w * 16 + lr + half * 8;
        float* orow = out + (size_t)m * D_ + n0 + lcq * 2;
        #pragma unroll
        for (int t = 0; t < 8; t++) {
            float2 v;
            v.x = acc[t][half * 2 + 0] + b2[t][0];
            v.y = acc[t][half * 2 + 1] + b2[t][1];
            *(float2*)&orow[8 * t] = v;
        }
    }
}

// ---------------------------------------------------------------------------
// Kernel 2: flash attention. BQ=128 (8 warps x 16 rows), BK=64.
// grid (S/128, BH), block 256, 2 CTAs/SM. smem: 2 x 32KB KV buffers.
// ---------------------------------------------------------------------------
#define BUF_STRIDE 32768
#define ATTN_SMEM  (2 * 32768)

__global__ void __launch_bounds__(256, 2) attn_kernel()
{
    extern __shared__ char sm[];
    const u32 sb  = smem_u32(sm);
    const int tid = threadIdx.x;
    const int w   = tid >> 5;
    const int L   = tid & 31;
    const int bh  = blockIdx.y;
    const int q0  = blockIdx.x * 128;

    const size_t head = (size_t)bh * S_ * (DH_ / 2);
    const u32* Qh = g_Qh + head; const u32* Ql = g_Ql + head;
    const u32* Kh = g_Kh + head; const u32* Kl = g_Kl + head;
    const u32* Vh = g_Vh + head; const u32* Vl = g_Vl + head;

    const int rt = L & 7;
    const int lb = (L >> 3) & 1;
    const int lc = L >> 4;

    // ---- prologue: stage Q (128 rows, hi+lo = 32KB) through buf0 ----
    #pragma unroll
    for (int i = 0; i < 4; i++) {
        int idx = tid + i * 256;           // < 1024
        int r = idx >> 3, c = idx & 7;
        cp16(sb + swz(r, c),         Qh + (size_t)(q0 + r) * 32 + c * 4);
        cp16(sb + 16384 + swz(r, c), Ql + (size_t)(q0 + r) * 32 + c * 4);
    }
    CP_COMMIT();
    CP_WAIT(0);
    __syncthreads();

    u32 qh[4][4], ql[4][4];
    #pragma unroll
    for (int j = 0; j < 4; j++) {
        int row = w * 16 + rt + lb * 8;
        LDSM_A(qh[j], sb + swz(row, 2 * j + lc));
        LDSM_A(ql[j], sb + 16384 + swz(row, 2 * j + lc));
    }
    __syncthreads();   // Q fully read before buf0 reuse

    const u32* kvsrc[4] = {Kh, Kl, Vh, Vl};
    #pragma unroll
    for (int t0 = 0; t0 < 2; t0++) {
        u32 bufb = sb + t0 * BUF_STRIDE;
        #pragma unroll
        for (int m = 0; m < 4; m++)
            #pragma unroll
            for (int i = 0; i < 2; i++) {
                int idx = tid + i * 256;   // < 512
                int r = idx >> 3, c = idx & 7;
                cp16(bufb + m * 8192 + swz(r, c),
                     kvsrc[m] + (size_t)(t0 * 64 + r) * 32 + c * 4);
            }
        CP_COMMIT();
    }

    float oacc[8][4];
    #pragma unroll
    for (int t = 0; t < 8; t++)
        #pragma unroll
        for (int e = 0; e < 4; e++) oacc[t][e] = 0.0f;
    float m_lo = -CUDART_INF_F, m_hi = -CUDART_INF_F;
    float l_lo = 0.0f, l_hi = 0.0f;

    const int NT = S_ / 64;
    for (int it = 0; it < NT; it++) {
        CP_WAIT(1);
        __syncthreads();
        const u32 bufb = sb + (it & 1) * BUF_STRIDE;
        const u32 aKH = bufb, aKL = bufb + 8192;
        const u32 aVH = bufb + 16384, aVL = bufb + 24576;

        // ---- S = Q K^T (3-split) ----
        float sacc[8][4];
        #pragma unroll
        for (int t = 0; t < 8; t++)
            #pragma unroll
            for (int e = 0; e < 4; e++) sacc[t][e] = 0.0f;

        #pragma unroll
        for (int j = 0; j < 4; j++) {
            #pragma unroll
            for (int p = 0; p < 4; p++) {
                int row = 16 * p + rt + lc * 8;
                int ch  = 2 * j + lb;
                u32 kh0, kh1, kh2, kh3, kl0, kl1, kl2, kl3;
                LDSM_X4(kh0, kh1, kh2, kh3, aKH + swz(row, ch));
                LDSM_X4(kl0, kl1, kl2, kl3, aKL + swz(row, ch));
                mma_bf16(sacc[2*p],   qh[j], kh0, kh1);
                mma_bf16(sacc[2*p+1], qh[j], kh2, kh3);
                mma_bf16(sacc[2*p],   ql[j], kh0, kh1);
                mma_bf16(sacc[2*p+1], ql[j], kh2, kh3);
                mma_bf16(sacc[2*p],   qh[j], kl0, kl1);
                mma_bf16(sacc[2*p+1], qh[j], kl2, kl3);
            }
        }

        // ---- row max (log2 domain) ----
        float mlo = -CUDART_INF_F, mhi = -CUDART_INF_F;
        #pragma unroll
        for (int t = 0; t < 8; t++) {
            mlo = fmaxf(mlo, fmaxf(sacc[t][0], sacc[t][1]));
            mhi = fmaxf(mhi, fmaxf(sacc[t][2], sacc[t][3]));
        }
        mlo = fmaxf(mlo, __shfl_xor_sync(0xffffffffu, mlo, 1));
        mlo = fmaxf(mlo, __shfl_xor_sync(0xffffffffu, mlo, 2));
        mhi = fmaxf(mhi, __shfl_xor_sync(0xffffffffu, mhi, 1));
        mhi = fmaxf(mhi, __shfl_xor_sync(0xffffffffu, mhi, 2));

        float mnlo = fmaxf(m_lo, mlo), mnhi = fmaxf(m_hi, mhi);
        float clo = ex2f(m_lo - mnlo), chi = ex2f(m_hi - mnhi);
        m_lo = mnlo; m_hi = mnhi;

        #pragma unroll
        for (int t = 0; t < 8; t++) {
            oacc[t][0] *= clo; oacc[t][1] *= clo;
            oacc[t][2] *= chi; oacc[t][3] *= chi;
        }

        // ---- PV with just-in-time P conversion ----
        float alo = 0.0f, ahi = 0.0f;
        #pragma unroll
        for (int j = 0; j < 4; j++) {
            u32 pa[4], pb[4];
            #pragma unroll
            for (int tt = 0; tt < 2; tt++) {
                const float* sv = sacc[2 * j + tt];
                float p0 = ex2f(sv[0] - mnlo);
                float p1 = ex2f(sv[1] - mnlo);
                float p2 = ex2f(sv[2] - mnhi);
                float p3 = ex2f(sv[3] - mnhi);
                alo += p0 + p1; ahi += p2 + p3;
                u32 h0 = cvt2(p1, p0), h1 = cvt2(p3, p2);
                pa[2 * tt]     = h0;
                pa[2 * tt + 1] = h1;
                pb[2 * tt]     = cvt2(p1 - bfhi(h0), p0 - bflo(h0));
                pb[2 * tt + 1] = cvt2(p3 - bfhi(h1), p2 - bflo(h1));
            }
            int row = 16 * j + rt + lb * 8;
            #pragma unroll
            for (int t = 0; t < 4; t++) {
                int ch = 2 * t + lc;
                u32 vh0, vh1, vh2, vh3, vl0, vl1, vl2, vl3;
                LDSM_X4T(vh0, vh1, vh2, vh3, aVH + swz(row, ch));
                LDSM_X4T(vl0, vl1, vl2, vl3, aVL + swz(row, ch));
                mma_bf16(oacc[2*t],   pa, vh0, vh1);
                mma_bf16(oacc[2*t+1], pa, vh2, vh3);
                mma_bf16(oacc[2*t],   pb, vh0, vh1);
                mma_bf16(oacc[2*t+1], pb, vh2, vh3);
                mma_bf16(oacc[2*t],   pa, vl0, vl1);
                mma_bf16(oacc[2*t+1], pa, vl2, vl3);
            }
        }
        l_lo = l_lo * clo + alo;
        l_hi = l_hi * chi + ahi;

        __syncthreads();
        if (it + 2 < NT) {
            u32 bb2 = sb + (it & 1) * BUF_STRIDE;
            int j2 = (it + 2) * 64;
            #pragma unroll
            for (int m = 0; m < 4; m++)
                #pragma unroll
                for (int i = 0; i < 2; i++) {
                    int idx = tid + i * 256;
                    int r = idx >> 3, c = idx & 7;
                    cp16(bb2 + m * 8192 + swz(r, c),
                         kvsrc[m] + (size_t)(j2 + r) * 32 + c * 4);
                }
        }
        CP_COMMIT();
    }

    // ---- epilogue: normalize, split to bf16 hi/lo, write g_Ah/g_Al ----
    float llo = l_lo + __shfl_xor_sync(0xffffffffu, l_lo, 1);
    llo += __shfl_xor_sync(0xffffffffu, llo, 2);
    float lhi = l_hi + __shfl_xor_sync(0xffffffffu, l_hi, 1);
    lhi += __shfl_xor_sync(0xffffffffu, lhi, 2);
    const float ilo = 1.0f / llo, ihi = 1.0f / lhi;

    const int bb = bh >> 2, h = bh & 3;
    const int rlo = q0 + w * 16 + (L >> 2);
    const size_t rw0 = ((size_t)(bb * S_) + rlo) * ROW_WORDS + h * 32 + (L & 3);
    const size_t rw1 = rw0 + 8 * ROW_WORDS;
    #pragma unroll
    for (int t = 0; t < 8; t++) {
        float o0 = oacc[t][0] * ilo, o1 = oacc[t][1] * ilo;
        float o2 = oacc[t][2] * ihi, o3 = oacc[t][3] * ihi;
        u32 h0 = cvt2(o1, o0), h1 = cvt2(o3, o2);
        g_Ah[rw0 + 4 * t] = h0;
        g_Al[rw0 + 4 * t] = cvt2(o1 - bfhi(h0), o0 - bflo(h0));
        g_Ah[rw1 + 4 * t] = h1;
        g_Al[rw1 + 4 * t] = cvt2(o3 - bfhi(h1), o2 - bflo(h1));
    }
}

// ---------------------------------------------------------------------------
// Launch
// ---------------------------------------------------------------------------
extern "C" void kernel_launch(void* const* d_in, const int* in_sizes, int n_in,
                              void* d_out, int out_size)
{
    const float* X  = (const float*)d_in[0];
    const float* Wq = (const float*)d_in[1];
    const float* bq = (const float*)d_in[2];
    const float* Wk = (const float*)d_in[3];
    const float* bk = (const float*)d_in[4];
    const float* Wv = (const float*)d_in[5];
    const float* bv = (const float*)d_in[6];
    const float* Wo = (const float*)d_in[7];
    const float* bo = (const float*)d_in[8];
    float* out = (float*)d_out;

    cudaFuncSetAttribute(attn_kernel,
                         cudaFuncAttributeMaxDynamicSharedMemorySize, ATTN_SMEM);
    cudaFuncSetAttribute(qkv_hmma,
                         cudaFuncAttributeMaxDynamicSharedMemorySize, GEMM_SMEM);
    cudaFuncSetAttribute(out_hmma,
                         cudaFuncAttributeMaxDynamicSharedMemorySize, GEMM_SMEM);

    prep_kernel<<<(XWORDS + WWORDS + 255) / 256, 256>>>(X, Wq, Wk, Wv, Wo);
    qkv_hmma<<<dim3(MT_ / 128, H_, 3), 256, GEMM_SMEM>>>(bq, bk, bv);
    attn_kernel<<<dim3(S_ / 128, BH_), 256, ATTN_SMEM>>>();
    out_hmma<<<dim3(MT_ / 128, 4), 256, GEMM_SMEM>>>(bo, out);
}

// round 8
// speedup vs baseline: 1.0653x; 1.0653x over previous
#include <cuda_runtime.h>
#include <cuda_bf16.h>
#include <math_constants.h>

#define B_  4
#define S_  4096
#define D_  256
#define H_  4
#define DH_ 64
#define MT_ (B_ * S_)
#define BH_ (B_ * H_)
#define LOG2E 1.4426950408889634f

typedef unsigned int       u32;
typedef unsigned long long u64;

// ---------------------------------------------------------------------------
// Scratch: bf16 hi/lo split, packed u32 = {hi16: odd col, lo16: even col}
// ---------------------------------------------------------------------------
#define QKV_WORDS ((size_t)BH_ * S_ * (DH_ / 2))
#define ROW_WORDS (D_ / 2)
__device__ u32 g_Qh[QKV_WORDS];  __device__ u32 g_Ql[QKV_WORDS];
__device__ u32 g_Kh[QKV_WORDS];  __device__ u32 g_Kl[QKV_WORDS];
__device__ u32 g_Vh[QKV_WORDS];  __device__ u32 g_Vl[QKV_WORDS];
__device__ u32 g_Xh[(size_t)MT_ * ROW_WORDS];
__device__ u32 g_Xl[(size_t)MT_ * ROW_WORDS];
__device__ u32 g_Ah[(size_t)MT_ * ROW_WORDS];
__device__ u32 g_Al[(size_t)MT_ * ROW_WORDS];
__device__ u32 g_Wth[4 * 256 * ROW_WORDS];
__device__ u32 g_Wtl[4 * 256 * ROW_WORDS];

// ---------------------------------------------------------------------------
// PTX helpers (baseline PTX only)
// ---------------------------------------------------------------------------
__device__ __forceinline__ u32 smem_u32(const void* p) {
    u32 a;
    asm("{ .reg .u64 t; cvta.to.shared.u64 t, %1; cvt.u32.u64 %0, t; }"
        : "=r"(a) : "l"(p));
    return a;
}
__device__ __forceinline__ u32 cvt2(float a, float b) {   // {hi=bf16(a), lo=bf16(b)}
    u32 r;
    asm("cvt.rn.bf16x2.f32 %0, %1, %2;" : "=r"(r) : "f"(a), "f"(b));
    return r;
}
__device__ __forceinline__ float bflo(u32 w) { return __uint_as_float(w << 16); }
__device__ __forceinline__ float bfhi(u32 w) { return __uint_as_float(w & 0xffff0000u); }
__device__ __forceinline__ float ex2f(float x) {
    float y; asm("ex2.approx.f32 %0, %1;" : "=f"(y) : "f"(x)); return y;
}
__device__ __forceinline__ void mma_bf16(float c[4], const u32 a[4], u32 b0, u32 b1) {
    asm volatile(
        "mma.sync.aligned.m16n8k16.row.col.f32.bf16.bf16.f32 "
        "{%0,%1,%2,%3},{%4,%5,%6,%7},{%8,%9},{%0,%1,%2,%3};"
        : "+f"(c[0]), "+f"(c[1]), "+f"(c[2]), "+f"(c[3])
        : "r"(a[0]), "r"(a[1]), "r"(a[2]), "r"(a[3]), "r"(b0), "r"(b1));
}
#define LDSM_X4(r0, r1, r2, r3, a) \
    asm volatile("ldmatrix.sync.aligned.m8n8.x4.shared.b16 {%0,%1,%2,%3}, [%4];" \
                 : "=r"(r0), "=r"(r1), "=r"(r2), "=r"(r3) : "r"(a))
#define LDSM_A(fr, a) LDSM_X4(fr[0], fr[1], fr[2], fr[3], a)
#define LDSM_X4T(r0, r1, r2, r3, a) \
    asm volatile("ldmatrix.sync.aligned.m8n8.x4.trans.shared.b16 {%0,%1,%2,%3}, [%4];" \
                 : "=r"(r0), "=r"(r1), "=r"(r2), "=r"(r3) : "r"(a))
__device__ __forceinline__ void cp16(u32 dst, const void* src) {
    asm volatile("cp.async.cg.shared.global [%0], [%1], 16;" :: "r"(dst), "l"(src));
}
#define CP_COMMIT() asm volatile("cp.async.commit_group;" ::: "memory")
#define CP_WAIT(n)  asm volatile("cp.async.wait_group %0;" :: "n"(n) : "memory")

__device__ __forceinline__ u32 swz(int row, int chunk) {
    return (u32)(row * 128 + (((chunk ^ row) & 7) << 4));
}

// ---------------------------------------------------------------------------
// Kernel 0: prep — split X; transpose+split W matrices.
// ---------------------------------------------------------------------------
#define XWORDS (2097152)
#define WWORDS (131072)
__global__ void __launch_bounds__(256) prep_kernel(
    const float* __restrict__ X,
    const float* __restrict__ Wq, const float* __restrict__ Wk,
    const float* __restrict__ Wv, const float* __restrict__ Wo)
{
    const int w = blockIdx.x * 256 + threadIdx.x;
    if (w < XWORDS) {
        float2 f = ((const float2*)X)[w];
        u32 hi = cvt2(f.y, f.x);
        g_Xh[w] = hi;
        g_Xl[w] = cvt2(f.y - bfhi(hi), f.x - bflo(hi));
    } else if (w < XWORDS + WWORDS) {
        int u = w - XWORDS;
        int z = u >> 15, r = u & 32767;
        int n = r >> 7, kp = r & 127;
        const float* Wm = (z == 0) ? Wq : (z == 1) ? Wk : (z == 2) ? Wv : Wo;
        float f0 = Wm[(size_t)(2 * kp)     * 256 + n];
        float f1 = Wm[(size_t)(2 * kp + 1) * 256 + n];
        u32 hi = cvt2(f1, f0);
        g_Wth[u] = hi;
        g_Wtl[u] = cvt2(f1 - bfhi(hi), f0 - bflo(hi));
    }
}

// ---------------------------------------------------------------------------
// HMMA GEMM core — 128 threads (4 warps x 32 rows, mt2), tile 128x64, K=256.
// Term-major MMA order (dep spacing 4).
// ---------------------------------------------------------------------------
#define GB_AH 0
#define GB_AL 16384
#define GB_BH 32768
#define GB_BL 40960
#define GBUF  49152
#define GEMM_SMEM (2 * GBUF)

__device__ __forceinline__ void gemm_stage(u32 sb, int bufi, int kb,
                                           const u32* Ah, const u32* Al,
                                           const u32* Bh, const u32* Bl,
                                           int m0, int n0, int tid)
{
    const u32 bufb = sb + bufi * GBUF;
    #pragma unroll
    for (int i = 0; i < 8; i++) {
        int idx = tid + i * 128;           // < 1024
        int r = idx >> 3, c = idx & 7;
        const size_t go = (size_t)(m0 + r) * ROW_WORDS + kb * 32 + c * 4;
        cp16(bufb + GB_AH + swz(r, c), Ah + go);
        cp16(bufb + GB_AL + swz(r, c), Al + go);
    }
    #pragma unroll
    for (int i = 0; i < 4; i++) {
        int idx = tid + i * 128;           // < 512
        int r = idx >> 3, c = idx & 7;
        const size_t go = (size_t)(n0 + r) * ROW_WORDS + kb * 32 + c * 4;
        cp16(bufb + GB_BH + swz(r, c), Bh + go);
        cp16(bufb + GB_BL + swz(r, c), Bl + go);
    }
}

__device__ __forceinline__ void gemm_main(u32 sb, float acc[2][8][4],
                                          const u32* Ah, const u32* Al,
                                          const u32* Bh, const u32* Bl,
                                          int m0, int n0, int tid)
{
    const int w  = tid >> 5;
    const int L  = tid & 31;
    const int rt = L & 7;
    const int lb = (L >> 3) & 1;
    const int lc = L >> 4;

    gemm_stage(sb, 0, 0, Ah, Al, Bh, Bl, m0, n0, tid);
    CP_COMMIT();
    gemm_stage(sb, 1, 1, Ah, Al, Bh, Bl, m0, n0, tid);
    CP_COMMIT();

    for (int kb = 0; kb < 4; kb++) {
        CP_WAIT(1);
        __syncthreads();
        const u32 bufb = sb + (kb & 1) * GBUF;
        const u32 aAH = bufb + GB_AH, aAL = bufb + GB_AL;
        const u32 aBH = bufb + GB_BH, aBL = bufb + GB_BL;

        #pragma unroll
        for (int j = 0; j < 4; j++) {
            u32 ah[2][4], al[2][4];
            #pragma unroll
            for (int mt = 0; mt < 2; mt++) {
                int row = w * 32 + mt * 16 + rt + lb * 8;
                LDSM_A(ah[mt], aAH + swz(row, 2 * j + lc));
                LDSM_A(al[mt], aAL + swz(row, 2 * j + lc));
            }
            #pragma unroll
            for (int p = 0; p < 4; p++) {
                int row = 16 * p + rt + lc * 8;
                int ch  = 2 * j + lb;
                u32 bh0, bh1, bh2, bh3, bl0, bl1, bl2, bl3;
                LDSM_X4(bh0, bh1, bh2, bh3, aBH + swz(row, ch));
                LDSM_X4(bl0, bl1, bl2, bl3, aBL + swz(row, ch));
                // term-major: 4 independent acc targets per term
                mma_bf16(acc[0][2*p],   ah[0], bh0, bh1);
                mma_bf16(acc[0][2*p+1], ah[0], bh2, bh3);
                mma_bf16(acc[1][2*p],   ah[1], bh0, bh1);
                mma_bf16(acc[1][2*p+1], ah[1], bh2, bh3);
                mma_bf16(acc[0][2*p],   al[0], bh0, bh1);
                mma_bf16(acc[0][2*p+1], al[0], bh2, bh3);
                mma_bf16(acc[1][2*p],   al[1], bh0, bh1);
                mma_bf16(acc[1][2*p+1], al[1], bh2, bh3);
                mma_bf16(acc[0][2*p],   ah[0], bl0, bl1);
                mma_bf16(acc[0][2*p+1], ah[0], bl2, bl3);
                mma_bf16(acc[1][2*p],   ah[1], bl0, bl1);
                mma_bf16(acc[1][2*p+1], ah[1], bl2, bl3);
            }
        }
        __syncthreads();
        if (kb + 2 < 4)
            gemm_stage(sb, kb & 1, kb + 2, Ah, Al, Bh, Bl, m0, n0, tid);
        CP_COMMIT();
    }
}

// ---------------------------------------------------------------------------
// Kernel 1: QKV projection. grid (MT/128, H, 3), block 128.
// ---------------------------------------------------------------------------
__global__ void __launch_bounds__(128, 2) qkv_hmma(
    const float* __restrict__ bq, const float* __restrict__ bk,
    const float* __restrict__ bv)
{
    extern __shared__ char sm[];
    const u32 sb  = smem_u32(sm);
    const int tid = threadIdx.x;
    const int z   = blockIdx.z;
    const int h   = blockIdx.y;
    const int m0  = blockIdx.x * 128;
    const int n0  = h * 64;

    const float* bias = (z == 0) ? bq : (z == 1) ? bk : bv;
    u32* oh = (z == 0) ? g_Qh : (z == 1) ? g_Kh : g_Vh;
    u32* ol = (z == 0) ? g_Ql : (z == 1) ? g_Kl : g_Vl;
    const float qs = (z == 0) ? (0.125f * LOG2E) : 1.0f;

    float acc[2][8][4];
    #pragma unroll
    for (int mt = 0; mt < 2; mt++)
        #pragma unroll
        for (int t = 0; t < 8; t++)
            #pragma unroll
            for (int e = 0; e < 4; e++) acc[mt][t][e] = 0.0f;

    gemm_main(sb, acc, g_Xh, g_Xl,
              g_Wth + (size_t)z * 256 * ROW_WORDS,
              g_Wtl + (size_t)z * 256 * ROW_WORDS, m0, n0, tid);

    const int w  = tid >> 5;
    const int L  = tid & 31;
    const int lr = L >> 2, lcq = L & 3;
    float b2[8][2];
    #pragma unroll
    for (int t = 0; t < 8; t++) {
        b2[t][0] = bias[n0 + 8 * t + lcq * 2];
        b2[t][1] = bias[n0 + 8 * t + lcq * 2 + 1];
    }
    const int bb = m0 >> 12;
    const int sbase = m0 & (S_ - 1);
    #pragma unroll
    for (int mt = 0; mt < 2; mt++) {
        #pragma unroll
        for (int half = 0; half < 2; half++) {
            int s = sbase + w * 32 + mt * 16 + lr + half * 8;
            size_t rw = ((size_t)(bb * H_ + h) * S_ + s) * 32 + lcq;
            #pragma unroll
            for (int t = 0; t < 8; t++) {
                float v0 = (acc[mt][t][half * 2 + 0] + b2[t][0]) * qs;
                float v1 = (acc[mt][t][half * 2 + 1] + b2[t][1]) * qs;
                u32 hi = cvt2(v1, v0);
                oh[rw + 4 * t] = hi;
                ol[rw + 4 * t] = cvt2(v1 - bfhi(hi), v0 - bflo(hi));
            }
        }
    }
}

// ---------------------------------------------------------------------------
// Kernel 3: output projection. grid (MT/128, 4), block 128.
// ---------------------------------------------------------------------------
__global__ void __launch_bounds__(128, 2) out_hmma(
    const float* __restrict__ bo, float* __restrict__ out)
{
    extern __shared__ char sm[];
    const u32 sb  = smem_u32(sm);
    const int tid = threadIdx.x;
    const int m0  = blockIdx.x * 128;
    const int n0  = blockIdx.y * 64;

    float acc[2][8][4];
    #pragma unroll
    for (int mt = 0; mt < 2; mt++)
        #pragma unroll
        for (int t = 0; t < 8; t++)
            #pragma unroll
            for (int e = 0; e < 4; e++) acc[mt][t][e] = 0.0f;

    gemm_main(sb, acc, g_Ah, g_Al,
              g_Wth + (size_t)3 * 256 * ROW_WORDS,
              g_Wtl + (size_t)3 * 256 * ROW_WORDS, m0, n0, tid);

    const int w  = tid >> 5;
    const int L  = tid & 31;
    const int lr = L >> 2, lcq = L & 3;
    float b2[8][2];
    #pragma unroll
    for (int t = 0; t < 8; t++) {
        b2[t][0] = bo[n0 + 8 * t + lcq * 2];
        b2[t][1] = bo[n0 + 8 * t + lcq * 2 + 1];
    }
    #pragma unroll
    for (int mt = 0; mt < 2; mt++) {
        #pragma unroll
        for (int half = 0; half < 2; half++) {
            int m = m0 + w * 32 + mt * 16 + lr + half * 8;
            float* orow = out + (size_t)m * D_ + n0 + lcq * 2;
            #pragma unroll
            for (int t = 0; t < 8; t++) {
                float2 v;
                v.x = acc[mt][t][half * 2 + 0] + b2[t][0];
                v.y = acc[mt][t][half * 2 + 1] + b2[t][1];
                *(float2*)&orow[8 * t] = v;
            }
        }
    }
}

// ---------------------------------------------------------------------------
// Kernel 2: flash attention. BQ=128 via 4 warps x 32 rows (mt2), BK=64.
// grid (S/128, BH), block 128, 2 CTAs/SM.
// smem: Q hi/lo 32KB (persistent) + 2 x 32KB KV buffers = 96KB.
// ---------------------------------------------------------------------------
#define BUF_STRIDE 32768
#define ATTN_SMEM  (32768 + 2 * 32768)

__global__ void __launch_bounds__(128, 2) attn_kernel()
{
    extern __shared__ char sm[];
    const u32 sb   = smem_u32(sm);
    const u32 sQh  = sb;
    const u32 sQl  = sb + 16384;
    const u32 bufbase = sb + 32768;
    const int tid = threadIdx.x;
    const int w   = tid >> 5;
    const int L   = tid & 31;
    const int bh  = blockIdx.y;
    const int q0  = blockIdx.x * 128;

    const size_t head = (size_t)bh * S_ * (DH_ / 2);
    const u32* Qh = g_Qh + head; const u32* Ql = g_Ql + head;
    const u32* Kh = g_Kh + head; const u32* Kl = g_Kl + head;
    const u32* Vh = g_Vh + head; const u32* Vl = g_Vl + head;

    const int rt = L & 7;
    const int lb = (L >> 3) & 1;
    const int lc = L >> 4;

    // ---- prologue: stage Q (persistent in smem) + first two KV tiles ----
    #pragma unroll
    for (int i = 0; i < 8; i++) {
        int idx = tid + i * 128;           // < 1024
        int r = idx >> 3, c = idx & 7;
        cp16(sQh + swz(r, c), Qh + (size_t)(q0 + r) * 32 + c * 4);
        cp16(sQl + swz(r, c), Ql + (size_t)(q0 + r) * 32 + c * 4);
    }
    CP_COMMIT();
    const u32* kvsrc[4] = {Kh, Kl, Vh, Vl};
    #pragma unroll
    for (int t0 = 0; t0 < 2; t0++) {
        u32 bufb = bufbase + t0 * BUF_STRIDE;
        #pragma unroll
        for (int m = 0; m < 4; m++)
            #pragma unroll
            for (int i = 0; i < 4; i++) {
                int idx = tid + i * 128;   // < 512
                int r = idx >> 3, c = idx & 7;
                cp16(bufb + m * 8192 + swz(r, c),
                     kvsrc[m] + (size_t)(t0 * 64 + r) * 32 + c * 4);
            }
        CP_COMMIT();
    }
    CP_WAIT(2);        // Q ready
    __syncthreads();

    float oacc[2][8][4];
    #pragma unroll
    for (int mt = 0; mt < 2; mt++)
        #pragma unroll
        for (int t = 0; t < 8; t++)
            #pragma unroll
            for (int e = 0; e < 4; e++) oacc[mt][t][e] = 0.0f;
    float m_[2][2] = {{-CUDART_INF_F, -CUDART_INF_F},
                      {-CUDART_INF_F, -CUDART_INF_F}};
    float l_[2][2] = {{0.0f, 0.0f}, {0.0f, 0.0f}};

    const int NT = S_ / 64;
    for (int it = 0; it < NT; it++) {
        CP_WAIT(1);
        __syncthreads();
        const u32 bufb = bufbase + (it & 1) * BUF_STRIDE;
        const u32 aKH = bufb, aKL = bufb + 8192;
        const u32 aVH = bufb + 16384, aVL = bufb + 24576;

        // ---- S = Q K^T (3-split, mt2, term-major) ----
        float sacc[2][8][4];
        #pragma unroll
        for (int mt = 0; mt < 2; mt++)
            #pragma unroll
            for (int t = 0; t < 8; t++)
                #pragma unroll
                for (int e = 0; e < 4; e++) sacc[mt][t][e] = 0.0f;

        #pragma unroll
        for (int j = 0; j < 4; j++) {
            u32 qh[2][4], ql[2][4];
            #pragma unroll
            for (int mt = 0; mt < 2; mt++) {
                int row = w * 32 + mt * 16 + rt + lb * 8;
                LDSM_A(qh[mt], sQh + swz(row, 2 * j + lc));
                LDSM_A(ql[mt], sQl + swz(row, 2 * j + lc));
            }
            #pragma unroll
            for (int p = 0; p < 4; p++) {
                int row = 16 * p + rt + lc * 8;
                int ch  = 2 * j + lb;
                u32 kh0, kh1, kh2, kh3, kl0, kl1, kl2, kl3;
                LDSM_X4(kh0, kh1, kh2, kh3, aKH + swz(row, ch));
                LDSM_X4(kl0, kl1, kl2, kl3, aKL + swz(row, ch));
                mma_bf16(sacc[0][2*p],   qh[0], kh0, kh1);
                mma_bf16(sacc[0][2*p+1], qh[0], kh2, kh3);
                mma_bf16(sacc[1][2*p],   qh[1], kh0, kh1);
                mma_bf16(sacc[1][2*p+1], qh[1], kh2, kh3);
                mma_bf16(sacc[0][2*p],   ql[0], kh0, kh1);
                mma_bf16(sacc[0][2*p+1], ql[0], kh2, kh3);
                mma_bf16(sacc[1][2*p],   ql[1], kh0, kh1);
                mma_bf16(sacc[1][2*p+1], ql[1], kh2, kh3);
                mma_bf16(sacc[0][2*p],   qh[0], kl0, kl1);
                mma_bf16(sacc[0][2*p+1], qh[0], kl2, kl3);
                mma_bf16(sacc[1][2*p],   qh[1], kl0, kl1);
                mma_bf16(sacc[1][2*p+1], qh[1], kl2, kl3);
            }
        }

        // ---- online softmax (log2 domain), per mt ----
        float mn[2][2], c_[2][2];
        #pragma unroll
        for (int mt = 0; mt < 2; mt++) {
            float mlo = -CUDART_INF_F, mhi = -CUDART_INF_F;
            #pragma unroll
            for (int t = 0; t < 8; t++) {
                mlo = fmaxf(mlo, fmaxf(sacc[mt][t][0], sacc[mt][t][1]));
                mhi = fmaxf(mhi, fmaxf(sacc[mt][t][2], sacc[mt][t][3]));
            }
            mlo = fmaxf(mlo, __shfl_xor_sync(0xffffffffu, mlo, 1));
            mlo = fmaxf(mlo, __shfl_xor_sync(0xffffffffu, mlo, 2));
            mhi = fmaxf(mhi, __shfl_xor_sync(0xffffffffu, mhi, 1));
            mhi = fmaxf(mhi, __shfl_xor_sync(0xffffffffu, mhi, 2));
            mn[mt][0] = fmaxf(m_[mt][0], mlo);
            mn[mt][1] = fmaxf(m_[mt][1], mhi);
            c_[mt][0] = ex2f(m_[mt][0] - mn[mt][0]);
            c_[mt][1] = ex2f(m_[mt][1] - mn[mt][1]);
            m_[mt][0] = mn[mt][0];
            m_[mt][1] = mn[mt][1];
            #pragma unroll
            for (int t = 0; t < 8; t++) {
                oacc[mt][t][0] *= c_[mt][0]; oacc[mt][t][1] *= c_[mt][0];
                oacc[mt][t][2] *= c_[mt][1]; oacc[mt][t][3] *= c_[mt][1];
            }
        }

        // ---- PV with JIT P conversion (mt2, term-major) ----
        float a_[2][2] = {{0.0f, 0.0f}, {0.0f, 0.0f}};
        #pragma unroll
        for (int j = 0; j < 4; j++) {
            u32 pa[2][4], pb[2][4];
            #pragma unroll
            for (int mt = 0; mt < 2; mt++) {
                #pragma unroll
                for (int tt = 0; tt < 2; tt++) {
                    const float* sv = sacc[mt][2 * j + tt];
                    float p0 = ex2f(sv[0] - mn[mt][0]);
                    float p1 = ex2f(sv[1] - mn[mt][0]);
                    float p2 = ex2f(sv[2] - mn[mt][1]);
                    float p3 = ex2f(sv[3] - mn[mt][1]);
                    a_[mt][0] += p0 + p1; a_[mt][1] += p2 + p3;
                    u32 h0 = cvt2(p1, p0), h1 = cvt2(p3, p2);
                    pa[mt][2 * tt]     = h0;
                    pa[mt][2 * tt + 1] = h1;
                    pb[mt][2 * tt]     = cvt2(p1 - bfhi(h0), p0 - bflo(h0));
                    pb[mt][2 * tt + 1] = cvt2(p3 - bfhi(h1), p2 - bflo(h1));
                }
            }
            int row = 16 * j + rt + lb * 8;
            #pragma unroll
            for (int t = 0; t < 4; t++) {
                int ch = 2 * t + lc;
                u32 vh0, vh1, vh2, vh3, vl0, vl1, vl2, vl3;
                LDSM_X4T(vh0, vh1, vh2, vh3, aVH + swz(row, ch));
                LDSM_X4T(vl0, vl1, vl2, vl3, aVL + swz(row, ch));
                mma_bf16(oacc[0][2*t],   pa[0], vh0, vh1);
                mma_bf16(oacc[0][2*t+1], pa[0], vh2, vh3);
                mma_bf16(oacc[1][2*t],   pa[1], vh0, vh1);
                mma_bf16(oacc[1][2*t+1], pa[1], vh2, vh3);
                mma_bf16(oacc[0][2*t],   pb[0], vh0, vh1);
                mma_bf16(oacc[0][2*t+1], pb[0], vh2, vh3);
                mma_bf16(oacc[1][2*t],   pb[1], vh0, vh1);
                mma_bf16(oacc[1][2*t+1], pb[1], vh2, vh3);
                mma_bf16(oacc[0][2*t],   pa[0], vl0, vl1);
                mma_bf16(oacc[0][2*t+1], pa[0], vl2, vl3);
                mma_bf16(oacc[1][2*t],   pa[1], vl0, vl1);
                mma_bf16(oacc[1][2*t+1], pa[1], vl2, vl3);
            }
        }
        #pragma unroll
        for (int mt = 0; mt < 2; mt++) {
            l_[mt][0] = l_[mt][0] * c_[mt][0] + a_[mt][0];
            l_[mt][1] = l_[mt][1] * c_[mt][1] + a_[mt][1];
        }

        __syncthreads();
        if (it + 2 < NT) {
            u32 bb2 = bufbase + (it & 1) * BUF_STRIDE;
            int j2 = (it + 2) * 64;
            #pragma unroll
            for (int m = 0; m < 4; m++)
                #pragma unroll
                for (int i = 0; i < 4; i++) {
                    int idx = tid + i * 128;
                    int r = idx >> 3, c = idx & 7;
                    cp16(bb2 + m * 8192 + swz(r, c),
                         kvsrc[m] + (size_t)(j2 + r) * 32 + c * 4);
                }
        }
        CP_COMMIT();
    }

    // ---- epilogue: normalize, split to bf16 hi/lo, write g_Ah/g_Al ----
    const int bb = bh >> 2, h = bh & 3;
    #pragma unroll
    for (int mt = 0; mt < 2; mt++) {
        float llo = l_[mt][0] + __shfl_xor_sync(0xffffffffu, l_[mt][0], 1);
        llo += __shfl_xor_sync(0xffffffffu, llo, 2);
        float lhi = l_[mt][1] + __shfl_xor_sync(0xffffffffu, l_[mt][1], 1);
        lhi += __shfl_xor_sync(0xffffffffu, lhi, 2);
        const float ilo = 1.0f / llo, ihi = 1.0f / lhi;

        const int rlo = q0 + w * 32 + mt * 16 + (L >> 2);
        const size_t rw0 = ((size_t)(bb * S_) + rlo) * ROW_WORDS + h * 32 + (L & 3);
        const size_t rw1 = rw0 + 8 * ROW_WORDS;
        #pragma unroll
        for (int t = 0; t < 8; t++) {
            float o0 = oacc[mt][t][0] * ilo, o1 = oacc[mt][t][1] * ilo;
            float o2 = oacc[mt][t][2] * ihi, o3 = oacc[mt][t][3] * ihi;
            u32 h0 = cvt2(o1, o0), h1 = cvt2(o3, o2);
            g_Ah[rw0 + 4 * t] = h0;
            g_Al[rw0 + 4 * t] = cvt2(o1 - bfhi(h0), o0 - bflo(h0));
            g_Ah[rw1 + 4 * t] = h1;
            g_Al[rw1 + 4 * t] = cvt2(o3 - bfhi(h1), o2 - bflo(h1));
        }
    }
}

// ---------------------------------------------------------------------------
// Launch
// ---------------------------------------------------------------------------
extern "C" void kernel_launch(void* const* d_in, const int* in_sizes, int n_in,
                              void* d_out, int out_size)
{
    const float* X  = (const float*)d_in[0];
    const float* Wq = (const float*)d_in[1];
    const float* bq = (const float*)d_in[2];
    const float* Wk = (const float*)d_in[3];
    const float* bk = (const float*)d_in[4];
    const float* Wv = (const float*)d_in[5];
    const float* bv = (const float*)d_in[6];
    const float* Wo = (const float*)d_in[7];
    const float* bo = (const float*)d_in[8];
    float* out = (float*)d_out;

    cudaFuncSetAttribute(attn_kernel,
                         cudaFuncAttributeMaxDynamicSharedMemorySize, ATTN_SMEM);
    cudaFuncSetAttribute(qkv_hmma,
                         cudaFuncAttributeMaxDynamicSharedMemorySize, GEMM_SMEM);
    cudaFuncSetAttribute(out_hmma,
                         cudaFuncAttributeMaxDynamicSharedMemorySize, GEMM_SMEM);

    prep_kernel<<<(XWORDS + WWORDS + 255) / 256, 256>>>(X, Wq, Wk, Wv, Wo);
    qkv_hmma<<<dim3(MT_ / 128, H_, 3), 128, GEMM_SMEM>>>(bq, bk, bv);
    attn_kernel<<<dim3(S_ / 128, BH_), 128, ATTN_SMEM>>>();
    out_hmma<<<dim3(MT_ / 128, 4), 128, GEMM_SMEM>>>(bo, out);
}

// round 9
// speedup vs baseline: 1.1357x; 1.0661x over previous
#include <cuda_runtime.h>
#include <cuda_bf16.h>
#include <math_constants.h>

#define B_  4
#define S_  4096
#define D_  256
#define H_  4
#define DH_ 64
#define MT_ (B_ * S_)
#define BH_ (B_ * H_)
#define LOG2E 1.4426950408889634f

typedef unsigned int       u32;
typedef unsigned long long u64;

// ---------------------------------------------------------------------------
// Scratch
// ---------------------------------------------------------------------------
#define QKV_WORDS ((size_t)BH_ * S_ * (DH_ / 2))
#define ROW_WORDS (D_ / 2)
__device__ u32 g_Qh[QKV_WORDS];  __device__ u32 g_Ql[QKV_WORDS];
__device__ u32 g_Kh[QKV_WORDS];  __device__ u32 g_Kl[QKV_WORDS];
__device__ u32 g_Vh[QKV_WORDS];  __device__ u32 g_Vl[QKV_WORDS];
__device__ u32 g_Xh[(size_t)MT_ * ROW_WORDS];
__device__ u32 g_Xl[(size_t)MT_ * ROW_WORDS];
__device__ u32 g_Ah[(size_t)MT_ * ROW_WORDS];
__device__ u32 g_Al[(size_t)MT_ * ROW_WORDS];
__device__ u32 g_Wth[4 * 256 * ROW_WORDS];
__device__ u32 g_Wtl[4 * 256 * ROW_WORDS];
// split-KV partials: [half(2)][bh(16)][row(4096)] x 64 cols fp32, + m/l per row
__device__ float g_Op[(size_t)2 * 16 * 4096 * 64];
__device__ float g_m[2 * 16 * 4096];
__device__ float g_l[2 * 16 * 4096];

// ---------------------------------------------------------------------------
// PTX helpers (baseline PTX only)
// ---------------------------------------------------------------------------
__device__ __forceinline__ u32 smem_u32(const void* p) {
    u32 a;
    asm("{ .reg .u64 t; cvta.to.shared.u64 t, %1; cvt.u32.u64 %0, t; }"
        : "=r"(a) : "l"(p));
    return a;
}
__device__ __forceinline__ u32 cvt2(float a, float b) {   // {hi=bf16(a), lo=bf16(b)}
    u32 r;
    asm("cvt.rn.bf16x2.f32 %0, %1, %2;" : "=r"(r) : "f"(a), "f"(b));
    return r;
}
__device__ __forceinline__ float bflo(u32 w) { return __uint_as_float(w << 16); }
__device__ __forceinline__ float bfhi(u32 w) { return __uint_as_float(w & 0xffff0000u); }
__device__ __forceinline__ float ex2f(float x) {
    float y; asm("ex2.approx.f32 %0, %1;" : "=f"(y) : "f"(x)); return y;
}
__device__ __forceinline__ void mma_bf16(float c[4], const u32 a[4], u32 b0, u32 b1) {
    asm volatile(
        "mma.sync.aligned.m16n8k16.row.col.f32.bf16.bf16.f32 "
        "{%0,%1,%2,%3},{%4,%5,%6,%7},{%8,%9},{%0,%1,%2,%3};"
        : "+f"(c[0]), "+f"(c[1]), "+f"(c[2]), "+f"(c[3])
        : "r"(a[0]), "r"(a[1]), "r"(a[2]), "r"(a[3]), "r"(b0), "r"(b1));
}
#define LDSM_X4(r0, r1, r2, r3, a) \
    asm volatile("ldmatrix.sync.aligned.m8n8.x4.shared.b16 {%0,%1,%2,%3}, [%4];" \
                 : "=r"(r0), "=r"(r1), "=r"(r2), "=r"(r3) : "r"(a))
#define LDSM_A(fr, a) LDSM_X4(fr[0], fr[1], fr[2], fr[3], a)
#define LDSM_X4T(r0, r1, r2, r3, a) \
    asm volatile("ldmatrix.sync.aligned.m8n8.x4.trans.shared.b16 {%0,%1,%2,%3}, [%4];" \
                 : "=r"(r0), "=r"(r1), "=r"(r2), "=r"(r3) : "r"(a))
__device__ __forceinline__ void cp16(u32 dst, const void* src) {
    asm volatile("cp.async.cg.shared.global [%0], [%1], 16;" :: "r"(dst), "l"(src));
}
#define CP_COMMIT() asm volatile("cp.async.commit_group;" ::: "memory")
#define CP_WAIT(n)  asm volatile("cp.async.wait_group %0;" :: "n"(n) : "memory")

__device__ __forceinline__ u32 swz(int row, int chunk) {
    return (u32)(row * 128 + (((chunk ^ row) & 7) << 4));
}

// ---------------------------------------------------------------------------
// Kernel 0: prep — split X; transpose+split W matrices.
// ---------------------------------------------------------------------------
#define XWORDS (2097152)
#define WWORDS (131072)
__global__ void __launch_bounds__(256) prep_kernel(
    const float* __restrict__ X,
    const float* __restrict__ Wq, const float* __restrict__ Wk,
    const float* __restrict__ Wv, const float* __restrict__ Wo)
{
    const int w = blockIdx.x * 256 + threadIdx.x;
    if (w < XWORDS) {
        float2 f = ((const float2*)X)[w];
        u32 hi = cvt2(f.y, f.x);
        g_Xh[w] = hi;
        g_Xl[w] = cvt2(f.y - bfhi(hi), f.x - bflo(hi));
    } else if (w < XWORDS + WWORDS) {
        int u = w - XWORDS;
        int z = u >> 15, r = u & 32767;
        int n = r >> 7, kp = r & 127;
        const float* Wm = (z == 0) ? Wq : (z == 1) ? Wk : (z == 2) ? Wv : Wo;
        float f0 = Wm[(size_t)(2 * kp)     * 256 + n];
        float f1 = Wm[(size_t)(2 * kp + 1) * 256 + n];
        u32 hi = cvt2(f1, f0);
        g_Wth[u] = hi;
        g_Wtl[u] = cvt2(f1 - bfhi(hi), f0 - bflo(hi));
    }
}

// ---------------------------------------------------------------------------
// HMMA GEMM core — 128 threads (4 warps x 32 rows mt2), tile 128x64, K=256.
// ---------------------------------------------------------------------------
#define GB_AH 0
#define GB_AL 16384
#define GB_BH 32768
#define GB_BL 40960
#define GBUF  49152
#define GEMM_SMEM (2 * GBUF)

__device__ __forceinline__ void gemm_stage(u32 sb, int bufi, int kb,
                                           const u32* Ah, const u32* Al,
                                           const u32* Bh, const u32* Bl,
                                           int m0, int n0, int tid)
{
    const u32 bufb = sb + bufi * GBUF;
    #pragma unroll
    for (int i = 0; i < 8; i++) {
        int idx = tid + i * 128;
        int r = idx >> 3, c = idx & 7;
        const size_t go = (size_t)(m0 + r) * ROW_WORDS + kb * 32 + c * 4;
        cp16(bufb + GB_AH + swz(r, c), Ah + go);
        cp16(bufb + GB_AL + swz(r, c), Al + go);
    }
    #pragma unroll
    for (int i = 0; i < 4; i++) {
        int idx = tid + i * 128;
        int r = idx >> 3, c = idx & 7;
        const size_t go = (size_t)(n0 + r) * ROW_WORDS + kb * 32 + c * 4;
        cp16(bufb + GB_BH + swz(r, c), Bh + go);
        cp16(bufb + GB_BL + swz(r, c), Bl + go);
    }
}

__device__ __forceinline__ void gemm_main(u32 sb, float acc[2][8][4],
                                          const u32* Ah, const u32* Al,
                                          const u32* Bh, const u32* Bl,
                                          int m0, int n0, int tid)
{
    const int w  = tid >> 5;
    const int L  = tid & 31;
    const int rt = L & 7;
    const int lb = (L >> 3) & 1;
    const int lc = L >> 4;

    gemm_stage(sb, 0, 0, Ah, Al, Bh, Bl, m0, n0, tid);
    CP_COMMIT();
    gemm_stage(sb, 1, 1, Ah, Al, Bh, Bl, m0, n0, tid);
    CP_COMMIT();

    for (int kb = 0; kb < 4; kb++) {
        CP_WAIT(1);
        __syncthreads();
        const u32 bufb = sb + (kb & 1) * GBUF;
        const u32 aAH = bufb + GB_AH, aAL = bufb + GB_AL;
        const u32 aBH = bufb + GB_BH, aBL = bufb + GB_BL;

        #pragma unroll
        for (int j = 0; j < 4; j++) {
            u32 ah[2][4], al[2][4];
            #pragma unroll
            for (int mt = 0; mt < 2; mt++) {
                int row = w * 32 + mt * 16 + rt + lb * 8;
                LDSM_A(ah[mt], aAH + swz(row, 2 * j + lc));
                LDSM_A(al[mt], aAL + swz(row, 2 * j + lc));
            }
            #pragma unroll
            for (int p = 0; p < 4; p++) {
                int row = 16 * p + rt + lc * 8;
                int ch  = 2 * j + lb;
                u32 bh0, bh1, bh2, bh3, bl0, bl1, bl2, bl3;
                LDSM_X4(bh0, bh1, bh2, bh3, aBH + swz(row, ch));
                LDSM_X4(bl0, bl1, bl2, bl3, aBL + swz(row, ch));
                mma_bf16(acc[0][2*p],   ah[0], bh0, bh1);
                mma_bf16(acc[0][2*p+1], ah[0], bh2, bh3);
                mma_bf16(acc[1][2*p],   ah[1], bh0, bh1);
                mma_bf16(acc[1][2*p+1], ah[1], bh2, bh3);
                mma_bf16(acc[0][2*p],   al[0], bh0, bh1);
                mma_bf16(acc[0][2*p+1], al[0], bh2, bh3);
                mma_bf16(acc[1][2*p],   al[1], bh0, bh1);
                mma_bf16(acc[1][2*p+1], al[1], bh2, bh3);
                mma_bf16(acc[0][2*p],   ah[0], bl0, bl1);
                mma_bf16(acc[0][2*p+1], ah[0], bl2, bl3);
                mma_bf16(acc[1][2*p],   ah[1], bl0, bl1);
                mma_bf16(acc[1][2*p+1], ah[1], bl2, bl3);
            }
        }
        __syncthreads();
        if (kb + 2 < 4)
            gemm_stage(sb, kb & 1, kb + 2, Ah, Al, Bh, Bl, m0, n0, tid);
        CP_COMMIT();
    }
}

// ---------------------------------------------------------------------------
// Kernel 1: QKV projection. grid (MT/128, H, 3), block 128.
// ---------------------------------------------------------------------------
__global__ void __launch_bounds__(128, 2) qkv_hmma(
    const float* __restrict__ bq, const float* __restrict__ bk,
    const float* __restrict__ bv)
{
    extern __shared__ char sm[];
    const u32 sb  = smem_u32(sm);
    const int tid = threadIdx.x;
    const int z   = blockIdx.z;
    const int h   = blockIdx.y;
    const int m0  = blockIdx.x * 128;
    const int n0  = h * 64;

    const float* bias = (z == 0) ? bq : (z == 1) ? bk : bv;
    u32* oh = (z == 0) ? g_Qh : (z == 1) ? g_Kh : g_Vh;
    u32* ol = (z == 0) ? g_Ql : (z == 1) ? g_Kl : g_Vl;
    const float qs = (z == 0) ? (0.125f * LOG2E) : 1.0f;

    float acc[2][8][4];
    #pragma unroll
    for (int mt = 0; mt < 2; mt++)
        #pragma unroll
        for (int t = 0; t < 8; t++)
            #pragma unroll
            for (int e = 0; e < 4; e++) acc[mt][t][e] = 0.0f;

    gemm_main(sb, acc, g_Xh, g_Xl,
              g_Wth + (size_t)z * 256 * ROW_WORDS,
              g_Wtl + (size_t)z * 256 * ROW_WORDS, m0, n0, tid);

    const int w  = tid >> 5;
    const int L  = tid & 31;
    const int lr = L >> 2, lcq = L & 3;
    float b2[8][2];
    #pragma unroll
    for (int t = 0; t < 8; t++) {
        b2[t][0] = bias[n0 + 8 * t + lcq * 2];
        b2[t][1] = bias[n0 + 8 * t + lcq * 2 + 1];
    }
    const int bb = m0 >> 12;
    const int sbase = m0 & (S_ - 1);
    #pragma unroll
    for (int mt = 0; mt < 2; mt++) {
        #pragma unroll
        for (int half = 0; half < 2; half++) {
            int s = sbase + w * 32 + mt * 16 + lr + half * 8;
            size_t rw = ((size_t)(bb * H_ + h) * S_ + s) * 32 + lcq;
            #pragma unroll
            for (int t = 0; t < 8; t++) {
                float v0 = (acc[mt][t][half * 2 + 0] + b2[t][0]) * qs;
                float v1 = (acc[mt][t][half * 2 + 1] + b2[t][1]) * qs;
                u32 hi = cvt2(v1, v0);
                oh[rw + 4 * t] = hi;
                ol[rw + 4 * t] = cvt2(v1 - bfhi(hi), v0 - bflo(hi));
            }
        }
    }
}

// ---------------------------------------------------------------------------
// Kernel 3: output projection. grid (MT/128, 4), block 128.
// ---------------------------------------------------------------------------
__global__ void __launch_bounds__(128, 2) out_hmma(
    const float* __restrict__ bo, float* __restrict__ out)
{
    extern __shared__ char sm[];
    const u32 sb  = smem_u32(sm);
    const int tid = threadIdx.x;
    const int m0  = blockIdx.x * 128;
    const int n0  = blockIdx.y * 64;

    float acc[2][8][4];
    #pragma unroll
    for (int mt = 0; mt < 2; mt++)
        #pragma unroll
        for (int t = 0; t < 8; t++)
            #pragma unroll
            for (int e = 0; e < 4; e++) acc[mt][t][e] = 0.0f;

    gemm_main(sb, acc, g_Ah, g_Al,
              g_Wth + (size_t)3 * 256 * ROW_WORDS,
              g_Wtl + (size_t)3 * 256 * ROW_WORDS, m0, n0, tid);

    const int w  = tid >> 5;
    const int L  = tid & 31;
    const int lr = L >> 2, lcq = L & 3;
    float b2[8][2];
    #pragma unroll
    for (int t = 0; t < 8; t++) {
        b2[t][0] = bo[n0 + 8 * t + lcq * 2];
        b2[t][1] = bo[n0 + 8 * t + lcq * 2 + 1];
    }
    #pragma unroll
    for (int mt = 0; mt < 2; mt++) {
        #pragma unroll
        for (int half = 0; half < 2; half++) {
            int m = m0 + w * 32 + mt * 16 + lr + half * 8;
            float* orow = out + (size_t)m * D_ + n0 + lcq * 2;
            #pragma unroll
            for (int t = 0; t < 8; t++) {
                float2 v;
                v.x = acc[mt][t][half * 2 + 0] + b2[t][0];
                v.y = acc[mt][t][half * 2 + 1] + b2[t][1];
                *(float2*)&orow[8 * t] = v;
            }
        }
    }
}

// ---------------------------------------------------------------------------
// Kernel 2: flash attention (R6 core) with split-KV x2.
// grid (S/64, BH*2): bh = y>>1, half = y&1 covers keys [half*2048, +2048).
// block 128, 3 CTAs/SM. Writes unnormalized fp32 partials + (m,l).
// ---------------------------------------------------------------------------
#define BUF_STRIDE 32768
#define ATTN_SMEM  (2 * 32768)

__global__ void __launch_bounds__(128, 3) attn_kernel()
{
    extern __shared__ char sm[];
    const u32 sb  = smem_u32(sm);
    const int tid = threadIdx.x;
    const int w   = tid >> 5;
    const int L   = tid & 31;
    const int bh   = blockIdx.y >> 1;
    const int half = blockIdx.y & 1;
    const int q0  = blockIdx.x * 64;

    const size_t head = (size_t)bh * S_ * (DH_ / 2);
    const size_t koff = (size_t)half * 2048 * 32;
    const u32* Qh = g_Qh + head;        const u32* Ql = g_Ql + head;
    const u32* Kh = g_Kh + head + koff; const u32* Kl = g_Kl + head + koff;
    const u32* Vh = g_Vh + head + koff; const u32* Vl = g_Vl + head + koff;

    const int rt = L & 7;
    const int lb = (L >> 3) & 1;
    const int lc = L >> 4;

    // ---- prologue: stage Q through buf0, extract frags, then start KV ----
    #pragma unroll
    for (int i = 0; i < 4; i++) {
        int idx = tid + i * 128;
        int r = idx >> 3, c = idx & 7;
        cp16(sb + swz(r, c),        Qh + (size_t)(q0 + r) * 32 + c * 4);
        cp16(sb + 8192 + swz(r, c), Ql + (size_t)(q0 + r) * 32 + c * 4);
    }
    CP_COMMIT();
    CP_WAIT(0);
    __syncthreads();

    u32 qh[4][4], ql[4][4];
    #pragma unroll
    for (int j = 0; j < 4; j++) {
        int row = w * 16 + rt + lb * 8;
        LDSM_A(qh[j], sb + swz(row, 2 * j + lc));
        LDSM_A(ql[j], sb + 8192 + swz(row, 2 * j + lc));
    }
    __syncthreads();   // Q fully read before buf0 reuse

    const u32* kvsrc[4] = {Kh, Kl, Vh, Vl};
    #pragma unroll
    for (int t0 = 0; t0 < 2; t0++) {
        u32 bufb = sb + t0 * BUF_STRIDE;
        #pragma unroll
        for (int m = 0; m < 4; m++)
            #pragma unroll
            for (int i = 0; i < 4; i++) {
                int idx = tid + i * 128;
                int r = idx >> 3, c = idx & 7;
                cp16(bufb + m * 8192 + swz(r, c),
                     kvsrc[m] + (size_t)(t0 * 64 + r) * 32 + c * 4);
            }
        CP_COMMIT();
    }

    float oacc[8][4];
    #pragma unroll
    for (int t = 0; t < 8; t++)
        #pragma unroll
        for (int e = 0; e < 4; e++) oacc[t][e] = 0.0f;
    float m_lo = -CUDART_INF_F, m_hi = -CUDART_INF_F;
    float l_lo = 0.0f, l_hi = 0.0f;

    const int NT = 2048 / 64;
    for (int it = 0; it < NT; it++) {
        CP_WAIT(1);
        __syncthreads();
        const u32 bufb = sb + (it & 1) * BUF_STRIDE;
        const u32 aKH = bufb, aKL = bufb + 8192;
        const u32 aVH = bufb + 16384, aVL = bufb + 24576;

        // ---- S = Q K^T (3-split) ----
        float sacc[8][4];
        #pragma unroll
        for (int t = 0; t < 8; t++)
            #pragma unroll
            for (int e = 0; e < 4; e++) sacc[t][e] = 0.0f;

        #pragma unroll
        for (int j = 0; j < 4; j++) {
            #pragma unroll
            for (int p = 0; p < 4; p++) {
                int row = 16 * p + rt + lc * 8;
                int ch  = 2 * j + lb;
                u32 kh0, kh1, kh2, kh3, kl0, kl1, kl2, kl3;
                LDSM_X4(kh0, kh1, kh2, kh3, aKH + swz(row, ch));
                LDSM_X4(kl0, kl1, kl2, kl3, aKL + swz(row, ch));
                mma_bf16(sacc[2*p],   qh[j], kh0, kh1);
                mma_bf16(sacc[2*p+1], qh[j], kh2, kh3);
                mma_bf16(sacc[2*p],   ql[j], kh0, kh1);
                mma_bf16(sacc[2*p+1], ql[j], kh2, kh3);
                mma_bf16(sacc[2*p],   qh[j], kl0, kl1);
                mma_bf16(sacc[2*p+1], qh[j], kl2, kl3);
            }
        }

        // ---- row max (log2 domain) ----
        float mlo = -CUDART_INF_F, mhi = -CUDART_INF_F;
        #pragma unroll
        for (int t = 0; t < 8; t++) {
            mlo = fmaxf(mlo, fmaxf(sacc[t][0], sacc[t][1]));
            mhi = fmaxf(mhi, fmaxf(sacc[t][2], sacc[t][3]));
        }
        mlo = fmaxf(mlo, __shfl_xor_sync(0xffffffffu, mlo, 1));
        mlo = fmaxf(mlo, __shfl_xor_sync(0xffffffffu, mlo, 2));
        mhi = fmaxf(mhi, __shfl_xor_sync(0xffffffffu, mhi, 1));
        mhi = fmaxf(mhi, __shfl_xor_sync(0xffffffffu, mhi, 2));

        float mnlo = fmaxf(m_lo, mlo), mnhi = fmaxf(m_hi, mhi);
        float clo = ex2f(m_lo - mnlo), chi = ex2f(m_hi - mnhi);
        m_lo = mnlo; m_hi = mnhi;

        #pragma unroll
        for (int t = 0; t < 8; t++) {
            oacc[t][0] *= clo; oacc[t][1] *= clo;
            oacc[t][2] *= chi; oacc[t][3] *= chi;
        }

        // ---- PV with just-in-time P conversion ----
        float alo = 0.0f, ahi = 0.0f;
        #pragma unroll
        for (int j = 0; j < 4; j++) {
            u32 pa[4], pb[4];
            #pragma unroll
            for (int tt = 0; tt < 2; tt++) {
                const float* sv = sacc[2 * j + tt];
                float p0 = ex2f(sv[0] - mnlo);
                float p1 = ex2f(sv[1] - mnlo);
                float p2 = ex2f(sv[2] - mnhi);
                float p3 = ex2f(sv[3] - mnhi);
                alo += p0 + p1; ahi += p2 + p3;
                u32 h0 = cvt2(p1, p0), h1 = cvt2(p3, p2);
                pa[2 * tt]     = h0;
                pa[2 * tt + 1] = h1;
                pb[2 * tt]     = cvt2(p1 - bfhi(h0), p0 - bflo(h0));
                pb[2 * tt + 1] = cvt2(p3 - bfhi(h1), p2 - bflo(h1));
            }
            int row = 16 * j + rt + lb * 8;
            #pragma unroll
            for (int t = 0; t < 4; t++) {
                int ch = 2 * t + lc;
                u32 vh0, vh1, vh2, vh3, vl0, vl1, vl2, vl3;
                LDSM_X4T(vh0, vh1, vh2, vh3, aVH + swz(row, ch));
                LDSM_X4T(vl0, vl1, vl2, vl3, aVL + swz(row, ch));
                mma_bf16(oacc[2*t],   pa, vh0, vh1);
                mma_bf16(oacc[2*t+1], pa, vh2, vh3);
                mma_bf16(oacc[2*t],   pb, vh0, vh1);
                mma_bf16(oacc[2*t+1], pb, vh2, vh3);
                mma_bf16(oacc[2*t],   pa, vl0, vl1);
                mma_bf16(oacc[2*t+1], pa, vl2, vl3);
            }
        }
        l_lo = l_lo * clo + alo;
        l_hi = l_hi * chi + ahi;

        __syncthreads();
        if (it + 2 < NT) {
            u32 bb2 = sb + (it & 1) * BUF_STRIDE;
            int j2 = (it + 2) * 64;
            #pragma unroll
            for (int m = 0; m < 4; m++)
                #pragma unroll
                for (int i = 0; i < 4; i++) {
                    int idx = tid + i * 128;
                    int r = idx >> 3, c = idx & 7;
                    cp16(bb2 + m * 8192 + swz(r, c),
                         kvsrc[m] + (size_t)(j2 + r) * 32 + c * 4);
                }
        }
        CP_COMMIT();
    }

    // ---- epilogue: write UNNORMALIZED fp32 partials + (m,l) per row ----
    float llo = l_lo + __shfl_xor_sync(0xffffffffu, l_lo, 1);
    llo += __shfl_xor_sync(0xffffffffu, llo, 2);
    float lhi = l_hi + __shfl_xor_sync(0xffffffffu, l_hi, 1);
    lhi += __shfl_xor_sync(0xffffffffu, lhi, 2);

    const int rlo = q0 + w * 16 + (L >> 2);
    const size_t pbase = (size_t)(half * 16 + bh) * 4096;
    float* O0 = g_Op + (pbase + rlo)     * 64 + (L & 3) * 2;
    float* O1 = g_Op + (pbase + rlo + 8) * 64 + (L & 3) * 2;
    #pragma unroll
    for (int t = 0; t < 8; t++) {
        *(float2*)&O0[8 * t] = make_float2(oacc[t][0], oacc[t][1]);
        *(float2*)&O1[8 * t] = make_float2(oacc[t][2], oacc[t][3]);
    }
    if ((L & 3) == 0) {
        g_m[pbase + rlo]     = m_lo;  g_l[pbase + rlo]     = llo;
        g_m[pbase + rlo + 8] = m_hi;  g_l[pbase + rlo + 8] = lhi;
    }
}

// ---------------------------------------------------------------------------
// Kernel 2b: combine split-KV halves -> split-bf16 attention output.
// 16*4096*32 = 2M words; one thread per word (2 cols).
// ---------------------------------------------------------------------------
__global__ void __launch_bounds__(256) combine_kernel()
{
    const int idx = blockIdx.x * 256 + threadIdx.x;   // < 2097152
    const int bh  = idx >> 17;
    const int rem = idx & 131071;
    const int row = rem >> 5;
    const int cw  = rem & 31;

    const int b0 = bh * 4096 + row;
    const int b1 = (16 + bh) * 4096 + row;
    const float m1 = g_m[b0], l1 = g_l[b0];
    const float m2 = g_m[b1], l2 = g_l[b1];
    const float ms = fmaxf(m1, m2);
    const float c1 = ex2f(m1 - ms), c2 = ex2f(m2 - ms);
    const float inv = 1.0f / (c1 * l1 + c2 * l2);

    const float2 o1 = *(const float2*)(g_Op + (size_t)b0 * 64 + 2 * cw);
    const float2 o2 = *(const float2*)(g_Op + (size_t)b1 * 64 + 2 * cw);
    const float v0 = (c1 * o1.x + c2 * o2.x) * inv;
    const float v1 = (c1 * o1.y + c2 * o2.y) * inv;

    u32 h0 = cvt2(v1, v0);
    const size_t rw = ((size_t)((bh >> 2) * S_) + row) * ROW_WORDS
                      + (bh & 3) * 32 + cw;
    g_Ah[rw] = h0;
    g_Al[rw] = cvt2(v1 - bfhi(h0), v0 - bflo(h0));
}

// ---------------------------------------------------------------------------
// Launch
// ---------------------------------------------------------------------------
extern "C" void kernel_launch(void* const* d_in, const int* in_sizes, int n_in,
                              void* d_out, int out_size)
{
    const float* X  = (const float*)d_in[0];
    const float* Wq = (const float*)d_in[1];
    const float* bq = (const float*)d_in[2];
    const float* Wk = (const float*)d_in[3];
    const float* bk = (const float*)d_in[4];
    const float* Wv = (const float*)d_in[5];
    const float* bv = (const float*)d_in[6];
    const float* Wo = (const float*)d_in[7];
    const float* bo = (const float*)d_in[8];
    float* out = (float*)d_out;

    cudaFuncSetAttribute(attn_kernel,
                         cudaFuncAttributeMaxDynamicSharedMemorySize, ATTN_SMEM);
    cudaFuncSetAttribute(qkv_hmma,
                         cudaFuncAttributeMaxDynamicSharedMemorySize, GEMM_SMEM);
    cudaFuncSetAttribute(out_hmma,
                         cudaFuncAttributeMaxDynamicSharedMemorySize, GEMM_SMEM);

    prep_kernel<<<(XWORDS + WWORDS + 255) / 256, 256>>>(X, Wq, Wk, Wv, Wo);
    qkv_hmma<<<dim3(MT_ / 128, H_, 3), 128, GEMM_SMEM>>>(bq, bk, bv);
    attn_kernel<<<dim3(S_ / 64, BH_ * 2), 128, ATTN_SMEM>>>();
    combine_kernel<<<8192, 256>>>();
    out_hmma<<<dim3(MT_ / 128, 4), 128, GEMM_SMEM>>>(bo, out);
}

// round 10
// speedup vs baseline: 1.1456x; 1.0087x over previous
#include <cuda_runtime.h>
#include <cuda_bf16.h>
#include <math_constants.h>

#define B_  4
#define S_  4096
#define D_  256
#define H_  4
#define DH_ 64
#define MT_ (B_ * S_)
#define BH_ (B_ * H_)
#define LOG2E 1.4426950408889634f

typedef unsigned int       u32;
typedef unsigned long long u64;

// ---------------------------------------------------------------------------
// Scratch
// ---------------------------------------------------------------------------
#define QKV_WORDS ((size_t)BH_ * S_ * (DH_ / 2))
#define ROW_WORDS (D_ / 2)
__device__ u32 g_Qh[QKV_WORDS];  __device__ u32 g_Ql[QKV_WORDS];
__device__ u32 g_Kh[QKV_WORDS];  __device__ u32 g_Kl[QKV_WORDS];
__device__ u32 g_Vh[QKV_WORDS];  __device__ u32 g_Vl[QKV_WORDS];
__device__ u32 g_Xh[(size_t)MT_ * ROW_WORDS];
__device__ u32 g_Xl[(size_t)MT_ * ROW_WORDS];
__device__ u32 g_Ah[(size_t)MT_ * ROW_WORDS];
__device__ u32 g_Al[(size_t)MT_ * ROW_WORDS];
__device__ u32 g_Wth[4 * 256 * ROW_WORDS];
__device__ u32 g_Wtl[4 * 256 * ROW_WORDS];
// split-KV partials
__device__ float g_Op[(size_t)2 * 16 * 4096 * 64];
__device__ float g_m[2 * 16 * 4096];
__device__ float g_l[2 * 16 * 4096];

// ---------------------------------------------------------------------------
// PTX helpers (baseline PTX only)
// ---------------------------------------------------------------------------
__device__ __forceinline__ u32 smem_u32(const void* p) {
    u32 a;
    asm("{ .reg .u64 t; cvta.to.shared.u64 t, %1; cvt.u32.u64 %0, t; }"
        : "=r"(a) : "l"(p));
    return a;
}
__device__ __forceinline__ u32 cvt2(float a, float b) {   // {hi=bf16(a), lo=bf16(b)}
    u32 r;
    asm("cvt.rn.bf16x2.f32 %0, %1, %2;" : "=r"(r) : "f"(a), "f"(b));
    return r;
}
__device__ __forceinline__ float bflo(u32 w) { return __uint_as_float(w << 16); }
__device__ __forceinline__ float bfhi(u32 w) { return __uint_as_float(w & 0xffff0000u); }
__device__ __forceinline__ float ex2f(float x) {
    float y; asm("ex2.approx.f32 %0, %1;" : "=f"(y) : "f"(x)); return y;
}
__device__ __forceinline__ void mma_bf16(float c[4], const u32 a[4], u32 b0, u32 b1) {
    asm volatile(
        "mma.sync.aligned.m16n8k16.row.col.f32.bf16.bf16.f32 "
        "{%0,%1,%2,%3},{%4,%5,%6,%7},{%8,%9},{%0,%1,%2,%3};"
        : "+f"(c[0]), "+f"(c[1]), "+f"(c[2]), "+f"(c[3])
        : "r"(a[0]), "r"(a[1]), "r"(a[2]), "r"(a[3]), "r"(b0), "r"(b1));
}
#define LDSM_X4(r0, r1, r2, r3, a) \
    asm volatile("ldmatrix.sync.aligned.m8n8.x4.shared.b16 {%0,%1,%2,%3}, [%4];" \
                 : "=r"(r0), "=r"(r1), "=r"(r2), "=r"(r3) : "r"(a))
#define LDSM_A(fr, a) LDSM_X4(fr[0], fr[1], fr[2], fr[3], a)
#define LDSM_X4T(r0, r1, r2, r3, a) \
    asm volatile("ldmatrix.sync.aligned.m8n8.x4.trans.shared.b16 {%0,%1,%2,%3}, [%4];" \
                 : "=r"(r0), "=r"(r1), "=r"(r2), "=r"(r3) : "r"(a))
#define LDSM_AT(fr, a) LDSM_X4T(fr[0], fr[1], fr[2], fr[3], a)
__device__ __forceinline__ void cp16(u32 dst, const void* src) {
    asm volatile("cp.async.cg.shared.global [%0], [%1], 16;" :: "r"(dst), "l"(src));
}
#define CP_COMMIT() asm volatile("cp.async.commit_group;" ::: "memory")
#define CP_WAIT(n)  asm volatile("cp.async.wait_group %0;" :: "n"(n) : "memory")

__device__ __forceinline__ u32 swz(int row, int chunk) {
    return (u32)(row * 128 + (((chunk ^ row) & 7) << 4));
}

// ---------------------------------------------------------------------------
// Kernel 0: prep — split X; transpose+split W matrices.
// ---------------------------------------------------------------------------
#define XWORDS (2097152)
#define WWORDS (131072)
__global__ void __launch_bounds__(256) prep_kernel(
    const float* __restrict__ X,
    const float* __restrict__ Wq, const float* __restrict__ Wk,
    const float* __restrict__ Wv, const float* __restrict__ Wo)
{
    const int w = blockIdx.x * 256 + threadIdx.x;
    if (w < XWORDS) {
        float2 f = ((const float2*)X)[w];
        u32 hi = cvt2(f.y, f.x);
        g_Xh[w] = hi;
        g_Xl[w] = cvt2(f.y - bfhi(hi), f.x - bflo(hi));
    } else if (w < XWORDS + WWORDS) {
        int u = w - XWORDS;
        int z = u >> 15, r = u & 32767;
        int n = r >> 7, kp = r & 127;
        const float* Wm = (z == 0) ? Wq : (z == 1) ? Wk : (z == 2) ? Wv : Wo;
        float f0 = Wm[(size_t)(2 * kp)     * 256 + n];
        float f1 = Wm[(size_t)(2 * kp + 1) * 256 + n];
        u32 hi = cvt2(f1, f0);
        g_Wth[u] = hi;
        g_Wtl[u] = cvt2(f1 - bfhi(hi), f0 - bflo(hi));
    }
}

// ---------------------------------------------------------------------------
// HMMA GEMM core — 128 threads (4 warps x 32 rows mt2), tile 128x64, K=256.
// Explicitly software-pipelined fragment loads (double-buffered in registers).
// ---------------------------------------------------------------------------
#define GB_AH 0
#define GB_AL 16384
#define GB_BH 32768
#define GB_BL 40960
#define GBUF  49152
#define GEMM_SMEM (2 * GBUF)

__device__ __forceinline__ void gemm_stage(u32 sb, int bufi, int kb,
                                           const u32* Ah, const u32* Al,
                                           const u32* Bh, const u32* Bl,
                                           int m0, int n0, int tid)
{
    const u32 bufb = sb + bufi * GBUF;
    #pragma unroll
    for (int i = 0; i < 8; i++) {
        int idx = tid + i * 128;
        int r = idx >> 3, c = idx & 7;
        const size_t go = (size_t)(m0 + r) * ROW_WORDS + kb * 32 + c * 4;
        cp16(bufb + GB_AH + swz(r, c), Ah + go);
        cp16(bufb + GB_AL + swz(r, c), Al + go);
    }
    #pragma unroll
    for (int i = 0; i < 4; i++) {
        int idx = tid + i * 128;
        int r = idx >> 3, c = idx & 7;
        const size_t go = (size_t)(n0 + r) * ROW_WORDS + kb * 32 + c * 4;
        cp16(bufb + GB_BH + swz(r, c), Bh + go);
        cp16(bufb + GB_BL + swz(r, c), Bl + go);
    }
}

__device__ __forceinline__ void gemm_main(u32 sb, float acc[2][8][4],
                                          const u32* Ah, const u32* Al,
                                          const u32* Bh, const u32* Bl,
                                          int m0, int n0, int tid)
{
    const int w  = tid >> 5;
    const int L  = tid & 31;
    const int rt = L & 7;
    const int lb = (L >> 3) & 1;
    const int lc = L >> 4;

    gemm_stage(sb, 0, 0, Ah, Al, Bh, Bl, m0, n0, tid);
    CP_COMMIT();
    gemm_stage(sb, 1, 1, Ah, Al, Bh, Bl, m0, n0, tid);
    CP_COMMIT();

    for (int kb = 0; kb < 4; kb++) {
        CP_WAIT(1);
        __syncthreads();
        const u32 bufb = sb + (kb & 1) * GBUF;
        const u32 aAH = bufb + GB_AH, aAL = bufb + GB_AL;
        const u32 aBH = bufb + GB_BH, aBL = bufb + GB_BL;

        u32 ah[2][2][4], al[2][2][4];   // [j parity][mt][frag]
        u32 bhf[2][4], blf[2][4];       // [group parity][frag]

        // preload: A(j=0), B(j=0, p=0)
        #pragma unroll
        for (int mt = 0; mt < 2; mt++) {
            int row = w * 32 + mt * 16 + rt + lb * 8;
            LDSM_A(ah[0][mt], aAH + swz(row, lc));
            LDSM_A(al[0][mt], aAL + swz(row, lc));
        }
        {
            int rowB = rt + lc * 8;
            LDSM_X4(bhf[0][0], bhf[0][1], bhf[0][2], bhf[0][3], aBH + swz(rowB, lb));
            LDSM_X4(blf[0][0], blf[0][1], blf[0][2], blf[0][3], aBL + swz(rowB, lb));
        }

        #pragma unroll
        for (int g = 0; g < 16; g++) {
            const int j = g >> 2, p = g & 3;
            const int cb = g & 1, nb = cb ^ 1;
            const int ja = j & 1;
            if (g + 1 < 16) {
                const int jn = (g + 1) >> 2, pn = (g + 1) & 3;
                if (pn == 0) {   // entering new j: load its A frags
                    #pragma unroll
                    for (int mt = 0; mt < 2; mt++) {
                        int row = w * 32 + mt * 16 + rt + lb * 8;
                        LDSM_A(ah[jn & 1][mt], aAH + swz(row, 2 * jn + lc));
                        LDSM_A(al[jn & 1][mt], aAL + swz(row, 2 * jn + lc));
                    }
                }
                int rowB = 16 * pn + rt + lc * 8;
                int chB  = 2 * jn + lb;
                LDSM_X4(bhf[nb][0], bhf[nb][1], bhf[nb][2], bhf[nb][3],
                        aBH + swz(rowB, chB));
                LDSM_X4(blf[nb][0], blf[nb][1], blf[nb][2], blf[nb][3],
                        aBL + swz(rowB, chB));
            }
            mma_bf16(acc[0][2*p],   ah[ja][0], bhf[cb][0], bhf[cb][1]);
            mma_bf16(acc[0][2*p+1], ah[ja][0], bhf[cb][2], bhf[cb][3]);
            mma_bf16(acc[1][2*p],   ah[ja][1], bhf[cb][0], bhf[cb][1]);
            mma_bf16(acc[1][2*p+1], ah[ja][1], bhf[cb][2], bhf[cb][3]);
            mma_bf16(acc[0][2*p],   al[ja][0], bhf[cb][0], bhf[cb][1]);
            mma_bf16(acc[0][2*p+1], al[ja][0], bhf[cb][2], bhf[cb][3]);
            mma_bf16(acc[1][2*p],   al[ja][1], bhf[cb][0], bhf[cb][1]);
            mma_bf16(acc[1][2*p+1], al[ja][1], bhf[cb][2], bhf[cb][3]);
            mma_bf16(acc[0][2*p],   ah[ja][0], blf[cb][0], blf[cb][1]);
            mma_bf16(acc[0][2*p+1], ah[ja][0], blf[cb][2], blf[cb][3]);
            mma_bf16(acc[1][2*p],   ah[ja][1], blf[cb][0], blf[cb][1]);
            mma_bf16(acc[1][2*p+1], ah[ja][1], blf[cb][2], blf[cb][3]);
        }
        __syncthreads();
        if (kb + 2 < 4)
            gemm_stage(sb, kb & 1, kb + 2, Ah, Al, Bh, Bl, m0, n0, tid);
        CP_COMMIT();
    }
}

// ---------------------------------------------------------------------------
// Kernel 1: QKV projection. grid (MT/128, H, 3), block 128.
// ---------------------------------------------------------------------------
__global__ void __launch_bounds__(128, 2) qkv_hmma(
    const float* __restrict__ bq, const float* __restrict__ bk,
    const float* __restrict__ bv)
{
    extern __shared__ char sm[];
    const u32 sb  = smem_u32(sm);
    const int tid = threadIdx.x;
    const int z   = blockIdx.z;
    const int h   = blockIdx.y;
    const int m0  = blockIdx.x * 128;
    const int n0  = h * 64;

    const float* bias = (z == 0) ? bq : (z == 1) ? bk : bv;
    u32* oh = (z == 0) ? g_Qh : (z == 1) ? g_Kh : g_Vh;
    u32* ol = (z == 0) ? g_Ql : (z == 1) ? g_Kl : g_Vl;
    const float qs = (z == 0) ? (0.125f * LOG2E) : 1.0f;

    float acc[2][8][4];
    #pragma unroll
    for (int mt = 0; mt < 2; mt++)
        #pragma unroll
        for (int t = 0; t < 8; t++)
            #pragma unroll
            for (int e = 0; e < 4; e++) acc[mt][t][e] = 0.0f;

    gemm_main(sb, acc, g_Xh, g_Xl,
              g_Wth + (size_t)z * 256 * ROW_WORDS,
              g_Wtl + (size_t)z * 256 * ROW_WORDS, m0, n0, tid);

    const int w  = tid >> 5;
    const int L  = tid & 31;
    const int lr = L >> 2, lcq = L & 3;
    float b2[8][2];
    #pragma unroll
    for (int t = 0; t < 8; t++) {
        b2[t][0] = bias[n0 + 8 * t + lcq * 2];
        b2[t][1] = bias[n0 + 8 * t + lcq * 2 + 1];
    }
    const int bb = m0 >> 12;
    const int sbase = m0 & (S_ - 1);
    #pragma unroll
    for (int mt = 0; mt < 2; mt++) {
        #pragma unroll
        for (int half = 0; half < 2; half++) {
            int s = sbase + w * 32 + mt * 16 + lr + half * 8;
            size_t rw = ((size_t)(bb * H_ + h) * S_ + s) * 32 + lcq;
            #pragma unroll
            for (int t = 0; t < 8; t++) {
                float v0 = (acc[mt][t][half * 2 + 0] + b2[t][0]) * qs;
                float v1 = (acc[mt][t][half * 2 + 1] + b2[t][1]) * qs;
                u32 hi = cvt2(v1, v0);
                oh[rw + 4 * t] = hi;
                ol[rw + 4 * t] = cvt2(v1 - bfhi(hi), v0 - bflo(hi));
            }
        }
    }
}

// ---------------------------------------------------------------------------
// Kernel 3: output projection. grid (MT/128, 4), block 128.
// ---------------------------------------------------------------------------
__global__ void __launch_bounds__(128, 2) out_hmma(
    const float* __restrict__ bo, float* __restrict__ out)
{
    extern __shared__ char sm[];
    const u32 sb  = smem_u32(sm);
    const int tid = threadIdx.x;
    const int m0  = blockIdx.x * 128;
    const int n0  = blockIdx.y * 64;

    float acc[2][8][4];
    #pragma unroll
    for (int mt = 0; mt < 2; mt++)
        #pragma unroll
        for (int t = 0; t < 8; t++)
            #pragma unroll
            for (int e = 0; e < 4; e++) acc[mt][t][e] = 0.0f;

    gemm_main(sb, acc, g_Ah, g_Al,
              g_Wth + (size_t)3 * 256 * ROW_WORDS,
              g_Wtl + (size_t)3 * 256 * ROW_WORDS, m0, n0, tid);

    const int w  = tid >> 5;
    const int L  = tid & 31;
    const int lr = L >> 2, lcq = L & 3;
    float b2[8][2];
    #pragma unroll
    for (int t = 0; t < 8; t++) {
        b2[t][0] = bo[n0 + 8 * t + lcq * 2];
        b2[t][1] = bo[n0 + 8 * t + lcq * 2 + 1];
    }
    #pragma unroll
    for (int mt = 0; mt < 2; mt++) {
        #pragma unroll
        for (int half = 0; half < 2; half++) {
            int m = m0 + w * 32 + mt * 16 + lr + half * 8;
            float* orow = out + (size_t)m * D_ + n0 + lcq * 2;
            #pragma unroll
            for (int t = 0; t < 8; t++) {
                float2 v;
                v.x = acc[mt][t][half * 2 + 0] + b2[t][0];
                v.y = acc[mt][t][half * 2 + 1] + b2[t][1];
                *(float2*)&orow[8 * t] = v;
            }
        }
    }
}

// ---------------------------------------------------------------------------
// Kernel 2: flash attention (R9 split-KV) with pipelined fragment loads.
// grid (S/64, BH*2), block 128, 3 CTAs/SM.
// ---------------------------------------------------------------------------
#define BUF_STRIDE 32768
#define ATTN_SMEM  (2 * 32768)

__global__ void __launch_bounds__(128, 3) attn_kernel()
{
    extern __shared__ char sm[];
    const u32 sb  = smem_u32(sm);
    const int tid = threadIdx.x;
    const int w   = tid >> 5;
    const int L   = tid & 31;
    const int bh   = blockIdx.y >> 1;
    const int half = blockIdx.y & 1;
    const int q0  = blockIdx.x * 64;

    const size_t head = (size_t)bh * S_ * (DH_ / 2);
    const size_t koff = (size_t)half * 2048 * 32;
    const u32* Qh = g_Qh + head;        const u32* Ql = g_Ql + head;
    const u32* Kh = g_Kh + head + koff; const u32* Kl = g_Kl + head + koff;
    const u32* Vh = g_Vh + head + koff; const u32* Vl = g_Vl + head + koff;

    const int rt = L & 7;
    const int lb = (L >> 3) & 1;
    const int lc = L >> 4;

    // ---- prologue: stage Q through buf0, extract frags, then start KV ----
    #pragma unroll
    for (int i = 0; i < 4; i++) {
        int idx = tid + i * 128;
        int r = idx >> 3, c = idx & 7;
        cp16(sb + swz(r, c),        Qh + (size_t)(q0 + r) * 32 + c * 4);
        cp16(sb + 8192 + swz(r, c), Ql + (size_t)(q0 + r) * 32 + c * 4);
    }
    CP_COMMIT();
    CP_WAIT(0);
    __syncthreads();

    u32 qh[4][4], ql[4][4];
    #pragma unroll
    for (int j = 0; j < 4; j++) {
        int row = w * 16 + rt + lb * 8;
        LDSM_A(qh[j], sb + swz(row, 2 * j + lc));
        LDSM_A(ql[j], sb + 8192 + swz(row, 2 * j + lc));
    }
    __syncthreads();   // Q fully read before buf0 reuse

    const u32* kvsrc[4] = {Kh, Kl, Vh, Vl};
    #pragma unroll
    for (int t0 = 0; t0 < 2; t0++) {
        u32 bufb = sb + t0 * BUF_STRIDE;
        #pragma unroll
        for (int m = 0; m < 4; m++)
            #pragma unroll
            for (int i = 0; i < 4; i++) {
                int idx = tid + i * 128;
                int r = idx >> 3, c = idx & 7;
                cp16(bufb + m * 8192 + swz(r, c),
                     kvsrc[m] + (size_t)(t0 * 64 + r) * 32 + c * 4);
            }
        CP_COMMIT();
    }

    float oacc[8][4];
    #pragma unroll
    for (int t = 0; t < 8; t++)
        #pragma unroll
        for (int e = 0; e < 4; e++) oacc[t][e] = 0.0f;
    float m_lo = -CUDART_INF_F, m_hi = -CUDART_INF_F;
    float l_lo = 0.0f, l_hi = 0.0f;

    const int NT = 2048 / 64;
    for (int it = 0; it < NT; it++) {
        CP_WAIT(1);
        __syncthreads();
        const u32 bufb = sb + (it & 1) * BUF_STRIDE;
        const u32 aKH = bufb, aKL = bufb + 8192;
        const u32 aVH = bufb + 16384, aVL = bufb + 24576;

        // ---- S = Q K^T (3-split), pipelined K-frag loads ----
        float sacc[8][4];
        #pragma unroll
        for (int t = 0; t < 8; t++)
            #pragma unroll
            for (int e = 0; e < 4; e++) sacc[t][e] = 0.0f;

        u32 khf[2][4], klf[2][4];
        LDSM_A(khf[0], aKH + swz(rt + lc * 8, lb));
        LDSM_A(klf[0], aKL + swz(rt + lc * 8, lb));

        #pragma unroll
        for (int g = 0; g < 16; g++) {
            const int j = g >> 2, p = g & 3;
            const int cb = g & 1, nb = cb ^ 1;
            if (g + 1 < 16) {
                const int jn = (g + 1) >> 2, pn = (g + 1) & 3;
                int row = 16 * pn + rt + lc * 8;
                int ch  = 2 * jn + lb;
                LDSM_A(khf[nb], aKH + swz(row, ch));
                LDSM_A(klf[nb], aKL + swz(row, ch));
            }
            mma_bf16(sacc[2*p],   qh[j], khf[cb][0], khf[cb][1]);
            mma_bf16(sacc[2*p+1], qh[j], khf[cb][2], khf[cb][3]);
            mma_bf16(sacc[2*p],   ql[j], khf[cb][0], khf[cb][1]);
            mma_bf16(sacc[2*p+1], ql[j], khf[cb][2], khf[cb][3]);
            mma_bf16(sacc[2*p],   qh[j], klf[cb][0], klf[cb][1]);
            mma_bf16(sacc[2*p+1], qh[j], klf[cb][2], klf[cb][3]);
        }

        // ---- row max (log2 domain) ----
        float mlo = -CUDART_INF_F, mhi = -CUDART_INF_F;
        #pragma unroll
        for (int t = 0; t < 8; t++) {
            mlo = fmaxf(mlo, fmaxf(sacc[t][0], sacc[t][1]));
            mhi = fmaxf(mhi, fmaxf(sacc[t][2], sacc[t][3]));
        }
        mlo = fmaxf(mlo, __shfl_xor_sync(0xffffffffu, mlo, 1));
        mlo = fmaxf(mlo, __shfl_xor_sync(0xffffffffu, mlo, 2));
        mhi = fmaxf(mhi, __shfl_xor_sync(0xffffffffu, mhi, 1));
        mhi = fmaxf(mhi, __shfl_xor_sync(0xffffffffu, mhi, 2));

        float mnlo = fmaxf(m_lo, mlo), mnhi = fmaxf(m_hi, mhi);
        float clo = ex2f(m_lo - mnlo), chi = ex2f(m_hi - mnhi);
        m_lo = mnlo; m_hi = mnhi;

        #pragma unroll
        for (int t = 0; t < 8; t++) {
            oacc[t][0] *= clo; oacc[t][1] *= clo;
            oacc[t][2] *= chi; oacc[t][3] *= chi;
        }

        // ---- PV with JIT P conversion, pipelined V-frag loads ----
        float alo = 0.0f, ahi = 0.0f;
        u32 vhf[2][4], vlf[2][4];
        LDSM_AT(vhf[0], aVH + swz(rt + lb * 8, lc));
        LDSM_AT(vlf[0], aVL + swz(rt + lb * 8, lc));

        #pragma unroll
        for (int j = 0; j < 4; j++) {
            u32 pa[4], pb[4];
            #pragma unroll
            for (int tt = 0; tt < 2; tt++) {
                const float* sv = sacc[2 * j + tt];
                float p0 = ex2f(sv[0] - mnlo);
                float p1 = ex2f(sv[1] - mnlo);
                float p2 = ex2f(sv[2] - mnhi);
                float p3 = ex2f(sv[3] - mnhi);
                alo += p0 + p1; ahi += p2 + p3;
                u32 h0 = cvt2(p1, p0), h1 = cvt2(p3, p2);
                pa[2 * tt]     = h0;
                pa[2 * tt + 1] = h1;
                pb[2 * tt]     = cvt2(p1 - bfhi(h0), p0 - bflo(h0));
                pb[2 * tt + 1] = cvt2(p3 - bfhi(h1), p2 - bflo(h1));
            }
            #pragma unroll
            for (int t = 0; t < 4; t++) {
                const int g = j * 4 + t;
                const int cb = g & 1, nb = cb ^ 1;
                if (g + 1 < 16) {
                    const int jn = (g + 1) >> 2, tn = (g + 1) & 3;
                    int row = 16 * jn + rt + lb * 8;
                    int ch  = 2 * tn + lc;
                    LDSM_AT(vhf[nb], aVH + swz(row, ch));
                    LDSM_AT(vlf[nb], aVL + swz(row, ch));
                }
                mma_bf16(oacc[2*t],   pa, vhf[cb][0], vhf[cb][1]);
                mma_bf16(oacc[2*t+1], pa, vhf[cb][2], vhf[cb][3]);
                mma_bf16(oacc[2*t],   pb, vhf[cb][0], vhf[cb][1]);
                mma_bf16(oacc[2*t+1], pb, vhf[cb][2], vhf[cb][3]);
                mma_bf16(oacc[2*t],   pa, vlf[cb][0], vlf[cb][1]);
                mma_bf16(oacc[2*t+1], pa, vlf[cb][2], vlf[cb][3]);
            }
        }
        l_lo = l_lo * clo + alo;
        l_hi = l_hi * chi + ahi;

        __syncthreads();
        if (it + 2 < NT) {
            u32 bb2 = sb + (it & 1) * BUF_STRIDE;
            int j2 = (it + 2) * 64;
            #pragma unroll
            for (int m = 0; m < 4; m++)
                #pragma unroll
                for (int i = 0; i < 4; i++) {
                    int idx = tid + i * 128;
                    int r = idx >> 3, c = idx & 7;
                    cp16(bb2 + m * 8192 + swz(r, c),
                         kvsrc[m] + (size_t)(j2 + r) * 32 + c * 4);
                }
        }
        CP_COMMIT();
    }

    // ---- epilogue: write UNNORMALIZED fp32 partials + (m,l) per row ----
    float llo = l_lo + __shfl_xor_sync(0xffffffffu, l_lo, 1);
    llo += __shfl_xor_sync(0xffffffffu, llo, 2);
    float lhi = l_hi + __shfl_xor_sync(0xffffffffu, l_hi, 1);
    lhi += __shfl_xor_sync(0xffffffffu, lhi, 2);

    const int rlo = q0 + w * 16 + (L >> 2);
    const size_t pbase = (size_t)(half * 16 + bh) * 4096;
    float* O0 = g_Op + (pbase + rlo)     * 64 + (L & 3) * 2;
    float* O1 = g_Op + (pbase + rlo + 8) * 64 + (L & 3) * 2;
    #pragma unroll
    for (int t = 0; t < 8; t++) {
        *(float2*)&O0[8 * t] = make_float2(oacc[t][0], oacc[t][1]);
        *(float2*)&O1[8 * t] = make_float2(oacc[t][2], oacc[t][3]);
    }
    if ((L & 3) == 0) {
        g_m[pbase + rlo]     = m_lo;  g_l[pbase + rlo]     = llo;
        g_m[pbase + rlo + 8] = m_hi;  g_l[pbase + rlo + 8] = lhi;
    }
}

// ---------------------------------------------------------------------------
// Kernel 2b: combine split-KV halves -> split-bf16 attention output.
// Vectorized: one thread per 8 columns (2x float4 per half).
// ---------------------------------------------------------------------------
__global__ void __launch_bounds__(256) combine_kernel()
{
    const int idx = blockIdx.x * 256 + threadIdx.x;   // < 524288
    const int bh  = idx >> 15;
    const int rem = idx & 32767;
    const int row = rem >> 3;
    const int q   = rem & 7;

    const int b0 = bh * 4096 + row;
    const int b1 = (16 + bh) * 4096 + row;
    const float m1 = g_m[b0], l1 = g_l[b0];
    const float m2 = g_m[b1], l2 = g_l[b1];
    const float ms = fmaxf(m1, m2);
    const float c1 = ex2f(m1 - ms), c2 = ex2f(m2 - ms);
    const float inv = 1.0f / (c1 * l1 + c2 * l2);
    const float s1 = c1 * inv, s2 = c2 * inv;

    const float4* p1 = (const float4*)(g_Op + (size_t)b0 * 64 + q * 8);
    const float4* p2 = (const float4*)(g_Op + (size_t)b1 * 64 + q * 8);
    float4 a0 = p1[0], a1 = p1[1];
    float4 d0 = p2[0], d1 = p2[1];
    float v[8];
    v[0] = s1 * a0.x + s2 * d0.x;  v[1] = s1 * a0.y + s2 * d0.y;
    v[2] = s1 * a0.z + s2 * d0.z;  v[3] = s1 * a0.w + s2 * d0.w;
    v[4] = s1 * a1.x + s2 * d1.x;  v[5] = s1 * a1.y + s2 * d1.y;
    v[6] = s1 * a1.z + s2 * d1.z;  v[7] = s1 * a1.w + s2 * d1.w;

    uint4 oh, ol;
    u32* ohp = (u32*)&oh; u32* olp = (u32*)&ol;
    #pragma unroll
    for (int i = 0; i < 4; i++) {
        u32 h = cvt2(v[2 * i + 1], v[2 * i]);
        ohp[i] = h;
        olp[i] = cvt2(v[2 * i + 1] - bfhi(h), v[2 * i] - bflo(h));
    }
    const size_t rw = ((size_t)((bh >> 2) * S_) + row) * ROW_WORDS
                      + (bh & 3) * 32 + q * 4;
    *(uint4*)(g_Ah + rw) = oh;
    *(uint4*)(g_Al + rw) = ol;
}

// ---------------------------------------------------------------------------
// Launch
// ---------------------------------------------------------------------------
extern "C" void kernel_launch(void* const* d_in, const int* in_sizes, int n_in,
                              void* d_out, int out_size)
{
    const float* X  = (const float*)d_in[0];
    const float* Wq = (const float*)d_in[1];
    const float* bq = (const float*)d_in[2];
    const float* Wk = (const float*)d_in[3];
    const float* bk = (const float*)d_in[4];
    const float* Wv = (const float*)d_in[5];
    const float* bv = (const float*)d_in[6];
    const float* Wo = (const float*)d_in[7];
    const float* bo = (const float*)d_in[8];
    float* out = (float*)d_out;

    cudaFuncSetAttribute(attn_kernel,
                         cudaFuncAttributeMaxDynamicSharedMemorySize, ATTN_SMEM);
    cudaFuncSetAttribute(qkv_hmma,
                         cudaFuncAttributeMaxDynamicSharedMemorySize, GEMM_SMEM);
    cudaFuncSetAttribute(out_hmma,
                         cudaFuncAttributeMaxDynamicSharedMemorySize, GEMM_SMEM);

    prep_kernel<<<(XWORDS + WWORDS + 255) / 256, 256>>>(X, Wq, Wk, Wv, Wo);
    qkv_hmma<<<dim3(MT_ / 128, H_, 3), 128, GEMM_SMEM>>>(bq, bk, bv);
    attn_kernel<<<dim3(S_ / 64, BH_ * 2), 128, ATTN_SMEM>>>();
    combine_kernel<<<2048, 256>>>();
    out_hmma<<<dim3(MT_ / 128, 4), 128, GEMM_SMEM>>>(bo, out);
}

// round 11
// speedup vs baseline: 1.1499x; 1.0037x over previous
#include <cuda_runtime.h>
#include <cuda_bf16.h>
#include <math_constants.h>

#define B_  4
#define S_  4096
#define D_  256
#define H_  4
#define DH_ 64
#define MT_ (B_ * S_)
#define BH_ (B_ * H_)
#define LOG2E 1.4426950408889634f

typedef unsigned int       u32;
typedef unsigned long long u64;

// ---------------------------------------------------------------------------
// Scratch
// ---------------------------------------------------------------------------
#define QKV_WORDS ((size_t)BH_ * S_ * (DH_ / 2))
#define ROW_WORDS (D_ / 2)
__device__ u32 g_Qh[QKV_WORDS];  __device__ u32 g_Ql[QKV_WORDS];
__device__ u32 g_Kh[QKV_WORDS];  __device__ u32 g_Kl[QKV_WORDS];
__device__ u32 g_Vh[QKV_WORDS];  __device__ u32 g_Vl[QKV_WORDS];
__device__ u32 g_Xh[(size_t)MT_ * ROW_WORDS];
__device__ u32 g_Xl[(size_t)MT_ * ROW_WORDS];
__device__ u32 g_Ah[(size_t)MT_ * ROW_WORDS];
__device__ u32 g_Al[(size_t)MT_ * ROW_WORDS];
__device__ u32 g_Wth[4 * 256 * ROW_WORDS];
__device__ u32 g_Wtl[4 * 256 * ROW_WORDS];
// split-KV partials
__device__ float g_Op[(size_t)2 * 16 * 4096 * 64];
__device__ float g_m[2 * 16 * 4096];
__device__ float g_l[2 * 16 * 4096];

// ---------------------------------------------------------------------------
// PTX helpers (baseline PTX only)
// ---------------------------------------------------------------------------
__device__ __forceinline__ u32 smem_u32(const void* p) {
    u32 a;
    asm("{ .reg .u64 t; cvta.to.shared.u64 t, %1; cvt.u32.u64 %0, t; }"
        : "=r"(a) : "l"(p));
    return a;
}
__device__ __forceinline__ u32 cvt2(float a, float b) {   // {hi=bf16(a), lo=bf16(b)}
    u32 r;
    asm("cvt.rn.bf16x2.f32 %0, %1, %2;" : "=r"(r) : "f"(a), "f"(b));
    return r;
}
__device__ __forceinline__ float bflo(u32 w) { return __uint_as_float(w << 16); }
__device__ __forceinline__ float bfhi(u32 w) { return __uint_as_float(w & 0xffff0000u); }
__device__ __forceinline__ float ex2f(float x) {
    float y; asm("ex2.approx.f32 %0, %1;" : "=f"(y) : "f"(x)); return y;
}
__device__ __forceinline__ void mma_bf16(float c[4], const u32 a[4], u32 b0, u32 b1) {
    asm volatile(
        "mma.sync.aligned.m16n8k16.row.col.f32.bf16.bf16.f32 "
        "{%0,%1,%2,%3},{%4,%5,%6,%7},{%8,%9},{%0,%1,%2,%3};"
        : "+f"(c[0]), "+f"(c[1]), "+f"(c[2]), "+f"(c[3])
        : "r"(a[0]), "r"(a[1]), "r"(a[2]), "r"(a[3]), "r"(b0), "r"(b1));
}
#define LDSM_X4(r0, r1, r2, r3, a) \
    asm volatile("ldmatrix.sync.aligned.m8n8.x4.shared.b16 {%0,%1,%2,%3}, [%4];" \
                 : "=r"(r0), "=r"(r1), "=r"(r2), "=r"(r3) : "r"(a))
#define LDSM_A(fr, a) LDSM_X4(fr[0], fr[1], fr[2], fr[3], a)
#define LDSM_X4T(r0, r1, r2, r3, a) \
    asm volatile("ldmatrix.sync.aligned.m8n8.x4.trans.shared.b16 {%0,%1,%2,%3}, [%4];" \
                 : "=r"(r0), "=r"(r1), "=r"(r2), "=r"(r3) : "r"(a))
#define LDSM_AT(fr, a) LDSM_X4T(fr[0], fr[1], fr[2], fr[3], a)
__device__ __forceinline__ void cp16(u32 dst, const void* src) {
    asm volatile("cp.async.cg.shared.global [%0], [%1], 16;" :: "r"(dst), "l"(src));
}
#define CP_COMMIT() asm volatile("cp.async.commit_group;" ::: "memory")
#define CP_WAIT(n)  asm volatile("cp.async.wait_group %0;" :: "n"(n) : "memory")

// 128-byte-row swizzle (attn tiles)
__device__ __forceinline__ u32 swz(int row, int chunk) {
    return (u32)(row * 128 + (((chunk ^ row) & 7) << 4));
}
// 64-byte-row swizzle (GEMM kb=32 tiles): chunk ^= (row>>1)&3
__device__ __forceinline__ u32 swz64(int row, int chunk) {
    return (u32)(row * 64 + (((chunk ^ (row >> 1)) & 3) << 4));
}

// ---------------------------------------------------------------------------
// Kernel 0: prep — split X; transpose+split W matrices.
// ---------------------------------------------------------------------------
#define XWORDS (2097152)
#define WWORDS (131072)
__global__ void __launch_bounds__(256) prep_kernel(
    const float* __restrict__ X,
    const float* __restrict__ Wq, const float* __restrict__ Wk,
    const float* __restrict__ Wv, const float* __restrict__ Wo)
{
    const int w = blockIdx.x * 256 + threadIdx.x;
    if (w < XWORDS) {
        float2 f = ((const float2*)X)[w];
        u32 hi = cvt2(f.y, f.x);
        g_Xh[w] = hi;
        g_Xl[w] = cvt2(f.y - bfhi(hi), f.x - bflo(hi));
    } else if (w < XWORDS + WWORDS) {
        int u = w - XWORDS;
        int z = u >> 15, r = u & 32767;
        int n = r >> 7, kp = r & 127;
        const float* Wm = (z == 0) ? Wq : (z == 1) ? Wk : (z == 2) ? Wv : Wo;
        float f0 = Wm[(size_t)(2 * kp)     * 256 + n];
        float f1 = Wm[(size_t)(2 * kp + 1) * 256 + n];
        u32 hi = cvt2(f1, f0);
        g_Wth[u] = hi;
        g_Wtl[u] = cvt2(f1 - bfhi(hi), f0 - bflo(hi));
    }
}

// ---------------------------------------------------------------------------
// HMMA GEMM core — kb=32: 8 k-stages, GBUF 24KB (x2 = 48KB), 3 CTAs/SM.
// 128 threads (4 warps x 32 rows mt2), tile 128x64.
// ---------------------------------------------------------------------------
#define GB_AH 0
#define GB_AL 8192
#define GB_BH 16384
#define GB_BL 20480
#define GBUF  24576
#define GEMM_SMEM (2 * GBUF)

__device__ __forceinline__ void gemm_stage(u32 sb, int bufi, int kb,
                                           const u32* Ah, const u32* Al,
                                           const u32* Bh, const u32* Bl,
                                           int m0, int n0, int tid)
{
    const u32 bufb = sb + bufi * GBUF;
    // A: 128 rows x 4 chunks (16B) per array = 512 chunks
    #pragma unroll
    for (int i = 0; i < 4; i++) {
        int idx = tid + i * 128;
        int r = idx >> 2, c = idx & 3;
        const size_t go = (size_t)(m0 + r) * ROW_WORDS + kb * 16 + c * 4;
        cp16(bufb + GB_AH + swz64(r, c), Ah + go);
        cp16(bufb + GB_AL + swz64(r, c), Al + go);
    }
    // B: 64 rows x 4 chunks = 256 chunks
    #pragma unroll
    for (int i = 0; i < 2; i++) {
        int idx = tid + i * 128;
        int r = idx >> 2, c = idx & 3;
        const size_t go = (size_t)(n0 + r) * ROW_WORDS + kb * 16 + c * 4;
        cp16(bufb + GB_BH + swz64(r, c), Bh + go);
        cp16(bufb + GB_BL + swz64(r, c), Bl + go);
    }
}

__device__ __forceinline__ void gemm_main(u32 sb, float acc[2][8][4],
                                          const u32* Ah, const u32* Al,
                                          const u32* Bh, const u32* Bl,
                                          int m0, int n0, int tid)
{
    const int w  = tid >> 5;
    const int L  = tid & 31;
    const int rt = L & 7;
    const int lb = (L >> 3) & 1;
    const int lc = L >> 4;

    gemm_stage(sb, 0, 0, Ah, Al, Bh, Bl, m0, n0, tid);
    CP_COMMIT();
    gemm_stage(sb, 1, 1, Ah, Al, Bh, Bl, m0, n0, tid);
    CP_COMMIT();

    #pragma unroll 2
    for (int kb = 0; kb < 8; kb++) {
        CP_WAIT(1);
        __syncthreads();
        const u32 bufb = sb + (kb & 1) * GBUF;
        const u32 aAH = bufb + GB_AH, aAL = bufb + GB_AL;
        const u32 aBH = bufb + GB_BH, aBL = bufb + GB_BL;

        #pragma unroll
        for (int j = 0; j < 2; j++) {          // k16 steps within kb32
            u32 ah[2][4], al[2][4];
            #pragma unroll
            for (int mt = 0; mt < 2; mt++) {
                int row = w * 32 + mt * 16 + rt + lb * 8;
                LDSM_A(ah[mt], aAH + swz64(row, 2 * j + lc));
                LDSM_A(al[mt], aAL + swz64(row, 2 * j + lc));
            }
            #pragma unroll
            for (int p = 0; p < 4; p++) {
                int row = 16 * p + rt + lc * 8;
                int ch  = 2 * j + lb;
                u32 bh0, bh1, bh2, bh3, bl0, bl1, bl2, bl3;
                LDSM_X4(bh0, bh1, bh2, bh3, aBH + swz64(row, ch));
                LDSM_X4(bl0, bl1, bl2, bl3, aBL + swz64(row, ch));
                mma_bf16(acc[0][2*p],   ah[0], bh0, bh1);
                mma_bf16(acc[0][2*p+1], ah[0], bh2, bh3);
                mma_bf16(acc[1][2*p],   ah[1], bh0, bh1);
                mma_bf16(acc[1][2*p+1], ah[1], bh2, bh3);
                mma_bf16(acc[0][2*p],   al[0], bh0, bh1);
                mma_bf16(acc[0][2*p+1], al[0], bh2, bh3);
                mma_bf16(acc[1][2*p],   al[1], bh0, bh1);
                mma_bf16(acc[1][2*p+1], al[1], bh2, bh3);
                mma_bf16(acc[0][2*p],   ah[0], bl0, bl1);
                mma_bf16(acc[0][2*p+1], ah[0], bl2, bl3);
                mma_bf16(acc[1][2*p],   ah[1], bl0, bl1);
                mma_bf16(acc[1][2*p+1], ah[1], bl2, bl3);
            }
        }
        __syncthreads();
        if (kb + 2 < 8)
            gemm_stage(sb, kb & 1, kb + 2, Ah, Al, Bh, Bl, m0, n0, tid);
        CP_COMMIT();
    }
}

// ---------------------------------------------------------------------------
// Kernel 1: QKV projection. grid (MT/128, H, 3), block 128, 3 CTAs/SM.
// ---------------------------------------------------------------------------
__global__ void __launch_bounds__(128, 3) qkv_hmma(
    const float* __restrict__ bq, const float* __restrict__ bk,
    const float* __restrict__ bv)
{
    extern __shared__ char sm[];
    const u32 sb  = smem_u32(sm);
    const int tid = threadIdx.x;
    const int z   = blockIdx.z;
    const int h   = blockIdx.y;
    const int m0  = blockIdx.x * 128;
    const int n0  = h * 64;

    const float* bias = (z == 0) ? bq : (z == 1) ? bk : bv;
    u32* oh = (z == 0) ? g_Qh : (z == 1) ? g_Kh : g_Vh;
    u32* ol = (z == 0) ? g_Ql : (z == 1) ? g_Kl : g_Vl;
    const float qs = (z == 0) ? (0.125f * LOG2E) : 1.0f;

    float acc[2][8][4];
    #pragma unroll
    for (int mt = 0; mt < 2; mt++)
        #pragma unroll
        for (int t = 0; t < 8; t++)
            #pragma unroll
            for (int e = 0; e < 4; e++) acc[mt][t][e] = 0.0f;

    gemm_main(sb, acc, g_Xh, g_Xl,
              g_Wth + (size_t)z * 256 * ROW_WORDS,
              g_Wtl + (size_t)z * 256 * ROW_WORDS, m0, n0, tid);

    const int w  = tid >> 5;
    const int L  = tid & 31;
    const int lr = L >> 2, lcq = L & 3;
    float b2[8][2];
    #pragma unroll
    for (int t = 0; t < 8; t++) {
        b2[t][0] = bias[n0 + 8 * t + lcq * 2];
        b2[t][1] = bias[n0 + 8 * t + lcq * 2 + 1];
    }
    const int bb = m0 >> 12;
    const int sbase = m0 & (S_ - 1);
    #pragma unroll
    for (int mt = 0; mt < 2; mt++) {
        #pragma unroll
        for (int half = 0; half < 2; half++) {
            int s = sbase + w * 32 + mt * 16 + lr + half * 8;
            size_t rw = ((size_t)(bb * H_ + h) * S_ + s) * 32 + lcq;
            #pragma unroll
            for (int t = 0; t < 8; t++) {
                float v0 = (acc[mt][t][half * 2 + 0] + b2[t][0]) * qs;
                float v1 = (acc[mt][t][half * 2 + 1] + b2[t][1]) * qs;
                u32 hi = cvt2(v1, v0);
                oh[rw + 4 * t] = hi;
                ol[rw + 4 * t] = cvt2(v1 - bfhi(hi), v0 - bflo(hi));
            }
        }
    }
}

// ---------------------------------------------------------------------------
// Kernel 3: output projection. grid (MT/128, 4), block 128, 3 CTAs/SM.
// ---------------------------------------------------------------------------
__global__ void __launch_bounds__(128, 3) out_hmma(
    const float* __restrict__ bo, float* __restrict__ out)
{
    extern __shared__ char sm[];
    const u32 sb  = smem_u32(sm);
    const int tid = threadIdx.x;
    const int m0  = blockIdx.x * 128;
    const int n0  = blockIdx.y * 64;

    float acc[2][8][4];
    #pragma unroll
    for (int mt = 0; mt < 2; mt++)
        #pragma unroll
        for (int t = 0; t < 8; t++)
            #pragma unroll
            for (int e = 0; e < 4; e++) acc[mt][t][e] = 0.0f;

    gemm_main(sb, acc, g_Ah, g_Al,
              g_Wth + (size_t)3 * 256 * ROW_WORDS,
              g_Wtl + (size_t)3 * 256 * ROW_WORDS, m0, n0, tid);

    const int w  = tid >> 5;
    const int L  = tid & 31;
    const int lr = L >> 2, lcq = L & 3;
    float b2[8][2];
    #pragma unroll
    for (int t = 0; t < 8; t++) {
        b2[t][0] = bo[n0 + 8 * t + lcq * 2];
        b2[t][1] = bo[n0 + 8 * t + lcq * 2 + 1];
    }
    #pragma unroll
    for (int mt = 0; mt < 2; mt++) {
        #pragma unroll
        for (int half = 0; half < 2; half++) {
            int m = m0 + w * 32 + mt * 16 + lr + half * 8;
            float* orow = out + (size_t)m * D_ + n0 + lcq * 2;
            #pragma unroll
            for (int t = 0; t < 8; t++) {
                float2 v;
                v.x = acc[mt][t][half * 2 + 0] + b2[t][0];
                v.y = acc[mt][t][half * 2 + 1] + b2[t][1];
                *(float2*)&orow[8 * t] = v;
            }
        }
    }
}

// ---------------------------------------------------------------------------
// Kernel 2: flash attention (R10, unchanged — best known config).
// grid (S/64, BH*2), block 128, 3 CTAs/SM.
// ---------------------------------------------------------------------------
#define BUF_STRIDE 32768
#define ATTN_SMEM  (2 * 32768)

__global__ void __launch_bounds__(128, 3) attn_kernel()
{
    extern __shared__ char sm[];
    const u32 sb  = smem_u32(sm);
    const int tid = threadIdx.x;
    const int w   = tid >> 5;
    const int L   = tid & 31;
    const int bh   = blockIdx.y >> 1;
    const int half = blockIdx.y & 1;
    const int q0  = blockIdx.x * 64;

    const size_t head = (size_t)bh * S_ * (DH_ / 2);
    const size_t koff = (size_t)half * 2048 * 32;
    const u32* Qh = g_Qh + head;        const u32* Ql = g_Ql + head;
    const u32* Kh = g_Kh + head + koff; const u32* Kl = g_Kl + head + koff;
    const u32* Vh = g_Vh + head + koff; const u32* Vl = g_Vl + head + koff;

    const int rt = L & 7;
    const int lb = (L >> 3) & 1;
    const int lc = L >> 4;

    #pragma unroll
    for (int i = 0; i < 4; i++) {
        int idx = tid + i * 128;
        int r = idx >> 3, c = idx & 7;
        cp16(sb + swz(r, c),        Qh + (size_t)(q0 + r) * 32 + c * 4);
        cp16(sb + 8192 + swz(r, c), Ql + (size_t)(q0 + r) * 32 + c * 4);
    }
    CP_COMMIT();
    CP_WAIT(0);
    __syncthreads();

    u32 qh[4][4], ql[4][4];
    #pragma unroll
    for (int j = 0; j < 4; j++) {
        int row = w * 16 + rt + lb * 8;
        LDSM_A(qh[j], sb + swz(row, 2 * j + lc));
        LDSM_A(ql[j], sb + 8192 + swz(row, 2 * j + lc));
    }
    __syncthreads();

    const u32* kvsrc[4] = {Kh, Kl, Vh, Vl};
    #pragma unroll
    for (int t0 = 0; t0 < 2; t0++) {
        u32 bufb = sb + t0 * BUF_STRIDE;
        #pragma unroll
        for (int m = 0; m < 4; m++)
            #pragma unroll
            for (int i = 0; i < 4; i++) {
                int idx = tid + i * 128;
                int r = idx >> 3, c = idx & 7;
                cp16(bufb + m * 8192 + swz(r, c),
                     kvsrc[m] + (size_t)(t0 * 64 + r) * 32 + c * 4);
            }
        CP_COMMIT();
    }

    float oacc[8][4];
    #pragma unroll
    for (int t = 0; t < 8; t++)
        #pragma unroll
        for (int e = 0; e < 4; e++) oacc[t][e] = 0.0f;
    float m_lo = -CUDART_INF_F, m_hi = -CUDART_INF_F;
    float l_lo = 0.0f, l_hi = 0.0f;

    const int NT = 2048 / 64;
    for (int it = 0; it < NT; it++) {
        CP_WAIT(1);
        __syncthreads();
        const u32 bufb = sb + (it & 1) * BUF_STRIDE;
        const u32 aKH = bufb, aKL = bufb + 8192;
        const u32 aVH = bufb + 16384, aVL = bufb + 24576;

        float sacc[8][4];
        #pragma unroll
        for (int t = 0; t < 8; t++)
            #pragma unroll
            for (int e = 0; e < 4; e++) sacc[t][e] = 0.0f;

        u32 khf[2][4], klf[2][4];
        LDSM_A(khf[0], aKH + swz(rt + lc * 8, lb));
        LDSM_A(klf[0], aKL + swz(rt + lc * 8, lb));

        #pragma unroll
        for (int g = 0; g < 16; g++) {
            const int j = g >> 2, p = g & 3;
            const int cb = g & 1, nb = cb ^ 1;
            if (g + 1 < 16) {
                const int jn = (g + 1) >> 2, pn = (g + 1) & 3;
                int row = 16 * pn + rt + lc * 8;
                int ch  = 2 * jn + lb;
                LDSM_A(khf[nb], aKH + swz(row, ch));
                LDSM_A(klf[nb], aKL + swz(row, ch));
            }
            mma_bf16(sacc[2*p],   qh[j], khf[cb][0], khf[cb][1]);
            mma_bf16(sacc[2*p+1], qh[j], khf[cb][2], khf[cb][3]);
            mma_bf16(sacc[2*p],   ql[j], khf[cb][0], khf[cb][1]);
            mma_bf16(sacc[2*p+1], ql[j], khf[cb][2], khf[cb][3]);
            mma_bf16(sacc[2*p],   qh[j], klf[cb][0], klf[cb][1]);
            mma_bf16(sacc[2*p+1], qh[j], klf[cb][2], klf[cb][3]);
        }

        float mlo = -CUDART_INF_F, mhi = -CUDART_INF_F;
        #pragma unroll
        for (int t = 0; t < 8; t++) {
            mlo = fmaxf(mlo, fmaxf(sacc[t][0], sacc[t][1]));
            mhi = fmaxf(mhi, fmaxf(sacc[t][2], sacc[t][3]));
        }
        mlo = fmaxf(mlo, __shfl_xor_sync(0xffffffffu, mlo, 1));
        mlo = fmaxf(mlo, __shfl_xor_sync(0xffffffffu, mlo, 2));
        mhi = fmaxf(mhi, __shfl_xor_sync(0xffffffffu, mhi, 1));
        mhi = fmaxf(mhi, __shfl_xor_sync(0xffffffffu, mhi, 2));

        float mnlo = fmaxf(m_lo, mlo), mnhi = fmaxf(m_hi, mhi);
        float clo = ex2f(m_lo - mnlo), chi = ex2f(m_hi - mnhi);
        m_lo = mnlo; m_hi = mnhi;

        #pragma unroll
        for (int t = 0; t < 8; t++) {
            oacc[t][0] *= clo; oacc[t][1] *= clo;
            oacc[t][2] *= chi; oacc[t][3] *= chi;
        }

        float alo = 0.0f, ahi = 0.0f;
        u32 vhf[2][4], vlf[2][4];
        LDSM_AT(vhf[0], aVH + swz(rt + lb * 8, lc));
        LDSM_AT(vlf[0], aVL + swz(rt + lb * 8, lc));

        #pragma unroll
        for (int j = 0; j < 4; j++) {
            u32 pa[4], pb[4];
            #pragma unroll
            for (int tt = 0; tt < 2; tt++) {
                const float* sv = sacc[2 * j + tt];
                float p0 = ex2f(sv[0] - mnlo);
                float p1 = ex2f(sv[1] - mnlo);
                float p2 = ex2f(sv[2] - mnhi);
                float p3 = ex2f(sv[3] - mnhi);
                alo += p0 + p1; ahi += p2 + p3;
                u32 h0 = cvt2(p1, p0), h1 = cvt2(p3, p2);
                pa[2 * tt]     = h0;
                pa[2 * tt + 1] = h1;
                pb[2 * tt]     = cvt2(p1 - bfhi(h0), p0 - bflo(h0));
                pb[2 * tt + 1] = cvt2(p3 - bfhi(h1), p2 - bflo(h1));
            }
            #pragma unroll
            for (int t = 0; t < 4; t++) {
                const int g = j * 4 + t;
                const int cb = g & 1, nb = cb ^ 1;
                if (g + 1 < 16) {
                    const int jn = (g + 1) >> 2, tn = (g + 1) & 3;
                    int row = 16 * jn + rt + lb * 8;
                    int ch  = 2 * tn + lc;
                    LDSM_AT(vhf[nb], aVH + swz(row, ch));
                    LDSM_AT(vlf[nb], aVL + swz(row, ch));
                }
                mma_bf16(oacc[2*t],   pa, vhf[cb][0], vhf[cb][1]);
                mma_bf16(oacc[2*t+1], pa, vhf[cb][2], vhf[cb][3]);
                mma_bf16(oacc[2*t],   pb, vhf[cb][0], vhf[cb][1]);
                mma_bf16(oacc[2*t+1], pb, vhf[cb][2], vhf[cb][3]);
                mma_bf16(oacc[2*t],   pa, vlf[cb][0], vlf[cb][1]);
                mma_bf16(oacc[2*t+1], pa, vlf[cb][2], vlf[cb][3]);
            }
        }
        l_lo = l_lo * clo + alo;
        l_hi = l_hi * chi + ahi;

        __syncthreads();
        if (it + 2 < NT) {
            u32 bb2 = sb + (it & 1) * BUF_STRIDE;
            int j2 = (it + 2) * 64;
            #pragma unroll
            for (int m = 0; m < 4; m++)
                #pragma unroll
                for (int i = 0; i < 4; i++) {
                    int idx = tid + i * 128;
                    int r = idx >> 3, c = idx & 7;
                    cp16(bb2 + m * 8192 + swz(r, c),
                         kvsrc[m] + (size_t)(j2 + r) * 32 + c * 4);
                }
        }
        CP_COMMIT();
    }

    float llo = l_lo + __shfl_xor_sync(0xffffffffu, l_lo, 1);
    llo += __shfl_xor_sync(0xffffffffu, llo, 2);
    float lhi = l_hi + __shfl_xor_sync(0xffffffffu, l_hi, 1);
    lhi += __shfl_xor_sync(0xffffffffu, lhi, 2);

    const int rlo = q0 + w * 16 + (L >> 2);
    const size_t pbase = (size_t)(half * 16 + bh) * 4096;
    float* O0 = g_Op + (pbase + rlo)     * 64 + (L & 3) * 2;
    float* O1 = g_Op + (pbase + rlo + 8) * 64 + (L & 3) * 2;
    #pragma unroll
    for (int t = 0; t < 8; t++) {
        *(float2*)&O0[8 * t] = make_float2(oacc[t][0], oacc[t][1]);
        *(float2*)&O1[8 * t] = make_float2(oacc[t][2], oacc[t][3]);
    }
    if ((L & 3) == 0) {
        g_m[pbase + rlo]     = m_lo;  g_l[pbase + rlo]     = llo;
        g_m[pbase + rlo + 8] = m_hi;  g_l[pbase + rlo + 8] = lhi;
    }
}

// ---------------------------------------------------------------------------
// Kernel 2b: combine split-KV halves (R10 vectorized).
// ---------------------------------------------------------------------------
__global__ void __launch_bounds__(256) combine_kernel()
{
    const int idx = blockIdx.x * 256 + threadIdx.x;
    const int bh  = idx >> 15;
    const int rem = idx & 32767;
    const int row = rem >> 3;
    const int q   = rem & 7;

    const int b0 = bh * 4096 + row;
    const int b1 = (16 + bh) * 4096 + row;
    const float m1 = g_m[b0], l1 = g_l[b0];
    const float m2 = g_m[b1], l2 = g_l[b1];
    const float ms = fmaxf(m1, m2);
    const float c1 = ex2f(m1 - ms), c2 = ex2f(m2 - ms);
    const float inv = 1.0f / (c1 * l1 + c2 * l2);
    const float s1 = c1 * inv, s2 = c2 * inv;

    const float4* p1 = (const float4*)(g_Op + (size_t)b0 * 64 + q * 8);
    const float4* p2 = (const float4*)(g_Op + (size_t)b1 * 64 + q * 8);
    float4 a0 = p1[0], a1 = p1[1];
    float4 d0 = p2[0], d1 = p2[1];
    float v[8];
    v[0] = s1 * a0.x + s2 * d0.x;  v[1] = s1 * a0.y + s2 * d0.y;
    v[2] = s1 * a0.z + s2 * d0.z;  v[3] = s1 * a0.w + s2 * d0.w;
    v[4] = s1 * a1.x + s2 * d1.x;  v[5] = s1 * a1.y + s2 * d1.y;
    v[6] = s1 * a1.z + s2 * d1.z;  v[7] = s1 * a1.w + s2 * d1.w;

    uint4 oh, ol;
    u32* ohp = (u32*)&oh; u32* olp = (u32*)&ol;
    #pragma unroll
    for (int i = 0; i < 4; i++) {
        u32 h = cvt2(v[2 * i + 1], v[2 * i]);
        ohp[i] = h;
        olp[i] = cvt2(v[2 * i + 1] - bfhi(h), v[2 * i] - bflo(h));
    }
    const size_t rw = ((size_t)((bh >> 2) * S_) + row) * ROW_WORDS
                      + (bh & 3) * 32 + q * 4;
    *(uint4*)(g_Ah + rw) = oh;
    *(uint4*)(g_Al + rw) = ol;
}

// ---------------------------------------------------------------------------
// Launch
// ---------------------------------------------------------------------------
extern "C" void kernel_launch(void* const* d_in, const int* in_sizes, int n_in,
                              void* d_out, int out_size)
{
    const float* X  = (const float*)d_in[0];
    const float* Wq = (const float*)d_in[1];
    const float* bq = (const float*)d_in[2];
    const float* Wk = (const float*)d_in[3];
    const float* bk = (const float*)d_in[4];
    const float* Wv = (const float*)d_in[5];
    const float* bv = (const float*)d_in[6];
    const float* Wo = (const float*)d_in[7];
    const float* bo = (const float*)d_in[8];
    float* out = (float*)d_out;

    cudaFuncSetAttribute(attn_kernel,
                         cudaFuncAttributeMaxDynamicSharedMemorySize, ATTN_SMEM);
    cudaFuncSetAttribute(qkv_hmma,
                         cudaFuncAttributeMaxDynamicSharedMemorySize, GEMM_SMEM);
    cudaFuncSetAttribute(out_hmma,
                         cudaFuncAttributeMaxDynamicSharedMemorySize, GEMM_SMEM);

    prep_kernel<<<(XWORDS + WWORDS + 255) / 256, 256>>>(X, Wq, Wk, Wv, Wo);
    qkv_hmma<<<dim3(MT_ / 128, H_, 3), 128, GEMM_SMEM>>>(bq, bk, bv);
    attn_kernel<<<dim3(S_ / 64, BH_ * 2), 128, ATTN_SMEM>>>();
    combine_kernel<<<2048, 256>>>();
    out_hmma<<<dim3(MT_ / 128, 4), 128, GEMM_SMEM>>>(bo, out);
}

// round 12
// speedup vs baseline: 1.5332x; 1.3334x over previous
#include <cuda_runtime.h>
#include <cuda_fp16.h>
#include <math_constants.h>

#define B_  4
#define S_  4096
#define D_  256
#define H_  4
#define DH_ 64
#define MT_ (B_ * S_)
#define BH_ (B_ * H_)
#define LOG2E 1.4426950408889634f

typedef unsigned int       u32;
typedef unsigned long long u64;

// ---------------------------------------------------------------------------
// Scratch (fp16 hi/lo split, packed u32 = {hi16: odd col, lo16: even col})
// ---------------------------------------------------------------------------
#define QKV_WORDS ((size_t)BH_ * S_ * (DH_ / 2))
#define ROW_WORDS (D_ / 2)
__device__ u32 g_Qh[QKV_WORDS];  __device__ u32 g_Ql[QKV_WORDS];
__device__ u32 g_Kh[QKV_WORDS];  __device__ u32 g_Kl[QKV_WORDS];
__device__ u32 g_Vh[QKV_WORDS];                       // V: fp16 only (1-term PV)
__device__ u32 g_Xh[(size_t)MT_ * ROW_WORDS];
__device__ u32 g_Xl[(size_t)MT_ * ROW_WORDS];
__device__ u32 g_Ah[(size_t)MT_ * ROW_WORDS];
__device__ u32 g_Al[(size_t)MT_ * ROW_WORDS];
__device__ u32 g_Wth[4 * 256 * ROW_WORDS];
__device__ u32 g_Wtl[4 * 256 * ROW_WORDS];
// split-KV partials
__device__ float g_Op[(size_t)2 * 16 * 4096 * 64];
__device__ float g_m[2 * 16 * 4096];
__device__ float g_l[2 * 16 * 4096];

// ---------------------------------------------------------------------------
// PTX helpers (baseline PTX only)
// ---------------------------------------------------------------------------
__device__ __forceinline__ u32 smem_u32(const void* p) {
    u32 a;
    asm("{ .reg .u64 t; cvta.to.shared.u64 t, %1; cvt.u32.u64 %0, t; }"
        : "=r"(a) : "l"(p));
    return a;
}
__device__ __forceinline__ u32 cvt2(float a, float b) {   // {hi16=f16(a), lo16=f16(b)}
    u32 r;
    asm("cvt.rn.f16x2.f32 %0, %1, %2;" : "=r"(r) : "f"(a), "f"(b));
    return r;
}
__device__ __forceinline__ float2 unpk2(u32 w) {          // .x = lo half, .y = hi half
    __half2 h = *reinterpret_cast<const __half2*>(&w);
    return __half22float2(h);
}
__device__ __forceinline__ float ex2f(float x) {
    float y; asm("ex2.approx.f32 %0, %1;" : "=f"(y) : "f"(x)); return y;
}
__device__ __forceinline__ void mma16(float c[4], const u32 a[4], u32 b0, u32 b1) {
    asm volatile(
        "mma.sync.aligned.m16n8k16.row.col.f32.f16.f16.f32 "
        "{%0,%1,%2,%3},{%4,%5,%6,%7},{%8,%9},{%0,%1,%2,%3};"
        : "+f"(c[0]), "+f"(c[1]), "+f"(c[2]), "+f"(c[3])
        : "r"(a[0]), "r"(a[1]), "r"(a[2]), "r"(a[3]), "r"(b0), "r"(b1));
}
#define LDSM_X4(r0, r1, r2, r3, a) \
    asm volatile("ldmatrix.sync.aligned.m8n8.x4.shared.b16 {%0,%1,%2,%3}, [%4];" \
                 : "=r"(r0), "=r"(r1), "=r"(r2), "=r"(r3) : "r"(a))
#define LDSM_A(fr, a) LDSM_X4(fr[0], fr[1], fr[2], fr[3], a)
#define LDSM_X4T(r0, r1, r2, r3, a) \
    asm volatile("ldmatrix.sync.aligned.m8n8.x4.trans.shared.b16 {%0,%1,%2,%3}, [%4];" \
                 : "=r"(r0), "=r"(r1), "=r"(r2), "=r"(r3) : "r"(a))
#define LDSM_AT(fr, a) LDSM_X4T(fr[0], fr[1], fr[2], fr[3], a)
__device__ __forceinline__ void cp16(u32 dst, const void* src) {
    asm volatile("cp.async.cg.shared.global [%0], [%1], 16;" :: "r"(dst), "l"(src));
}
#define CP_COMMIT() asm volatile("cp.async.commit_group;" ::: "memory")
#define CP_WAIT(n)  asm volatile("cp.async.wait_group %0;" :: "n"(n) : "memory")

// 128-byte-row swizzle (attn tiles)
__device__ __forceinline__ u32 swz(int row, int chunk) {
    return (u32)(row * 128 + (((chunk ^ row) & 7) << 4));
}
// 64-byte-row swizzle (GEMM kb=32 tiles)
__device__ __forceinline__ u32 swz64(int row, int chunk) {
    return (u32)(row * 64 + (((chunk ^ (row >> 1)) & 3) << 4));
}

// ---------------------------------------------------------------------------
// Kernel 0: prep — split X; transpose+split W matrices (fp16 hi/lo).
// ---------------------------------------------------------------------------
#define XWORDS (2097152)
#define WWORDS (131072)
__global__ void __launch_bounds__(256) prep_kernel(
    const float* __restrict__ X,
    const float* __restrict__ Wq, const float* __restrict__ Wk,
    const float* __restrict__ Wv, const float* __restrict__ Wo)
{
    const int w = blockIdx.x * 256 + threadIdx.x;
    if (w < XWORDS) {
        float2 f = ((const float2*)X)[w];
        u32 hi = cvt2(f.y, f.x);
        float2 hf = unpk2(hi);
        g_Xh[w] = hi;
        g_Xl[w] = cvt2(f.y - hf.y, f.x - hf.x);
    } else if (w < XWORDS + WWORDS) {
        int u = w - XWORDS;
        int z = u >> 15, r = u & 32767;
        int n = r >> 7, kp = r & 127;
        const float* Wm = (z == 0) ? Wq : (z == 1) ? Wk : (z == 2) ? Wv : Wo;
        float f0 = Wm[(size_t)(2 * kp)     * 256 + n];
        float f1 = Wm[(size_t)(2 * kp + 1) * 256 + n];
        u32 hi = cvt2(f1, f0);
        float2 hf = unpk2(hi);
        g_Wth[u] = hi;
        g_Wtl[u] = cvt2(f1 - hf.y, f0 - hf.x);
    }
}

// ---------------------------------------------------------------------------
// HMMA GEMM core — kb=32, 8 stages, GBUF 24KB x2, 3 CTAs/SM (R11 form, fp16).
// ---------------------------------------------------------------------------
#define GB_AH 0
#define GB_AL 8192
#define GB_BH 16384
#define GB_BL 20480
#define GBUF  24576
#define GEMM_SMEM (2 * GBUF)

__device__ __forceinline__ void gemm_stage(u32 sb, int bufi, int kb,
                                           const u32* Ah, const u32* Al,
                                           const u32* Bh, const u32* Bl,
                                           int m0, int n0, int tid)
{
    const u32 bufb = sb + bufi * GBUF;
    #pragma unroll
    for (int i = 0; i < 4; i++) {
        int idx = tid + i * 128;
        int r = idx >> 2, c = idx & 3;
        const size_t go = (size_t)(m0 + r) * ROW_WORDS + kb * 16 + c * 4;
        cp16(bufb + GB_AH + swz64(r, c), Ah + go);
        cp16(bufb + GB_AL + swz64(r, c), Al + go);
    }
    #pragma unroll
    for (int i = 0; i < 2; i++) {
        int idx = tid + i * 128;
        int r = idx >> 2, c = idx & 3;
        const size_t go = (size_t)(n0 + r) * ROW_WORDS + kb * 16 + c * 4;
        cp16(bufb + GB_BH + swz64(r, c), Bh + go);
        cp16(bufb + GB_BL + swz64(r, c), Bl + go);
    }
}

__device__ __forceinline__ void gemm_main(u32 sb, float acc[2][8][4],
                                          const u32* Ah, const u32* Al,
                                          const u32* Bh, const u32* Bl,
                                          int m0, int n0, int tid)
{
    const int w  = tid >> 5;
    const int L  = tid & 31;
    const int rt = L & 7;
    const int lb = (L >> 3) & 1;
    const int lc = L >> 4;

    gemm_stage(sb, 0, 0, Ah, Al, Bh, Bl, m0, n0, tid);
    CP_COMMIT();
    gemm_stage(sb, 1, 1, Ah, Al, Bh, Bl, m0, n0, tid);
    CP_COMMIT();

    #pragma unroll 2
    for (int kb = 0; kb < 8; kb++) {
        CP_WAIT(1);
        __syncthreads();
        const u32 bufb = sb + (kb & 1) * GBUF;
        const u32 aAH = bufb + GB_AH, aAL = bufb + GB_AL;
        const u32 aBH = bufb + GB_BH, aBL = bufb + GB_BL;

        #pragma unroll
        for (int j = 0; j < 2; j++) {
            u32 ah[2][4], al[2][4];
            #pragma unroll
            for (int mt = 0; mt < 2; mt++) {
                int row = w * 32 + mt * 16 + rt + lb * 8;
                LDSM_A(ah[mt], aAH + swz64(row, 2 * j + lc));
                LDSM_A(al[mt], aAL + swz64(row, 2 * j + lc));
            }
            #pragma unroll
            for (int p = 0; p < 4; p++) {
                int row = 16 * p + rt + lc * 8;
                int ch  = 2 * j + lb;
                u32 bh0, bh1, bh2, bh3, bl0, bl1, bl2, bl3;
                LDSM_X4(bh0, bh1, bh2, bh3, aBH + swz64(row, ch));
                LDSM_X4(bl0, bl1, bl2, bl3, aBL + swz64(row, ch));
                mma16(acc[0][2*p],   ah[0], bh0, bh1);
                mma16(acc[0][2*p+1], ah[0], bh2, bh3);
                mma16(acc[1][2*p],   ah[1], bh0, bh1);
                mma16(acc[1][2*p+1], ah[1], bh2, bh3);
                mma16(acc[0][2*p],   al[0], bh0, bh1);
                mma16(acc[0][2*p+1], al[0], bh2, bh3);
                mma16(acc[1][2*p],   al[1], bh0, bh1);
                mma16(acc[1][2*p+1], al[1], bh2, bh3);
                mma16(acc[0][2*p],   ah[0], bl0, bl1);
                mma16(acc[0][2*p+1], ah[0], bl2, bl3);
                mma16(acc[1][2*p],   ah[1], bl0, bl1);
                mma16(acc[1][2*p+1], ah[1], bl2, bl3);
            }
        }
        __syncthreads();
        if (kb + 2 < 8)
            gemm_stage(sb, kb & 1, kb + 2, Ah, Al, Bh, Bl, m0, n0, tid);
        CP_COMMIT();
    }
}

// ---------------------------------------------------------------------------
// Kernel 1: QKV projection. grid (MT/128, H, 3), block 128, 3 CTAs/SM.
// V (z==2) stores fp16 hi only.
// ---------------------------------------------------------------------------
__global__ void __launch_bounds__(128, 3) qkv_hmma(
    const float* __restrict__ bq, const float* __restrict__ bk,
    const float* __restrict__ bv)
{
    extern __shared__ char sm[];
    const u32 sb  = smem_u32(sm);
    const int tid = threadIdx.x;
    const int z   = blockIdx.z;
    const int h   = blockIdx.y;
    const int m0  = blockIdx.x * 128;
    const int n0  = h * 64;

    const float* bias = (z == 0) ? bq : (z == 1) ? bk : bv;
    u32* oh = (z == 0) ? g_Qh : (z == 1) ? g_Kh : g_Vh;
    u32* ol = (z == 0) ? g_Ql : g_Kl;   // unused when z==2 (guarded below)
    const float qs = (z == 0) ? (0.125f * LOG2E) : 1.0f;

    float acc[2][8][4];
    #pragma unroll
    for (int mt = 0; mt < 2; mt++)
        #pragma unroll
        for (int t = 0; t < 8; t++)
            #pragma unroll
            for (int e = 0; e < 4; e++) acc[mt][t][e] = 0.0f;

    gemm_main(sb, acc, g_Xh, g_Xl,
              g_Wth + (size_t)z * 256 * ROW_WORDS,
              g_Wtl + (size_t)z * 256 * ROW_WORDS, m0, n0, tid);

    const int w  = tid >> 5;
    const int L  = tid & 31;
    const int lr = L >> 2, lcq = L & 3;
    float b2[8][2];
    #pragma unroll
    for (int t = 0; t < 8; t++) {
        b2[t][0] = bias[n0 + 8 * t + lcq * 2];
        b2[t][1] = bias[n0 + 8 * t + lcq * 2 + 1];
    }
    const int bb = m0 >> 12;
    const int sbase = m0 & (S_ - 1);
    #pragma unroll
    for (int mt = 0; mt < 2; mt++) {
        #pragma unroll
        for (int half = 0; half < 2; half++) {
            int s = sbase + w * 32 + mt * 16 + lr + half * 8;
            size_t rw = ((size_t)(bb * H_ + h) * S_ + s) * 32 + lcq;
            #pragma unroll
            for (int t = 0; t < 8; t++) {
                float v0 = (acc[mt][t][half * 2 + 0] + b2[t][0]) * qs;
                float v1 = (acc[mt][t][half * 2 + 1] + b2[t][1]) * qs;
                u32 hi = cvt2(v1, v0);
                oh[rw + 4 * t] = hi;
                if (z != 2) {
                    float2 hf = unpk2(hi);
                    ol[rw + 4 * t] = cvt2(v1 - hf.y, v0 - hf.x);
                }
            }
        }
    }
}

// ---------------------------------------------------------------------------
// Kernel 3: output projection. grid (MT/128, 4), block 128, 3 CTAs/SM.
// ---------------------------------------------------------------------------
__global__ void __launch_bounds__(128, 3) out_hmma(
    const float* __restrict__ bo, float* __restrict__ out)
{
    extern __shared__ char sm[];
    const u32 sb  = smem_u32(sm);
    const int tid = threadIdx.x;
    const int m0  = blockIdx.x * 128;
    const int n0  = blockIdx.y * 64;

    float acc[2][8][4];
    #pragma unroll
    for (int mt = 0; mt < 2; mt++)
        #pragma unroll
        for (int t = 0; t < 8; t++)
            #pragma unroll
            for (int e = 0; e < 4; e++) acc[mt][t][e] = 0.0f;

    gemm_main(sb, acc, g_Ah, g_Al,
              g_Wth + (size_t)3 * 256 * ROW_WORDS,
              g_Wtl + (size_t)3 * 256 * ROW_WORDS, m0, n0, tid);

    const int w  = tid >> 5;
    const int L  = tid & 31;
    const int lr = L >> 2, lcq = L & 3;
    float b2[8][2];
    #pragma unroll
    for (int t = 0; t < 8; t++) {
        b2[t][0] = bo[n0 + 8 * t + lcq * 2];
        b2[t][1] = bo[n0 + 8 * t + lcq * 2 + 1];
    }
    #pragma unroll
    for (int mt = 0; mt < 2; mt++) {
        #pragma unroll
        for (int half = 0; half < 2; half++) {
            int m = m0 + w * 32 + mt * 16 + lr + half * 8;
            float* orow = out + (size_t)m * D_ + n0 + lcq * 2;
            #pragma unroll
            for (int t = 0; t < 8; t++) {
                float2 v;
                v.x = acc[mt][t][half * 2 + 0] + b2[t][0];
                v.y = acc[mt][t][half * 2 + 1] + b2[t][1];
                *(float2*)&orow[8 * t] = v;
            }
        }
    }
}

// ---------------------------------------------------------------------------
// Kernel 2: flash attention, fp16: S 3-term, PV 1-term. Split-KV x2.
// KV tile: Kh 8K | Kl 8K | Vh 8K = 24KB; double buffered = 48KB.
// grid (S/64, BH*2), block 128, 3 CTAs/SM.
// ---------------------------------------------------------------------------
#define BUF_STRIDE 24576
#define ATTN_SMEM  (2 * 24576)

__global__ void __launch_bounds__(128, 3) attn_kernel()
{
    extern __shared__ char sm[];
    const u32 sb  = smem_u32(sm);
    const int tid = threadIdx.x;
    const int w   = tid >> 5;
    const int L   = tid & 31;
    const int bh   = blockIdx.y >> 1;
    const int half = blockIdx.y & 1;
    const int q0  = blockIdx.x * 64;

    const size_t head = (size_t)bh * S_ * (DH_ / 2);
    const size_t koff = (size_t)half * 2048 * 32;
    const u32* Qh = g_Qh + head;        const u32* Ql = g_Ql + head;
    const u32* Kh = g_Kh + head + koff; const u32* Kl = g_Kl + head + koff;
    const u32* Vh = g_Vh + head + koff;

    const int rt = L & 7;
    const int lb = (L >> 3) & 1;
    const int lc = L >> 4;

    // ---- prologue: stage Q through buf0, extract frags, then start KV ----
    #pragma unroll
    for (int i = 0; i < 4; i++) {
        int idx = tid + i * 128;
        int r = idx >> 3, c = idx & 7;
        cp16(sb + swz(r, c),        Qh + (size_t)(q0 + r) * 32 + c * 4);
        cp16(sb + 8192 + swz(r, c), Ql + (size_t)(q0 + r) * 32 + c * 4);
    }
    CP_COMMIT();
    CP_WAIT(0);
    __syncthreads();

    u32 qh[4][4], ql[4][4];
    #pragma unroll
    for (int j = 0; j < 4; j++) {
        int row = w * 16 + rt + lb * 8;
        LDSM_A(qh[j], sb + swz(row, 2 * j + lc));
        LDSM_A(ql[j], sb + 8192 + swz(row, 2 * j + lc));
    }
    __syncthreads();   // Q fully read before buf0 reuse

    const u32* kvsrc[3] = {Kh, Kl, Vh};
    #pragma unroll
    for (int t0 = 0; t0 < 2; t0++) {
        u32 bufb = sb + t0 * BUF_STRIDE;
        #pragma unroll
        for (int m = 0; m < 3; m++)
            #pragma unroll
            for (int i = 0; i < 4; i++) {
                int idx = tid + i * 128;
                int r = idx >> 3, c = idx & 7;
                cp16(bufb + m * 8192 + swz(r, c),
                     kvsrc[m] + (size_t)(t0 * 64 + r) * 32 + c * 4);
            }
        CP_COMMIT();
    }

    float oacc[8][4];
    #pragma unroll
    for (int t = 0; t < 8; t++)
        #pragma unroll
        for (int e = 0; e < 4; e++) oacc[t][e] = 0.0f;
    float m_lo = -CUDART_INF_F, m_hi = -CUDART_INF_F;
    float l_lo = 0.0f, l_hi = 0.0f;

    const int NT = 2048 / 64;
    for (int it = 0; it < NT; it++) {
        CP_WAIT(1);
        __syncthreads();
        const u32 bufb = sb + (it & 1) * BUF_STRIDE;
        const u32 aKH = bufb, aKL = bufb + 8192, aVH = bufb + 16384;

        // ---- S = Q K^T (3-term fp16), pipelined K-frag loads ----
        float sacc[8][4];
        #pragma unroll
        for (int t = 0; t < 8; t++)
            #pragma unroll
            for (int e = 0; e < 4; e++) sacc[t][e] = 0.0f;

        u32 khf[2][4], klf[2][4];
        LDSM_A(khf[0], aKH + swz(rt + lc * 8, lb));
        LDSM_A(klf[0], aKL + swz(rt + lc * 8, lb));

        #pragma unroll
        for (int g = 0; g < 16; g++) {
            const int j = g >> 2, p = g & 3;
            const int cb = g & 1, nb = cb ^ 1;
            if (g + 1 < 16) {
                const int jn = (g + 1) >> 2, pn = (g + 1) & 3;
                int row = 16 * pn + rt + lc * 8;
                int ch  = 2 * jn + lb;
                LDSM_A(khf[nb], aKH + swz(row, ch));
                LDSM_A(klf[nb], aKL + swz(row, ch));
            }
            mma16(sacc[2*p],   qh[j], khf[cb][0], khf[cb][1]);
            mma16(sacc[2*p+1], qh[j], khf[cb][2], khf[cb][3]);
            mma16(sacc[2*p],   ql[j], khf[cb][0], khf[cb][1]);
            mma16(sacc[2*p+1], ql[j], khf[cb][2], khf[cb][3]);
            mma16(sacc[2*p],   qh[j], klf[cb][0], klf[cb][1]);
            mma16(sacc[2*p+1], qh[j], klf[cb][2], klf[cb][3]);
        }

        // ---- row max (log2 domain) ----
        float mlo = -CUDART_INF_F, mhi = -CUDART_INF_F;
        #pragma unroll
        for (int t = 0; t < 8; t++) {
            mlo = fmaxf(mlo, fmaxf(sacc[t][0], sacc[t][1]));
            mhi = fmaxf(mhi, fmaxf(sacc[t][2], sacc[t][3]));
        }
        mlo = fmaxf(mlo, __shfl_xor_sync(0xffffffffu, mlo, 1));
        mlo = fmaxf(mlo, __shfl_xor_sync(0xffffffffu, mlo, 2));
        mhi = fmaxf(mhi, __shfl_xor_sync(0xffffffffu, mhi, 1));
        mhi = fmaxf(mhi, __shfl_xor_sync(0xffffffffu, mhi, 2));

        float mnlo = fmaxf(m_lo, mlo), mnhi = fmaxf(m_hi, mhi);
        float clo = ex2f(m_lo - mnlo), chi = ex2f(m_hi - mnhi);
        m_lo = mnlo; m_hi = mnhi;

        #pragma unroll
        for (int t = 0; t < 8; t++) {
            oacc[t][0] *= clo; oacc[t][1] *= clo;
            oacc[t][2] *= chi; oacc[t][3] *= chi;
        }

        // ---- PV: 1-term fp16 (P fp16, V fp16), pipelined V-frag loads ----
        float alo = 0.0f, ahi = 0.0f;
        u32 vhf[2][4];
        LDSM_AT(vhf[0], aVH + swz(rt + lb * 8, lc));

        #pragma unroll
        for (int j = 0; j < 4; j++) {
            u32 pa[4];
            #pragma unroll
            for (int tt = 0; tt < 2; tt++) {
                const float* sv = sacc[2 * j + tt];
                float p0 = ex2f(sv[0] - mnlo);
                float p1 = ex2f(sv[1] - mnlo);
                float p2 = ex2f(sv[2] - mnhi);
                float p3 = ex2f(sv[3] - mnhi);
                alo += p0 + p1; ahi += p2 + p3;
                pa[2 * tt]     = cvt2(p1, p0);
                pa[2 * tt + 1] = cvt2(p3, p2);
            }
            #pragma unroll
            for (int t = 0; t < 4; t++) {
                const int g = j * 4 + t;
                const int cb = g & 1, nb = cb ^ 1;
                if (g + 1 < 16) {
                    const int jn = (g + 1) >> 2, tn = (g + 1) & 3;
                    int row = 16 * jn + rt + lb * 8;
                    int ch  = 2 * tn + lc;
                    LDSM_AT(vhf[nb], aVH + swz(row, ch));
                }
                mma16(oacc[2*t],   pa, vhf[cb][0], vhf[cb][1]);
                mma16(oacc[2*t+1], pa, vhf[cb][2], vhf[cb][3]);
            }
        }
        l_lo = l_lo * clo + alo;
        l_hi = l_hi * chi + ahi;

        __syncthreads();
        if (it + 2 < NT) {
            u32 bb2 = sb + (it & 1) * BUF_STRIDE;
            int j2 = (it + 2) * 64;
            #pragma unroll
            for (int m = 0; m < 3; m++)
                #pragma unroll
                for (int i = 0; i < 4; i++) {
                    int idx = tid + i * 128;
                    int r = idx >> 3, c = idx & 7;
                    cp16(bb2 + m * 8192 + swz(r, c),
                         kvsrc[m] + (size_t)(j2 + r) * 32 + c * 4);
                }
        }
        CP_COMMIT();
    }

    // ---- epilogue: write UNNORMALIZED fp32 partials + (m,l) per row ----
    float llo = l_lo + __shfl_xor_sync(0xffffffffu, l_lo, 1);
    llo += __shfl_xor_sync(0xffffffffu, llo, 2);
    float lhi = l_hi + __shfl_xor_sync(0xffffffffu, l_hi, 1);
    lhi += __shfl_xor_sync(0xffffffffu, lhi, 2);

    const int rlo = q0 + w * 16 + (L >> 2);
    const size_t pbase = (size_t)(half * 16 + bh) * 4096;
    float* O0 = g_Op + (pbase + rlo)     * 64 + (L & 3) * 2;
    float* O1 = g_Op + (pbase + rlo + 8) * 64 + (L & 3) * 2;
    #pragma unroll
    for (int t = 0; t < 8; t++) {
        *(float2*)&O0[8 * t] = make_float2(oacc[t][0], oacc[t][1]);
        *(float2*)&O1[8 * t] = make_float2(oacc[t][2], oacc[t][3]);
    }
    if ((L & 3) == 0) {
        g_m[pbase + rlo]     = m_lo;  g_l[pbase + rlo]     = llo;
        g_m[pbase + rlo + 8] = m_hi;  g_l[pbase + rlo + 8] = lhi;
    }
}

// ---------------------------------------------------------------------------
// Kernel 2b: combine split-KV halves -> fp16-split attention output.
// ---------------------------------------------------------------------------
__global__ void __launch_bounds__(256) combine_kernel()
{
    const int idx = blockIdx.x * 256 + threadIdx.x;
    const int bh  = idx >> 15;
    const int rem = idx & 32767;
    const int row = rem >> 3;
    const int q   = rem & 7;

    const int b0 = bh * 4096 + row;
    const int b1 = (16 + bh) * 4096 + row;
    const float m1 = g_m[b0], l1 = g_l[b0];
    const float m2 = g_m[b1], l2 = g_l[b1];
    const float ms = fmaxf(m1, m2);
    const float c1 = ex2f(m1 - ms), c2 = ex2f(m2 - ms);
    const float inv = 1.0f / (c1 * l1 + c2 * l2);
    const float s1 = c1 * inv, s2 = c2 * inv;

    const float4* p1 = (const float4*)(g_Op + (size_t)b0 * 64 + q * 8);
    const float4* p2 = (const float4*)(g_Op + (size_t)b1 * 64 + q * 8);
    float4 a0 = p1[0], a1 = p1[1];
    float4 d0 = p2[0], d1 = p2[1];
    float v[8];
    v[0] = s1 * a0.x + s2 * d0.x;  v[1] = s1 * a0.y + s2 * d0.y;
    v[2] = s1 * a0.z + s2 * d0.z;  v[3] = s1 * a0.w + s2 * d0.w;
    v[4] = s1 * a1.x + s2 * d1.x;  v[5] = s1 * a1.y + s2 * d1.y;
    v[6] = s1 * a1.z + s2 * d1.z;  v[7] = s1 * a1.w + s2 * d1.w;

    uint4 oh, ol;
    u32* ohp = (u32*)&oh; u32* olp = (u32*)&ol;
    #pragma unroll
    for (int i = 0; i < 4; i++) {
        u32 h = cvt2(v[2 * i + 1], v[2 * i]);
        float2 hf = unpk2(h);
        ohp[i] = h;
        olp[i] = cvt2(v[2 * i + 1] - hf.y, v[2 * i] - hf.x);
    }
    const size_t rw = ((size_t)((bh >> 2) * S_) + row) * ROW_WORDS
                      + (bh & 3) * 32 + q * 4;
    *(uint4*)(g_Ah + rw) = oh;
    *(uint4*)(g_Al + rw) = ol;
}

// ---------------------------------------------------------------------------
// Launch
// ---------------------------------------------------------------------------
extern "C" void kernel_launch(void* const* d_in, const int* in_sizes, int n_in,
                              void* d_out, int out_size)
{
    const float* X  = (const float*)d_in[0];
    const float* Wq = (const float*)d_in[1];
    const float* bq = (const float*)d_in[2];
    const float* Wk = (const float*)d_in[3];
    const float* bk = (const float*)d_in[4];
    const float* Wv = (const float*)d_in[5];
    const float* bv = (const float*)d_in[6];
    const float* Wo = (const float*)d_in[7];
    const float* bo = (const float*)d_in[8];
    float* out = (float*)d_out;

    cudaFuncSetAttribute(attn_kernel,
                         cudaFuncAttributeMaxDynamicSharedMemorySize, ATTN_SMEM);
    cudaFuncSetAttribute(qkv_hmma,
                         cudaFuncAttributeMaxDynamicSharedMemorySize, GEMM_SMEM);
    cudaFuncSetAttribute(out_hmma,
                         cudaFuncAttributeMaxDynamicSharedMemorySize, GEMM_SMEM);

    prep_kernel<<<(XWORDS + WWORDS + 255) / 256, 256>>>(X, Wq, Wk, Wv, Wo);
    qkv_hmma<<<dim3(MT_ / 128, H_, 3), 128, GEMM_SMEM>>>(bq, bk, bv);
    attn_kernel<<<dim3(S_ / 64, BH_ * 2), 128, ATTN_SMEM>>>();
    combine_kernel<<<2048, 256>>>();
    out_hmma<<<dim3(MT_ / 128, 4), 128, GEMM_SMEM>>>(bo, out);
}

// round 13
// speedup vs baseline: 1.9323x; 1.2603x over previous
#include <cuda_runtime.h>
#include <cuda_fp16.h>
#include <math_constants.h>

#define B_  4
#define S_  4096
#define D_  256
#define H_  4
#define DH_ 64
#define MT_ (B_ * S_)
#define BH_ (B_ * H_)
#define LOG2E 1.4426950408889634f

typedef unsigned int       u32;
typedef unsigned long long u64;

// ---------------------------------------------------------------------------
// Scratch (fp16; A-operands split hi/lo, B-operands hi only)
// ---------------------------------------------------------------------------
#define QKV_WORDS ((size_t)BH_ * S_ * (DH_ / 2))
#define ROW_WORDS (D_ / 2)
__device__ u32 g_Qh[QKV_WORDS];  __device__ u32 g_Ql[QKV_WORDS];
__device__ u32 g_Kh[QKV_WORDS];                     // K: fp16 only (S 2-term)
__device__ u32 g_Vh[QKV_WORDS];                     // V: fp16 only (PV 1-term)
__device__ u32 g_Xh[(size_t)MT_ * ROW_WORDS];
__device__ u32 g_Xl[(size_t)MT_ * ROW_WORDS];
__device__ u32 g_Ah[(size_t)MT_ * ROW_WORDS];
__device__ u32 g_Al[(size_t)MT_ * ROW_WORDS];
__device__ u32 g_Wth[4 * 256 * ROW_WORDS];          // W: fp16 only (2-term GEMM)
// split-KV partials
__device__ float g_Op[(size_t)2 * 16 * 4096 * 64];
__device__ float g_m[2 * 16 * 4096];
__device__ float g_l[2 * 16 * 4096];

// ---------------------------------------------------------------------------
// PTX helpers (baseline PTX only)
// ---------------------------------------------------------------------------
__device__ __forceinline__ u32 smem_u32(const void* p) {
    u32 a;
    asm("{ .reg .u64 t; cvta.to.shared.u64 t, %1; cvt.u32.u64 %0, t; }"
        : "=r"(a) : "l"(p));
    return a;
}
__device__ __forceinline__ u32 cvt2(float a, float b) {   // {hi16=f16(a), lo16=f16(b)}
    u32 r;
    asm("cvt.rn.f16x2.f32 %0, %1, %2;" : "=r"(r) : "f"(a), "f"(b));
    return r;
}
__device__ __forceinline__ float2 unpk2(u32 w) {
    __half2 h = *reinterpret_cast<const __half2*>(&w);
    return __half22float2(h);
}
__device__ __forceinline__ float ex2f(float x) {
    float y; asm("ex2.approx.f32 %0, %1;" : "=f"(y) : "f"(x)); return y;
}
__device__ __forceinline__ void mma16(float c[4], const u32 a[4], u32 b0, u32 b1) {
    asm volatile(
        "mma.sync.aligned.m16n8k16.row.col.f32.f16.f16.f32 "
        "{%0,%1,%2,%3},{%4,%5,%6,%7},{%8,%9},{%0,%1,%2,%3};"
        : "+f"(c[0]), "+f"(c[1]), "+f"(c[2]), "+f"(c[3])
        : "r"(a[0]), "r"(a[1]), "r"(a[2]), "r"(a[3]), "r"(b0), "r"(b1));
}
#define LDSM_X4(r0, r1, r2, r3, a) \
    asm volatile("ldmatrix.sync.aligned.m8n8.x4.shared.b16 {%0,%1,%2,%3}, [%4];" \
                 : "=r"(r0), "=r"(r1), "=r"(r2), "=r"(r3) : "r"(a))
#define LDSM_A(fr, a) LDSM_X4(fr[0], fr[1], fr[2], fr[3], a)
#define LDSM_X4T(r0, r1, r2, r3, a) \
    asm volatile("ldmatrix.sync.aligned.m8n8.x4.trans.shared.b16 {%0,%1,%2,%3}, [%4];" \
                 : "=r"(r0), "=r"(r1), "=r"(r2), "=r"(r3) : "r"(a))
#define LDSM_AT(fr, a) LDSM_X4T(fr[0], fr[1], fr[2], fr[3], a)
__device__ __forceinline__ void cp16(u32 dst, const void* src) {
    asm volatile("cp.async.cg.shared.global [%0], [%1], 16;" :: "r"(dst), "l"(src));
}
#define CP_COMMIT() asm volatile("cp.async.commit_group;" ::: "memory")
#define CP_WAIT(n)  asm volatile("cp.async.wait_group %0;" :: "n"(n) : "memory")

__device__ __forceinline__ u32 swz(int row, int chunk) {
    return (u32)(row * 128 + (((chunk ^ row) & 7) << 4));
}
__device__ __forceinline__ u32 swz64(int row, int chunk) {
    return (u32)(row * 64 + (((chunk ^ (row >> 1)) & 3) << 4));
}

// ---------------------------------------------------------------------------
// Kernel 0: prep — split X (hi/lo); transpose W (hi only).
// ---------------------------------------------------------------------------
#define XWORDS (2097152)
#define WWORDS (131072)
__global__ void __launch_bounds__(256) prep_kernel(
    const float* __restrict__ X,
    const float* __restrict__ Wq, const float* __restrict__ Wk,
    const float* __restrict__ Wv, const float* __restrict__ Wo)
{
    const int w = blockIdx.x * 256 + threadIdx.x;
    if (w < XWORDS) {
        float2 f = ((const float2*)X)[w];
        u32 hi = cvt2(f.y, f.x);
        float2 hf = unpk2(hi);
        g_Xh[w] = hi;
        g_Xl[w] = cvt2(f.y - hf.y, f.x - hf.x);
    } else if (w < XWORDS + WWORDS) {
        int u = w - XWORDS;
        int z = u >> 15, r = u & 32767;
        int n = r >> 7, kp = r & 127;
        const float* Wm = (z == 0) ? Wq : (z == 1) ? Wk : (z == 2) ? Wv : Wo;
        float f0 = Wm[(size_t)(2 * kp)     * 256 + n];
        float f1 = Wm[(size_t)(2 * kp + 1) * 256 + n];
        g_Wth[u] = cvt2(f1, f0);
    }
}

// ---------------------------------------------------------------------------
// HMMA GEMM core — 2-term (A split, B hi only). kb=32, 8 stages.
// GBUF: AH 8K | AL 8K | BH 4K = 20KB x2 = 40KB, 3 CTAs/SM.
// ---------------------------------------------------------------------------
#define GB_AH 0
#define GB_AL 8192
#define GB_BH 16384
#define GBUF  20480
#define GEMM_SMEM (2 * GBUF)

__device__ __forceinline__ void gemm_stage(u32 sb, int bufi, int kb,
                                           const u32* Ah, const u32* Al,
                                           const u32* Bh,
                                           int m0, int n0, int tid)
{
    const u32 bufb = sb + bufi * GBUF;
    #pragma unroll
    for (int i = 0; i < 4; i++) {
        int idx = tid + i * 128;
        int r = idx >> 2, c = idx & 3;
        const size_t go = (size_t)(m0 + r) * ROW_WORDS + kb * 16 + c * 4;
        cp16(bufb + GB_AH + swz64(r, c), Ah + go);
        cp16(bufb + GB_AL + swz64(r, c), Al + go);
    }
    #pragma unroll
    for (int i = 0; i < 2; i++) {
        int idx = tid + i * 128;
        int r = idx >> 2, c = idx & 3;
        const size_t go = (size_t)(n0 + r) * ROW_WORDS + kb * 16 + c * 4;
        cp16(bufb + GB_BH + swz64(r, c), Bh + go);
    }
}

__device__ __forceinline__ void gemm_main(u32 sb, float acc[2][8][4],
                                          const u32* Ah, const u32* Al,
                                          const u32* Bh,
                                          int m0, int n0, int tid)
{
    const int w  = tid >> 5;
    const int L  = tid & 31;
    const int rt = L & 7;
    const int lb = (L >> 3) & 1;
    const int lc = L >> 4;

    gemm_stage(sb, 0, 0, Ah, Al, Bh, m0, n0, tid);
    CP_COMMIT();
    gemm_stage(sb, 1, 1, Ah, Al, Bh, m0, n0, tid);
    CP_COMMIT();

    #pragma unroll 2
    for (int kb = 0; kb < 8; kb++) {
        CP_WAIT(1);
        __syncthreads();
        const u32 bufb = sb + (kb & 1) * GBUF;
        const u32 aAH = bufb + GB_AH, aAL = bufb + GB_AL, aBH = bufb + GB_BH;

        #pragma unroll
        for (int j = 0; j < 2; j++) {
            u32 ah[2][4], al[2][4];
            #pragma unroll
            for (int mt = 0; mt < 2; mt++) {
                int row = w * 32 + mt * 16 + rt + lb * 8;
                LDSM_A(ah[mt], aAH + swz64(row, 2 * j + lc));
                LDSM_A(al[mt], aAL + swz64(row, 2 * j + lc));
            }
            #pragma unroll
            for (int p = 0; p < 4; p++) {
                int row = 16 * p + rt + lc * 8;
                int ch  = 2 * j + lb;
                u32 bh0, bh1, bh2, bh3;
                LDSM_X4(bh0, bh1, bh2, bh3, aBH + swz64(row, ch));
                mma16(acc[0][2*p],   ah[0], bh0, bh1);
                mma16(acc[0][2*p+1], ah[0], bh2, bh3);
                mma16(acc[1][2*p],   ah[1], bh0, bh1);
                mma16(acc[1][2*p+1], ah[1], bh2, bh3);
                mma16(acc[0][2*p],   al[0], bh0, bh1);
                mma16(acc[0][2*p+1], al[0], bh2, bh3);
                mma16(acc[1][2*p],   al[1], bh0, bh1);
                mma16(acc[1][2*p+1], al[1], bh2, bh3);
            }
        }
        __syncthreads();
        if (kb + 2 < 8)
            gemm_stage(sb, kb & 1, kb + 2, Ah, Al, Bh, m0, n0, tid);
        CP_COMMIT();
    }
}

// ---------------------------------------------------------------------------
// Kernel 1: QKV projection. Q stores hi+lo; K,V store hi only.
// grid (MT/128, H, 3), block 128, 3 CTAs/SM.
// ---------------------------------------------------------------------------
__global__ void __launch_bounds__(128, 3) qkv_hmma(
    const float* __restrict__ bq, const float* __restrict__ bk,
    const float* __restrict__ bv)
{
    extern __shared__ char sm[];
    const u32 sb  = smem_u32(sm);
    const int tid = threadIdx.x;
    const int z   = blockIdx.z;
    const int h   = blockIdx.y;
    const int m0  = blockIdx.x * 128;
    const int n0  = h * 64;

    const float* bias = (z == 0) ? bq : (z == 1) ? bk : bv;
    u32* oh = (z == 0) ? g_Qh : (z == 1) ? g_Kh : g_Vh;
    const float qs = (z == 0) ? (0.125f * LOG2E) : 1.0f;

    float acc[2][8][4];
    #pragma unroll
    for (int mt = 0; mt < 2; mt++)
        #pragma unroll
        for (int t = 0; t < 8; t++)
            #pragma unroll
            for (int e = 0; e < 4; e++) acc[mt][t][e] = 0.0f;

    gemm_main(sb, acc, g_Xh, g_Xl,
              g_Wth + (size_t)z * 256 * ROW_WORDS, m0, n0, tid);

    const int w  = tid >> 5;
    const int L  = tid & 31;
    const int lr = L >> 2, lcq = L & 3;
    float b2[8][2];
    #pragma unroll
    for (int t = 0; t < 8; t++) {
        b2[t][0] = bias[n0 + 8 * t + lcq * 2];
        b2[t][1] = bias[n0 + 8 * t + lcq * 2 + 1];
    }
    const int bb = m0 >> 12;
    const int sbase = m0 & (S_ - 1);
    #pragma unroll
    for (int mt = 0; mt < 2; mt++) {
        #pragma unroll
        for (int half = 0; half < 2; half++) {
            int s = sbase + w * 32 + mt * 16 + lr + half * 8;
            size_t rw = ((size_t)(bb * H_ + h) * S_ + s) * 32 + lcq;
            #pragma unroll
            for (int t = 0; t < 8; t++) {
                float v0 = (acc[mt][t][half * 2 + 0] + b2[t][0]) * qs;
                float v1 = (acc[mt][t][half * 2 + 1] + b2[t][1]) * qs;
                u32 hi = cvt2(v1, v0);
                oh[rw + 4 * t] = hi;
                if (z == 0) {
                    float2 hf = unpk2(hi);
                    g_Ql[rw + 4 * t] = cvt2(v1 - hf.y, v0 - hf.x);
                }
            }
        }
    }
}

// ---------------------------------------------------------------------------
// Kernel 3: output projection. grid (MT/128, 4), block 128, 3 CTAs/SM.
// ---------------------------------------------------------------------------
__global__ void __launch_bounds__(128, 3) out_hmma(
    const float* __restrict__ bo, float* __restrict__ out)
{
    extern __shared__ char sm[];
    const u32 sb  = smem_u32(sm);
    const int tid = threadIdx.x;
    const int m0  = blockIdx.x * 128;
    const int n0  = blockIdx.y * 64;

    float acc[2][8][4];
    #pragma unroll
    for (int mt = 0; mt < 2; mt++)
        #pragma unroll
        for (int t = 0; t < 8; t++)
            #pragma unroll
            for (int e = 0; e < 4; e++) acc[mt][t][e] = 0.0f;

    gemm_main(sb, acc, g_Ah, g_Al,
              g_Wth + (size_t)3 * 256 * ROW_WORDS, m0, n0, tid);

    const int w  = tid >> 5;
    const int L  = tid & 31;
    const int lr = L >> 2, lcq = L & 3;
    float b2[8][2];
    #pragma unroll
    for (int t = 0; t < 8; t++) {
        b2[t][0] = bo[n0 + 8 * t + lcq * 2];
        b2[t][1] = bo[n0 + 8 * t + lcq * 2 + 1];
    }
    #pragma unroll
    for (int mt = 0; mt < 2; mt++) {
        #pragma unroll
        for (int half = 0; half < 2; half++) {
            int m = m0 + w * 32 + mt * 16 + lr + half * 8;
            float* orow = out + (size_t)m * D_ + n0 + lcq * 2;
            #pragma unroll
            for (int t = 0; t < 8; t++) {
                float2 v;
                v.x = acc[mt][t][half * 2 + 0] + b2[t][0];
                v.y = acc[mt][t][half * 2 + 1] + b2[t][1];
                *(float2*)&orow[8 * t] = v;
            }
        }
    }
}

// ---------------------------------------------------------------------------
// Kernel 2: flash attention. S 2-term (qh+ql vs kh), PV 1-term. Split-KV x2.
// KV tile: Kh 8K | Vh 8K = 16KB; double buffered = 32KB.
// grid (S/64, BH*2), block 128, 3 CTAs/SM.
// ---------------------------------------------------------------------------
#define BUF_STRIDE 16384
#define ATTN_SMEM  (2 * 16384)

__global__ void __launch_bounds__(128, 3) attn_kernel()
{
    extern __shared__ char sm[];
    const u32 sb  = smem_u32(sm);
    const int tid = threadIdx.x;
    const int w   = tid >> 5;
    const int L   = tid & 31;
    const int bh   = blockIdx.y >> 1;
    const int half = blockIdx.y & 1;
    const int q0  = blockIdx.x * 64;

    const size_t head = (size_t)bh * S_ * (DH_ / 2);
    const size_t koff = (size_t)half * 2048 * 32;
    const u32* Qh = g_Qh + head;        const u32* Ql = g_Ql + head;
    const u32* Kh = g_Kh + head + koff;
    const u32* Vh = g_Vh + head + koff;

    const int rt = L & 7;
    const int lb = (L >> 3) & 1;
    const int lc = L >> 4;

    // ---- prologue: stage Q (hi 8K @ sb, lo 8K @ sb+8192 = buf0) ----
    #pragma unroll
    for (int i = 0; i < 4; i++) {
        int idx = tid + i * 128;
        int r = idx >> 3, c = idx & 7;
        cp16(sb + swz(r, c),        Qh + (size_t)(q0 + r) * 32 + c * 4);
        cp16(sb + 8192 + swz(r, c), Ql + (size_t)(q0 + r) * 32 + c * 4);
    }
    CP_COMMIT();
    CP_WAIT(0);
    __syncthreads();

    u32 qh[4][4], ql[4][4];
    #pragma unroll
    for (int j = 0; j < 4; j++) {
        int row = w * 16 + rt + lb * 8;
        LDSM_A(qh[j], sb + swz(row, 2 * j + lc));
        LDSM_A(ql[j], sb + 8192 + swz(row, 2 * j + lc));
    }
    __syncthreads();   // Q fully read before buf0 reuse

    const u32* kvsrc[2] = {Kh, Vh};
    #pragma unroll
    for (int t0 = 0; t0 < 2; t0++) {
        u32 bufb = sb + t0 * BUF_STRIDE;
        #pragma unroll
        for (int m = 0; m < 2; m++)
            #pragma unroll
            for (int i = 0; i < 4; i++) {
                int idx = tid + i * 128;
                int r = idx >> 3, c = idx & 7;
                cp16(bufb + m * 8192 + swz(r, c),
                     kvsrc[m] + (size_t)(t0 * 64 + r) * 32 + c * 4);
            }
        CP_COMMIT();
    }

    float oacc[8][4];
    #pragma unroll
    for (int t = 0; t < 8; t++)
        #pragma unroll
        for (int e = 0; e < 4; e++) oacc[t][e] = 0.0f;
    float m_lo = -CUDART_INF_F, m_hi = -CUDART_INF_F;
    float l_lo = 0.0f, l_hi = 0.0f;

    const int NT = 2048 / 64;
    for (int it = 0; it < NT; it++) {
        CP_WAIT(1);
        __syncthreads();
        const u32 bufb = sb + (it & 1) * BUF_STRIDE;
        const u32 aKH = bufb, aVH = bufb + 8192;

        // ---- S = Q K^T (2-term), pipelined K-frag loads ----
        float sacc[8][4];
        #pragma unroll
        for (int t = 0; t < 8; t++)
            #pragma unroll
            for (int e = 0; e < 4; e++) sacc[t][e] = 0.0f;

        u32 khf[2][4];
        LDSM_A(khf[0], aKH + swz(rt + lc * 8, lb));

        #pragma unroll
        for (int g = 0; g < 16; g++) {
            const int j = g >> 2, p = g & 3;
            const int cb = g & 1, nb = cb ^ 1;
            if (g + 1 < 16) {
                const int jn = (g + 1) >> 2, pn = (g + 1) & 3;
                int row = 16 * pn + rt + lc * 8;
                int ch  = 2 * jn + lb;
                LDSM_A(khf[nb], aKH + swz(row, ch));
            }
            mma16(sacc[2*p],   qh[j], khf[cb][0], khf[cb][1]);
            mma16(sacc[2*p+1], qh[j], khf[cb][2], khf[cb][3]);
            mma16(sacc[2*p],   ql[j], khf[cb][0], khf[cb][1]);
            mma16(sacc[2*p+1], ql[j], khf[cb][2], khf[cb][3]);
        }

        // ---- row max (log2 domain) ----
        float mlo = -CUDART_INF_F, mhi = -CUDART_INF_F;
        #pragma unroll
        for (int t = 0; t < 8; t++) {
            mlo = fmaxf(mlo, fmaxf(sacc[t][0], sacc[t][1]));
            mhi = fmaxf(mhi, fmaxf(sacc[t][2], sacc[t][3]));
        }
        mlo = fmaxf(mlo, __shfl_xor_sync(0xffffffffu, mlo, 1));
        mlo = fmaxf(mlo, __shfl_xor_sync(0xffffffffu, mlo, 2));
        mhi = fmaxf(mhi, __shfl_xor_sync(0xffffffffu, mhi, 1));
        mhi = fmaxf(mhi, __shfl_xor_sync(0xffffffffu, mhi, 2));

        float mnlo = fmaxf(m_lo, mlo), mnhi = fmaxf(m_hi, mhi);
        float clo = ex2f(m_lo - mnlo), chi = ex2f(m_hi - mnhi);
        m_lo = mnlo; m_hi = mnhi;

        #pragma unroll
        for (int t = 0; t < 8; t++) {
            oacc[t][0] *= clo; oacc[t][1] *= clo;
            oacc[t][2] *= chi; oacc[t][3] *= chi;
        }

        // ---- PV: 1-term fp16, pipelined V-frag loads ----
        float alo = 0.0f, ahi = 0.0f;
        u32 vhf[2][4];
        LDSM_AT(vhf[0], aVH + swz(rt + lb * 8, lc));

        #pragma unroll
        for (int j = 0; j < 4; j++) {
            u32 pa[4];
            #pragma unroll
            for (int tt = 0; tt < 2; tt++) {
                const float* sv = sacc[2 * j + tt];
                float p0 = ex2f(sv[0] - mnlo);
                float p1 = ex2f(sv[1] - mnlo);
                float p2 = ex2f(sv[2] - mnhi);
                float p3 = ex2f(sv[3] - mnhi);
                alo += p0 + p1; ahi += p2 + p3;
                pa[2 * tt]     = cvt2(p1, p0);
                pa[2 * tt + 1] = cvt2(p3, p2);
            }
            #pragma unroll
            for (int t = 0; t < 4; t++) {
                const int g = j * 4 + t;
                const int cb = g & 1, nb = cb ^ 1;
                if (g + 1 < 16) {
                    const int jn = (g + 1) >> 2, tn = (g + 1) & 3;
                    int row = 16 * jn + rt + lb * 8;
                    int ch  = 2 * tn + lc;
                    LDSM_AT(vhf[nb], aVH + swz(row, ch));
                }
                mma16(oacc[2*t],   pa, vhf[cb][0], vhf[cb][1]);
                mma16(oacc[2*t+1], pa, vhf[cb][2], vhf[cb][3]);
            }
        }
        l_lo = l_lo * clo + alo;
        l_hi = l_hi * chi + ahi;

        __syncthreads();
        if (it + 2 < NT) {
            u32 bb2 = sb + (it & 1) * BUF_STRIDE;
            int j2 = (it + 2) * 64;
            #pragma unroll
            for (int m = 0; m < 2; m++)
                #pragma unroll
                for (int i = 0; i < 4; i++) {
                    int idx = tid + i * 128;
                    int r = idx >> 3, c = idx & 7;
                    cp16(bb2 + m * 8192 + swz(r, c),
                         kvsrc[m] + (size_t)(j2 + r) * 32 + c * 4);
                }
        }
        CP_COMMIT();
    }

    // ---- epilogue: write UNNORMALIZED fp32 partials + (m,l) per row ----
    float llo = l_lo + __shfl_xor_sync(0xffffffffu, l_lo, 1);
    llo += __shfl_xor_sync(0xffffffffu, llo, 2);
    float lhi = l_hi + __shfl_xor_sync(0xffffffffu, l_hi, 1);
    lhi += __shfl_xor_sync(0xffffffffu, lhi, 2);

    const int rlo = q0 + w * 16 + (L >> 2);
    const size_t pbase = (size_t)(half * 16 + bh) * 4096;
    float* O0 = g_Op + (pbase + rlo)     * 64 + (L & 3) * 2;
    float* O1 = g_Op + (pbase + rlo + 8) * 64 + (L & 3) * 2;
    #pragma unroll
    for (int t = 0; t < 8; t++) {
        *(float2*)&O0[8 * t] = make_float2(oacc[t][0], oacc[t][1]);
        *(float2*)&O1[8 * t] = make_float2(oacc[t][2], oacc[t][3]);
    }
    if ((L & 3) == 0) {
        g_m[pbase + rlo]     = m_lo;  g_l[pbase + rlo]     = llo;
        g_m[pbase + rlo + 8] = m_hi;  g_l[pbase + rlo + 8] = lhi;
    }
}

// ---------------------------------------------------------------------------
// Kernel 2b: combine split-KV halves -> fp16-split attention output.
// ---------------------------------------------------------------------------
__global__ void __launch_bounds__(256) combine_kernel()
{
    const int idx = blockIdx.x * 256 + threadIdx.x;
    const int bh  = idx >> 15;
    const int rem = idx & 32767;
    const int row = rem >> 3;
    const int q   = rem & 7;

    const int b0 = bh * 4096 + row;
    const int b1 = (16 + bh) * 4096 + row;
    const float m1 = g_m[b0], l1 = g_l[b0];
    const float m2 = g_m[b1], l2 = g_l[b1];
    const float ms = fmaxf(m1, m2);
    const float c1 = ex2f(m1 - ms), c2 = ex2f(m2 - ms);
    const float inv = 1.0f / (c1 * l1 + c2 * l2);
    const float s1 = c1 * inv, s2 = c2 * inv;

    const float4* p1 = (const float4*)(g_Op + (size_t)b0 * 64 + q * 8);
    const float4* p2 = (const float4*)(g_Op + (size_t)b1 * 64 + q * 8);
    float4 a0 = p1[0], a1 = p1[1];
    float4 d0 = p2[0], d1 = p2[1];
    float v[8];
    v[0] = s1 * a0.x + s2 * d0.x;  v[1] = s1 * a0.y + s2 * d0.y;
    v[2] = s1 * a0.z + s2 * d0.z;  v[3] = s1 * a0.w + s2 * d0.w;
    v[4] = s1 * a1.x + s2 * d1.x;  v[5] = s1 * a1.y + s2 * d1.y;
    v[6] = s1 * a1.z + s2 * d1.z;  v[7] = s1 * a1.w + s2 * d1.w;

    uint4 oh, ol;
    u32* ohp = (u32*)&oh; u32* olp = (u32*)&ol;
    #pragma unroll
    for (int i = 0; i < 4; i++) {
        u32 h = cvt2(v[2 * i + 1], v[2 * i]);
        float2 hf = unpk2(h);
        ohp[i] = h;
        olp[i] = cvt2(v[2 * i + 1] - hf.y, v[2 * i] - hf.x);
    }
    const size_t rw = ((size_t)((bh >> 2) * S_) + row) * ROW_WORDS
                      + (bh & 3) * 32 + q * 4;
    *(uint4*)(g_Ah + rw) = oh;
    *(uint4*)(g_Al + rw) = ol;
}

// ---------------------------------------------------------------------------
// Launch
// ---------------------------------------------------------------------------
extern "C" void kernel_launch(void* const* d_in, const int* in_sizes, int n_in,
                              void* d_out, int out_size)
{
    const float* X  = (const float*)d_in[0];
    const float* Wq = (const float*)d_in[1];
    const float* bq = (const float*)d_in[2];
    const float* Wk = (const float*)d_in[3];
    const float* bk = (const float*)d_in[4];
    const float* Wv = (const float*)d_in[5];
    const float* bv = (const float*)d_in[6];
    const float* Wo = (const float*)d_in[7];
    const float* bo = (const float*)d_in[8];
    float* out = (float*)d_out;

    cudaFuncSetAttribute(attn_kernel,
                         cudaFuncAttributeMaxDynamicSharedMemorySize, ATTN_SMEM);
    cudaFuncSetAttribute(qkv_hmma,
                         cudaFuncAttributeMaxDynamicSharedMemorySize, GEMM_SMEM);
    cudaFuncSetAttribute(out_hmma,
                         cudaFuncAttributeMaxDynamicSharedMemorySize, GEMM_SMEM);

    prep_kernel<<<(XWORDS + WWORDS + 255) / 256, 256>>>(X, Wq, Wk, Wv, Wo);
    qkv_hmma<<<dim3(MT_ / 128, H_, 3), 128, GEMM_SMEM>>>(bq, bk, bv);
    attn_kernel<<<dim3(S_ / 64, BH_ * 2), 128, ATTN_SMEM>>>();
    combine_kernel<<<2048, 256>>>();
    out_hmma<<<dim3(MT_ / 128, 4), 128, GEMM_SMEM>>>(bo, out);
}

// round 14
// speedup vs baseline: 1.9637x; 1.0163x over previous
#include <cuda_runtime.h>
#include <cuda_fp16.h>
#include <math_constants.h>

#define B_  4
#define S_  4096
#define D_  256
#define H_  4
#define DH_ 64
#define MT_ (B_ * S_)
#define BH_ (B_ * H_)
#define LOG2E 1.4426950408889634f

typedef unsigned int       u32;
typedef unsigned long long u64;

// ---------------------------------------------------------------------------
// Scratch (fp16; A-operands split hi/lo, B-operands hi only)
// ---------------------------------------------------------------------------
#define QKV_WORDS ((size_t)BH_ * S_ * (DH_ / 2))
#define ROW_WORDS (D_ / 2)
__device__ u32 g_Qh[QKV_WORDS];  __device__ u32 g_Ql[QKV_WORDS];
__device__ u32 g_Kh[QKV_WORDS];
__device__ u32 g_Vh[QKV_WORDS];
__device__ u32 g_Xh[(size_t)MT_ * ROW_WORDS];
__device__ u32 g_Xl[(size_t)MT_ * ROW_WORDS];
__device__ u32 g_Ah[(size_t)MT_ * ROW_WORDS];
__device__ u32 g_Al[(size_t)MT_ * ROW_WORDS];
__device__ u32 g_Wth[4 * 256 * ROW_WORDS];
// split-KV partials
__device__ float g_Op[(size_t)2 * 16 * 4096 * 64];
__device__ float g_m[2 * 16 * 4096];
__device__ float g_l[2 * 16 * 4096];

// ---------------------------------------------------------------------------
// PTX helpers (baseline PTX only)
// ---------------------------------------------------------------------------
__device__ __forceinline__ u32 smem_u32(const void* p) {
    u32 a;
    asm("{ .reg .u64 t; cvta.to.shared.u64 t, %1; cvt.u32.u64 %0, t; }"
        : "=r"(a) : "l"(p));
    return a;
}
__device__ __forceinline__ u32 cvt2(float a, float b) {   // {hi16=f16(a), lo16=f16(b)}
    u32 r;
    asm("cvt.rn.f16x2.f32 %0, %1, %2;" : "=r"(r) : "f"(a), "f"(b));
    return r;
}
__device__ __forceinline__ float2 unpk2(u32 w) {
    __half2 h = *reinterpret_cast<const __half2*>(&w);
    return __half22float2(h);
}
__device__ __forceinline__ float ex2f(float x) {
    float y; asm("ex2.approx.f32 %0, %1;" : "=f"(y) : "f"(x)); return y;
}
__device__ __forceinline__ u32 ex2h2(u32 x) {             // packed fp16x2 exp2
    u32 y; asm("ex2.approx.f16x2 %0, %1;" : "=r"(y) : "r"(x)); return y;
}
__device__ __forceinline__ void mma16(float c[4], const u32 a[4], u32 b0, u32 b1) {
    asm volatile(
        "mma.sync.aligned.m16n8k16.row.col.f32.f16.f16.f32 "
        "{%0,%1,%2,%3},{%4,%5,%6,%7},{%8,%9},{%0,%1,%2,%3};"
        : "+f"(c[0]), "+f"(c[1]), "+f"(c[2]), "+f"(c[3])
        : "r"(a[0]), "r"(a[1]), "r"(a[2]), "r"(a[3]), "r"(b0), "r"(b1));
}
#define LDSM_X4(r0, r1, r2, r3, a) \
    asm volatile("ldmatrix.sync.aligned.m8n8.x4.shared.b16 {%0,%1,%2,%3}, [%4];" \
                 : "=r"(r0), "=r"(r1), "=r"(r2), "=r"(r3) : "r"(a))
#define LDSM_A(fr, a) LDSM_X4(fr[0], fr[1], fr[2], fr[3], a)
#define LDSM_X4T(r0, r1, r2, r3, a) \
    asm volatile("ldmatrix.sync.aligned.m8n8.x4.trans.shared.b16 {%0,%1,%2,%3}, [%4];" \
                 : "=r"(r0), "=r"(r1), "=r"(r2), "=r"(r3) : "r"(a))
#define LDSM_AT(fr, a) LDSM_X4T(fr[0], fr[1], fr[2], fr[3], a)
__device__ __forceinline__ void cp16(u32 dst, const void* src) {
    asm volatile("cp.async.cg.shared.global [%0], [%1], 16;" :: "r"(dst), "l"(src));
}
#define CP_COMMIT() asm volatile("cp.async.commit_group;" ::: "memory")
#define CP_WAIT(n)  asm volatile("cp.async.wait_group %0;" :: "n"(n) : "memory")

__device__ __forceinline__ u32 swz(int row, int chunk) {
    return (u32)(row * 128 + (((chunk ^ row) & 7) << 4));
}
__device__ __forceinline__ u32 swz64(int row, int chunk) {
    return (u32)(row * 64 + (((chunk ^ (row >> 1)) & 3) << 4));
}

// ---------------------------------------------------------------------------
// Kernel 0: prep — split X (hi/lo); transpose W (hi only).
// ---------------------------------------------------------------------------
#define XWORDS (2097152)
#define WWORDS (131072)
__global__ void __launch_bounds__(256) prep_kernel(
    const float* __restrict__ X,
    const float* __restrict__ Wq, const float* __restrict__ Wk,
    const float* __restrict__ Wv, const float* __restrict__ Wo)
{
    const int w = blockIdx.x * 256 + threadIdx.x;
    if (w < XWORDS) {
        float2 f = ((const float2*)X)[w];
        u32 hi = cvt2(f.y, f.x);
        float2 hf = unpk2(hi);
        g_Xh[w] = hi;
        g_Xl[w] = cvt2(f.y - hf.y, f.x - hf.x);
    } else if (w < XWORDS + WWORDS) {
        int u = w - XWORDS;
        int z = u >> 15, r = u & 32767;
        int n = r >> 7, kp = r & 127;
        const float* Wm = (z == 0) ? Wq : (z == 1) ? Wk : (z == 2) ? Wv : Wo;
        float f0 = Wm[(size_t)(2 * kp)     * 256 + n];
        float f1 = Wm[(size_t)(2 * kp + 1) * 256 + n];
        g_Wth[u] = cvt2(f1, f0);
    }
}

// ---------------------------------------------------------------------------
// HMMA GEMM core — 2-term (A split, B hi only). kb=32, 8 stages. (R13 frozen)
// ---------------------------------------------------------------------------
#define GB_AH 0
#define GB_AL 8192
#define GB_BH 16384
#define GBUF  20480
#define GEMM_SMEM (2 * GBUF)

__device__ __forceinline__ void gemm_stage(u32 sb, int bufi, int kb,
                                           const u32* Ah, const u32* Al,
                                           const u32* Bh,
                                           int m0, int n0, int tid)
{
    const u32 bufb = sb + bufi * GBUF;
    #pragma unroll
    for (int i = 0; i < 4; i++) {
        int idx = tid + i * 128;
        int r = idx >> 2, c = idx & 3;
        const size_t go = (size_t)(m0 + r) * ROW_WORDS + kb * 16 + c * 4;
        cp16(bufb + GB_AH + swz64(r, c), Ah + go);
        cp16(bufb + GB_AL + swz64(r, c), Al + go);
    }
    #pragma unroll
    for (int i = 0; i < 2; i++) {
        int idx = tid + i * 128;
        int r = idx >> 2, c = idx & 3;
        const size_t go = (size_t)(n0 + r) * ROW_WORDS + kb * 16 + c * 4;
        cp16(bufb + GB_BH + swz64(r, c), Bh + go);
    }
}

__device__ __forceinline__ void gemm_main(u32 sb, float acc[2][8][4],
                                          const u32* Ah, const u32* Al,
                                          const u32* Bh,
                                          int m0, int n0, int tid)
{
    const int w  = tid >> 5;
    const int L  = tid & 31;
    const int rt = L & 7;
    const int lb = (L >> 3) & 1;
    const int lc = L >> 4;

    gemm_stage(sb, 0, 0, Ah, Al, Bh, m0, n0, tid);
    CP_COMMIT();
    gemm_stage(sb, 1, 1, Ah, Al, Bh, m0, n0, tid);
    CP_COMMIT();

    #pragma unroll 2
    for (int kb = 0; kb < 8; kb++) {
        CP_WAIT(1);
        __syncthreads();
        const u32 bufb = sb + (kb & 1) * GBUF;
        const u32 aAH = bufb + GB_AH, aAL = bufb + GB_AL, aBH = bufb + GB_BH;

        #pragma unroll
        for (int j = 0; j < 2; j++) {
            u32 ah[2][4], al[2][4];
            #pragma unroll
            for (int mt = 0; mt < 2; mt++) {
                int row = w * 32 + mt * 16 + rt + lb * 8;
                LDSM_A(ah[mt], aAH + swz64(row, 2 * j + lc));
                LDSM_A(al[mt], aAL + swz64(row, 2 * j + lc));
            }
            #pragma unroll
            for (int p = 0; p < 4; p++) {
                int row = 16 * p + rt + lc * 8;
                int ch  = 2 * j + lb;
                u32 bh0, bh1, bh2, bh3;
                LDSM_X4(bh0, bh1, bh2, bh3, aBH + swz64(row, ch));
                mma16(acc[0][2*p],   ah[0], bh0, bh1);
                mma16(acc[0][2*p+1], ah[0], bh2, bh3);
                mma16(acc[1][2*p],   ah[1], bh0, bh1);
                mma16(acc[1][2*p+1], ah[1], bh2, bh3);
                mma16(acc[0][2*p],   al[0], bh0, bh1);
                mma16(acc[0][2*p+1], al[0], bh2, bh3);
                mma16(acc[1][2*p],   al[1], bh0, bh1);
                mma16(acc[1][2*p+1], al[1], bh2, bh3);
            }
        }
        __syncthreads();
        if (kb + 2 < 8)
            gemm_stage(sb, kb & 1, kb + 2, Ah, Al, Bh, m0, n0, tid);
        CP_COMMIT();
    }
}

// ---------------------------------------------------------------------------
// Kernel 1: QKV projection (R13 frozen).
// ---------------------------------------------------------------------------
__global__ void __launch_bounds__(128, 3) qkv_hmma(
    const float* __restrict__ bq, const float* __restrict__ bk,
    const float* __restrict__ bv)
{
    extern __shared__ char sm[];
    const u32 sb  = smem_u32(sm);
    const int tid = threadIdx.x;
    const int z   = blockIdx.z;
    const int h   = blockIdx.y;
    const int m0  = blockIdx.x * 128;
    const int n0  = h * 64;

    const float* bias = (z == 0) ? bq : (z == 1) ? bk : bv;
    u32* oh = (z == 0) ? g_Qh : (z == 1) ? g_Kh : g_Vh;
    const float qs = (z == 0) ? (0.125f * LOG2E) : 1.0f;

    float acc[2][8][4];
    #pragma unroll
    for (int mt = 0; mt < 2; mt++)
        #pragma unroll
        for (int t = 0; t < 8; t++)
            #pragma unroll
            for (int e = 0; e < 4; e++) acc[mt][t][e] = 0.0f;

    gemm_main(sb, acc, g_Xh, g_Xl,
              g_Wth + (size_t)z * 256 * ROW_WORDS, m0, n0, tid);

    const int w  = tid >> 5;
    const int L  = tid & 31;
    const int lr = L >> 2, lcq = L & 3;
    float b2[8][2];
    #pragma unroll
    for (int t = 0; t < 8; t++) {
        b2[t][0] = bias[n0 + 8 * t + lcq * 2];
        b2[t][1] = bias[n0 + 8 * t + lcq * 2 + 1];
    }
    const int bb = m0 >> 12;
    const int sbase = m0 & (S_ - 1);
    #pragma unroll
    for (int mt = 0; mt < 2; mt++) {
        #pragma unroll
        for (int half = 0; half < 2; half++) {
            int s = sbase + w * 32 + mt * 16 + lr + half * 8;
            size_t rw = ((size_t)(bb * H_ + h) * S_ + s) * 32 + lcq;
            #pragma unroll
            for (int t = 0; t < 8; t++) {
                float v0 = (acc[mt][t][half * 2 + 0] + b2[t][0]) * qs;
                float v1 = (acc[mt][t][half * 2 + 1] + b2[t][1]) * qs;
                u32 hi = cvt2(v1, v0);
                oh[rw + 4 * t] = hi;
                if (z == 0) {
                    float2 hf = unpk2(hi);
                    g_Ql[rw + 4 * t] = cvt2(v1 - hf.y, v0 - hf.x);
                }
            }
        }
    }
}

// ---------------------------------------------------------------------------
// Kernel 3: output projection (R13 frozen).
// ---------------------------------------------------------------------------
__global__ void __launch_bounds__(128, 3) out_hmma(
    const float* __restrict__ bo, float* __restrict__ out)
{
    extern __shared__ char sm[];
    const u32 sb  = smem_u32(sm);
    const int tid = threadIdx.x;
    const int m0  = blockIdx.x * 128;
    const int n0  = blockIdx.y * 64;

    float acc[2][8][4];
    #pragma unroll
    for (int mt = 0; mt < 2; mt++)
        #pragma unroll
        for (int t = 0; t < 8; t++)
            #pragma unroll
            for (int e = 0; e < 4; e++) acc[mt][t][e] = 0.0f;

    gemm_main(sb, acc, g_Ah, g_Al,
              g_Wth + (size_t)3 * 256 * ROW_WORDS, m0, n0, tid);

    const int w  = tid >> 5;
    const int L  = tid & 31;
    const int lr = L >> 2, lcq = L & 3;
    float b2[8][2];
    #pragma unroll
    for (int t = 0; t < 8; t++) {
        b2[t][0] = bo[n0 + 8 * t + lcq * 2];
        b2[t][1] = bo[n0 + 8 * t + lcq * 2 + 1];
    }
    #pragma unroll
    for (int mt = 0; mt < 2; mt++) {
        #pragma unroll
        for (int half = 0; half < 2; half++) {
            int m = m0 + w * 32 + mt * 16 + lr + half * 8;
            float* orow = out + (size_t)m * D_ + n0 + lcq * 2;
            #pragma unroll
            for (int t = 0; t < 8; t++) {
                float2 v;
                v.x = acc[mt][t][half * 2 + 0] + b2[t][0];
                v.y = acc[mt][t][half * 2 + 1] + b2[t][1];
                *(float2*)&orow[8 * t] = v;
            }
        }
    }
}

// ---------------------------------------------------------------------------
// Kernel 2: flash attention. S 2-term, PV 1-term. Split-KV x2.
// NEW: P via ex2.approx.f16x2; l via ones-column MMA (quantization-consistent).
// grid (S/64, BH*2), block 128, 3 CTAs/SM.
// ---------------------------------------------------------------------------
#define BUF_STRIDE 16384
#define ATTN_SMEM  (2 * 16384)
#define ONES2 0x3C003C00u   // fp16x2 {1.0, 1.0}

__global__ void __launch_bounds__(128, 3) attn_kernel()
{
    extern __shared__ char sm[];
    const u32 sb  = smem_u32(sm);
    const int tid = threadIdx.x;
    const int w   = tid >> 5;
    const int L   = tid & 31;
    const int bh   = blockIdx.y >> 1;
    const int half = blockIdx.y & 1;
    const int q0  = blockIdx.x * 64;

    const size_t head = (size_t)bh * S_ * (DH_ / 2);
    const size_t koff = (size_t)half * 2048 * 32;
    const u32* Qh = g_Qh + head;        const u32* Ql = g_Ql + head;
    const u32* Kh = g_Kh + head + koff;
    const u32* Vh = g_Vh + head + koff;

    const int rt = L & 7;
    const int lb = (L >> 3) & 1;
    const int lc = L >> 4;

    // ---- prologue ----
    #pragma unroll
    for (int i = 0; i < 4; i++) {
        int idx = tid + i * 128;
        int r = idx >> 3, c = idx & 7;
        cp16(sb + swz(r, c),        Qh + (size_t)(q0 + r) * 32 + c * 4);
        cp16(sb + 8192 + swz(r, c), Ql + (size_t)(q0 + r) * 32 + c * 4);
    }
    CP_COMMIT();
    CP_WAIT(0);
    __syncthreads();

    u32 qh[4][4], ql[4][4];
    #pragma unroll
    for (int j = 0; j < 4; j++) {
        int row = w * 16 + rt + lb * 8;
        LDSM_A(qh[j], sb + swz(row, 2 * j + lc));
        LDSM_A(ql[j], sb + 8192 + swz(row, 2 * j + lc));
    }
    __syncthreads();

    const u32* kvsrc[2] = {Kh, Vh};
    #pragma unroll
    for (int t0 = 0; t0 < 2; t0++) {
        u32 bufb = sb + t0 * BUF_STRIDE;
        #pragma unroll
        for (int m = 0; m < 2; m++)
            #pragma unroll
            for (int i = 0; i < 4; i++) {
                int idx = tid + i * 128;
                int r = idx >> 3, c = idx & 7;
                cp16(bufb + m * 8192 + swz(r, c),
                     kvsrc[m] + (size_t)(t0 * 64 + r) * 32 + c * 4);
            }
        CP_COMMIT();
    }

    float oacc[8][4];
    #pragma unroll
    for (int t = 0; t < 8; t++)
        #pragma unroll
        for (int e = 0; e < 4; e++) oacc[t][e] = 0.0f;
    float lacc[4] = {0.0f, 0.0f, 0.0f, 0.0f};   // ones-MMA accumulator: [0]=lo, [2]=hi
    float m_lo = -CUDART_INF_F, m_hi = -CUDART_INF_F;

    const int NT = 2048 / 64;
    for (int it = 0; it < NT; it++) {
        CP_WAIT(1);
        __syncthreads();
        const u32 bufb = sb + (it & 1) * BUF_STRIDE;
        const u32 aKH = bufb, aVH = bufb + 8192;

        // ---- S = Q K^T (2-term), pipelined K-frag loads ----
        float sacc[8][4];
        #pragma unroll
        for (int t = 0; t < 8; t++)
            #pragma unroll
            for (int e = 0; e < 4; e++) sacc[t][e] = 0.0f;

        u32 khf[2][4];
        LDSM_A(khf[0], aKH + swz(rt + lc * 8, lb));

        #pragma unroll
        for (int g = 0; g < 16; g++) {
            const int j = g >> 2, p = g & 3;
            const int cb = g & 1, nb = cb ^ 1;
            if (g + 1 < 16) {
                const int jn = (g + 1) >> 2, pn = (g + 1) & 3;
                int row = 16 * pn + rt + lc * 8;
                int ch  = 2 * jn + lb;
                LDSM_A(khf[nb], aKH + swz(row, ch));
            }
            mma16(sacc[2*p],   qh[j], khf[cb][0], khf[cb][1]);
            mma16(sacc[2*p+1], qh[j], khf[cb][2], khf[cb][3]);
            mma16(sacc[2*p],   ql[j], khf[cb][0], khf[cb][1]);
            mma16(sacc[2*p+1], ql[j], khf[cb][2], khf[cb][3]);
        }

        // ---- row max (log2 domain) ----
        float mlo = -CUDART_INF_F, mhi = -CUDART_INF_F;
        #pragma unroll
        for (int t = 0; t < 8; t++) {
            mlo = fmaxf(mlo, fmaxf(sacc[t][0], sacc[t][1]));
            mhi = fmaxf(mhi, fmaxf(sacc[t][2], sacc[t][3]));
        }
        mlo = fmaxf(mlo, __shfl_xor_sync(0xffffffffu, mlo, 1));
        mlo = fmaxf(mlo, __shfl_xor_sync(0xffffffffu, mlo, 2));
        mhi = fmaxf(mhi, __shfl_xor_sync(0xffffffffu, mhi, 1));
        mhi = fmaxf(mhi, __shfl_xor_sync(0xffffffffu, mhi, 2));

        float mnlo = fmaxf(m_lo, mlo), mnhi = fmaxf(m_hi, mhi);
        float clo = ex2f(m_lo - mnlo), chi = ex2f(m_hi - mnhi);
        m_lo = mnlo; m_hi = mnhi;

        #pragma unroll
        for (int t = 0; t < 8; t++) {
            oacc[t][0] *= clo; oacc[t][1] *= clo;
            oacc[t][2] *= chi; oacc[t][3] *= chi;
        }
        lacc[0] *= clo; lacc[1] *= clo;
        lacc[2] *= chi; lacc[3] *= chi;

        // ---- PV + l: P = ex2.f16x2(s - m); l via ones-column MMA ----
        u32 vhf[2][4];
        LDSM_AT(vhf[0], aVH + swz(rt + lb * 8, lc));

        #pragma unroll
        for (int j = 0; j < 4; j++) {
            u32 pa[4];
            #pragma unroll
            for (int tt = 0; tt < 2; tt++) {
                const float* sv = sacc[2 * j + tt];
                pa[2 * tt]     = ex2h2(cvt2(sv[1] - mnlo, sv[0] - mnlo));
                pa[2 * tt + 1] = ex2h2(cvt2(sv[3] - mnhi, sv[2] - mnhi));
            }
            mma16(lacc, pa, ONES2, ONES2);   // row sums of quantized P
            #pragma unroll
            for (int t = 0; t < 4; t++) {
                const int g = j * 4 + t;
                const int cb = g & 1, nb = cb ^ 1;
                if (g + 1 < 16) {
                    const int jn = (g + 1) >> 2, tn = (g + 1) & 3;
                    int row = 16 * jn + rt + lb * 8;
                    int ch  = 2 * tn + lc;
                    LDSM_AT(vhf[nb], aVH + swz(row, ch));
                }
                mma16(oacc[2*t],   pa, vhf[cb][0], vhf[cb][1]);
                mma16(oacc[2*t+1], pa, vhf[cb][2], vhf[cb][3]);
            }
        }

        __syncthreads();
        if (it + 2 < NT) {
            u32 bb2 = sb + (it & 1) * BUF_STRIDE;
            int j2 = (it + 2) * 64;
            #pragma unroll
            for (int m = 0; m < 2; m++)
                #pragma unroll
                for (int i = 0; i < 4; i++) {
                    int idx = tid + i * 128;
                    int r = idx >> 3, c = idx & 7;
                    cp16(bb2 + m * 8192 + swz(r, c),
                         kvsrc[m] + (size_t)(j2 + r) * 32 + c * 4);
                }
        }
        CP_COMMIT();
    }

    // ---- epilogue: write UNNORMALIZED fp32 partials + (m,l) per row ----
    // lacc[0]/[2] hold row sums (every lane in the quad has the same value
    // only after quad reduction — MMA spreads row sum across the 4 quad lanes'
    // columns identically? No: each lane's lacc[0] is its 2 columns' partial;
    // all 8 columns are identical row sums, so lacc[0]==lacc[1] and each lane
    // already holds the FULL row sum. No cross-lane reduction needed.
    const int rlo = q0 + w * 16 + (L >> 2);
    const size_t pbase = (size_t)(half * 16 + bh) * 4096;
    float* O0 = g_Op + (pbase + rlo)     * 64 + (L & 3) * 2;
    float* O1 = g_Op + (pbase + rlo + 8) * 64 + (L & 3) * 2;
    #pragma unroll
    for (int t = 0; t < 8; t++) {
        *(float2*)&O0[8 * t] = make_float2(oacc[t][0], oacc[t][1]);
        *(float2*)&O1[8 * t] = make_float2(oacc[t][2], oacc[t][3]);
    }
    if ((L & 3) == 0) {
        g_m[pbase + rlo]     = m_lo;  g_l[pbase + rlo]     = lacc[0];
        g_m[pbase + rlo + 8] = m_hi;  g_l[pbase + rlo + 8] = lacc[2];
    }
}

// ---------------------------------------------------------------------------
// Kernel 2b: combine split-KV halves (R13 frozen).
// ---------------------------------------------------------------------------
__global__ void __launch_bounds__(256) combine_kernel()
{
    const int idx = blockIdx.x * 256 + threadIdx.x;
    const int bh  = idx >> 15;
    const int rem = idx & 32767;
    const int row = rem >> 3;
    const int q   = rem & 7;

    const int b0 = bh * 4096 + row;
    const int b1 = (16 + bh) * 4096 + row;
    const float m1 = g_m[b0], l1 = g_l[b0];
    const float m2 = g_m[b1], l2 = g_l[b1];
    const float ms = fmaxf(m1, m2);
    const float c1 = ex2f(m1 - ms), c2 = ex2f(m2 - ms);
    const float inv = 1.0f / (c1 * l1 + c2 * l2);
    const float s1 = c1 * inv, s2 = c2 * inv;

    const float4* p1 = (const float4*)(g_Op + (size_t)b0 * 64 + q * 8);
    const float4* p2 = (const float4*)(g_Op + (size_t)b1 * 64 + q * 8);
    float4 a0 = p1[0], a1 = p1[1];
    float4 d0 = p2[0], d1 = p2[1];
    float v[8];
    v[0] = s1 * a0.x + s2 * d0.x;  v[1] = s1 * a0.y + s2 * d0.y;
    v[2] = s1 * a0.z + s2 * d0.z;  v[3] = s1 * a0.w + s2 * d0.w;
    v[4] = s1 * a1.x + s2 * d1.x;  v[5] = s1 * a1.y + s2 * d1.y;
    v[6] = s1 * a1.z + s2 * d1.z;  v[7] = s1 * a1.w + s2 * d1.w;

    uint4 oh, ol;
    u32* ohp = (u32*)&oh; u32* olp = (u32*)&ol;
    #pragma unroll
    for (int i = 0; i < 4; i++) {
        u32 h = cvt2(v[2 * i + 1], v[2 * i]);
        float2 hf = unpk2(h);
        ohp[i] = h;
        olp[i] = cvt2(v[2 * i + 1] - hf.y, v[2 * i] - hf.x);
    }
    const size_t rw = ((size_t)((bh >> 2) * S_) + row) * ROW_WORDS
                      + (bh & 3) * 32 + q * 4;
    *(uint4*)(g_Ah + rw) = oh;
    *(uint4*)(g_Al + rw) = ol;
}

// ---------------------------------------------------------------------------
// Launch
// ---------------------------------------------------------------------------
extern "C" void kernel_launch(void* const* d_in, const int* in_sizes, int n_in,
                              void* d_out, int out_size)
{
    const float* X  = (const float*)d_in[0];
    const float* Wq = (const float*)d_in[1];
    const float* bq = (const float*)d_in[2];
    const float* Wk = (const float*)d_in[3];
    const float* bk = (const float*)d_in[4];
    const float* Wv = (const float*)d_in[5];
    const float* bv = (const float*)d_in[6];
    const float* Wo = (const float*)d_in[7];
    const float* bo = (const float*)d_in[8];
    float* out = (float*)d_out;

    cudaFuncSetAttribute(attn_kernel,
                         cudaFuncAttributeMaxDynamicSharedMemorySize, ATTN_SMEM);
    cudaFuncSetAttribute(qkv_hmma,
                         cudaFuncAttributeMaxDynamicSharedMemorySize, GEMM_SMEM);
    cudaFuncSetAttribute(out_hmma,
                         cudaFuncAttributeMaxDynamicSharedMemorySize, GEMM_SMEM);

    prep_kernel<<<(XWORDS + WWORDS + 255) / 256, 256>>>(X, Wq, Wk, Wv, Wo);
    qkv_hmma<<<dim3(MT_ / 128, H_, 3), 128, GEMM_SMEM>>>(bq, bk, bv);
    attn_kernel<<<dim3(S_ / 64, BH_ * 2), 128, ATTN_SMEM>>>();
    combine_kernel<<<2048, 256>>>();
    out_hmma<<<dim3(MT_ / 128, 4), 128, GEMM_SMEM>>>(bo, out);
}

// round 15
// speedup vs baseline: 1.9890x; 1.0129x over previous
#include <cuda_runtime.h>
#include <cuda_fp16.h>
#include <math_constants.h>

#define B_  4
#define S_  4096
#define D_  256
#define H_  4
#define DH_ 64
#define MT_ (B_ * S_)
#define BH_ (B_ * H_)
#define LOG2E 1.4426950408889634f

typedef unsigned int       u32;
typedef unsigned long long u64;

// ---------------------------------------------------------------------------
// Scratch (fp16; A-operands split hi/lo, B-operands hi only)
// ---------------------------------------------------------------------------
#define QKV_WORDS ((size_t)BH_ * S_ * (DH_ / 2))
#define ROW_WORDS (D_ / 2)
__device__ u32 g_Qh[QKV_WORDS];  __device__ u32 g_Ql[QKV_WORDS];
__device__ u32 g_Kh[QKV_WORDS];
__device__ u32 g_Vh[QKV_WORDS];
__device__ u32 g_Xh[(size_t)MT_ * ROW_WORDS];
__device__ u32 g_Xl[(size_t)MT_ * ROW_WORDS];
__device__ u32 g_Ah[(size_t)MT_ * ROW_WORDS];
__device__ u32 g_Al[(size_t)MT_ * ROW_WORDS];
__device__ u32 g_Wth[4 * 256 * ROW_WORDS];
// split-KV partials
__device__ float g_Op[(size_t)2 * 16 * 4096 * 64];
__device__ float g_m[2 * 16 * 4096];
__device__ float g_l[2 * 16 * 4096];

// ---------------------------------------------------------------------------
// PTX helpers (baseline PTX only)
// ---------------------------------------------------------------------------
__device__ __forceinline__ u32 smem_u32(const void* p) {
    u32 a;
    asm("{ .reg .u64 t; cvta.to.shared.u64 t, %1; cvt.u32.u64 %0, t; }"
        : "=r"(a) : "l"(p));
    return a;
}
__device__ __forceinline__ u32 cvt2(float a, float b) {   // {hi16=f16(a), lo16=f16(b)}
    u32 r;
    asm("cvt.rn.f16x2.f32 %0, %1, %2;" : "=r"(r) : "f"(a), "f"(b));
    return r;
}
__device__ __forceinline__ float2 unpk2(u32 w) {
    __half2 h = *reinterpret_cast<const __half2*>(&w);
    return __half22float2(h);
}
__device__ __forceinline__ float ex2f(float x) {
    float y; asm("ex2.approx.f32 %0, %1;" : "=f"(y) : "f"(x)); return y;
}
__device__ __forceinline__ u32 ex2h2(u32 x) {
    u32 y; asm("ex2.approx.f16x2 %0, %1;" : "=r"(y) : "r"(x)); return y;
}
__device__ __forceinline__ void mma16(float c[4], const u32 a[4], u32 b0, u32 b1) {
    asm volatile(
        "mma.sync.aligned.m16n8k16.row.col.f32.f16.f16.f32 "
        "{%0,%1,%2,%3},{%4,%5,%6,%7},{%8,%9},{%0,%1,%2,%3};"
        : "+f"(c[0]), "+f"(c[1]), "+f"(c[2]), "+f"(c[3])
        : "r"(a[0]), "r"(a[1]), "r"(a[2]), "r"(a[3]), "r"(b0), "r"(b1));
}
#define LDSM_X4(r0, r1, r2, r3, a) \
    asm volatile("ldmatrix.sync.aligned.m8n8.x4.shared.b16 {%0,%1,%2,%3}, [%4];" \
                 : "=r"(r0), "=r"(r1), "=r"(r2), "=r"(r3) : "r"(a))
#define LDSM_A(fr, a) LDSM_X4(fr[0], fr[1], fr[2], fr[3], a)
#define LDSM_X4T(r0, r1, r2, r3, a) \
    asm volatile("ldmatrix.sync.aligned.m8n8.x4.trans.shared.b16 {%0,%1,%2,%3}, [%4];" \
                 : "=r"(r0), "=r"(r1), "=r"(r2), "=r"(r3) : "r"(a))
#define LDSM_AT(fr, a) LDSM_X4T(fr[0], fr[1], fr[2], fr[3], a)
__device__ __forceinline__ void cp16(u32 dst, const void* src) {
    asm volatile("cp.async.cg.shared.global [%0], [%1], 16;" :: "r"(dst), "l"(src));
}
#define CP_COMMIT() asm volatile("cp.async.commit_group;" ::: "memory")
#define CP_WAIT(n)  asm volatile("cp.async.wait_group %0;" :: "n"(n) : "memory")

__device__ __forceinline__ u32 swz(int row, int chunk) {
    return (u32)(row * 128 + (((chunk ^ row) & 7) << 4));
}
__device__ __forceinline__ u32 swz64(int row, int chunk) {
    return (u32)(row * 64 + (((chunk ^ (row >> 1)) & 3) << 4));
}

// ---------------------------------------------------------------------------
// Kernel 0: prep — split X (hi/lo); transpose W (hi only).
// ---------------------------------------------------------------------------
#define XWORDS (2097152)
#define WWORDS (131072)
__global__ void __launch_bounds__(256) prep_kernel(
    const float* __restrict__ X,
    const float* __restrict__ Wq, const float* __restrict__ Wk,
    const float* __restrict__ Wv, const float* __restrict__ Wo)
{
    const int w = blockIdx.x * 256 + threadIdx.x;
    if (w < XWORDS) {
        float2 f = ((const float2*)X)[w];
        u32 hi = cvt2(f.y, f.x);
        float2 hf = unpk2(hi);
        g_Xh[w] = hi;
        g_Xl[w] = cvt2(f.y - hf.y, f.x - hf.x);
    } else if (w < XWORDS + WWORDS) {
        int u = w - XWORDS;
        int z = u >> 15, r = u & 32767;
        int n = r >> 7, kp = r & 127;
        const float* Wm = (z == 0) ? Wq : (z == 1) ? Wk : (z == 2) ? Wv : Wo;
        float f0 = Wm[(size_t)(2 * kp)     * 256 + n];
        float f1 = Wm[(size_t)(2 * kp + 1) * 256 + n];
        g_Wth[u] = cvt2(f1, f0);
    }
}

// ---------------------------------------------------------------------------
// HMMA GEMM core — 2-term (A split, B hi only). kb=32, 8 stages. (frozen)
// ---------------------------------------------------------------------------
#define GB_AH 0
#define GB_AL 8192
#define GB_BH 16384
#define GBUF  20480
#define GEMM_SMEM (2 * GBUF)

__device__ __forceinline__ void gemm_stage(u32 sb, int bufi, int kb,
                                           const u32* Ah, const u32* Al,
                                           const u32* Bh,
                                           int m0, int n0, int tid)
{
    const u32 bufb = sb + bufi * GBUF;
    #pragma unroll
    for (int i = 0; i < 4; i++) {
        int idx = tid + i * 128;
        int r = idx >> 2, c = idx & 3;
        const size_t go = (size_t)(m0 + r) * ROW_WORDS + kb * 16 + c * 4;
        cp16(bufb + GB_AH + swz64(r, c), Ah + go);
        cp16(bufb + GB_AL + swz64(r, c), Al + go);
    }
    #pragma unroll
    for (int i = 0; i < 2; i++) {
        int idx = tid + i * 128;
        int r = idx >> 2, c = idx & 3;
        const size_t go = (size_t)(n0 + r) * ROW_WORDS + kb * 16 + c * 4;
        cp16(bufb + GB_BH + swz64(r, c), Bh + go);
    }
}

__device__ __forceinline__ void gemm_main(u32 sb, float acc[2][8][4],
                                          const u32* Ah, const u32* Al,
                                          const u32* Bh,
                                          int m0, int n0, int tid)
{
    const int w  = tid >> 5;
    const int L  = tid & 31;
    const int rt = L & 7;
    const int lb = (L >> 3) & 1;
    const int lc = L >> 4;

    gemm_stage(sb, 0, 0, Ah, Al, Bh, m0, n0, tid);
    CP_COMMIT();
    gemm_stage(sb, 1, 1, Ah, Al, Bh, m0, n0, tid);
    CP_COMMIT();

    #pragma unroll 2
    for (int kb = 0; kb < 8; kb++) {
        CP_WAIT(1);
        __syncthreads();
        const u32 bufb = sb + (kb & 1) * GBUF;
        const u32 aAH = bufb + GB_AH, aAL = bufb + GB_AL, aBH = bufb + GB_BH;

        #pragma unroll
        for (int j = 0; j < 2; j++) {
            u32 ah[2][4], al[2][4];
            #pragma unroll
            for (int mt = 0; mt < 2; mt++) {
                int row = w * 32 + mt * 16 + rt + lb * 8;
                LDSM_A(ah[mt], aAH + swz64(row, 2 * j + lc));
                LDSM_A(al[mt], aAL + swz64(row, 2 * j + lc));
            }
            #pragma unroll
            for (int p = 0; p < 4; p++) {
                int row = 16 * p + rt + lc * 8;
                int ch  = 2 * j + lb;
                u32 bh0, bh1, bh2, bh3;
                LDSM_X4(bh0, bh1, bh2, bh3, aBH + swz64(row, ch));
                mma16(acc[0][2*p],   ah[0], bh0, bh1);
                mma16(acc[0][2*p+1], ah[0], bh2, bh3);
                mma16(acc[1][2*p],   ah[1], bh0, bh1);
                mma16(acc[1][2*p+1], ah[1], bh2, bh3);
                mma16(acc[0][2*p],   al[0], bh0, bh1);
                mma16(acc[0][2*p+1], al[0], bh2, bh3);
                mma16(acc[1][2*p],   al[1], bh0, bh1);
                mma16(acc[1][2*p+1], al[1], bh2, bh3);
            }
        }
        __syncthreads();
        if (kb + 2 < 8)
            gemm_stage(sb, kb & 1, kb + 2, Ah, Al, Bh, m0, n0, tid);
        CP_COMMIT();
    }
}

// ---------------------------------------------------------------------------
// Kernel 1: QKV projection (frozen).
// ---------------------------------------------------------------------------
__global__ void __launch_bounds__(128, 3) qkv_hmma(
    const float* __restrict__ bq, const float* __restrict__ bk,
    const float* __restrict__ bv)
{
    extern __shared__ char sm[];
    const u32 sb  = smem_u32(sm);
    const int tid = threadIdx.x;
    const int z   = blockIdx.z;
    const int h   = blockIdx.y;
    const int m0  = blockIdx.x * 128;
    const int n0  = h * 64;

    const float* bias = (z == 0) ? bq : (z == 1) ? bk : bv;
    u32* oh = (z == 0) ? g_Qh : (z == 1) ? g_Kh : g_Vh;
    const float qs = (z == 0) ? (0.125f * LOG2E) : 1.0f;

    float acc[2][8][4];
    #pragma unroll
    for (int mt = 0; mt < 2; mt++)
        #pragma unroll
        for (int t = 0; t < 8; t++)
            #pragma unroll
            for (int e = 0; e < 4; e++) acc[mt][t][e] = 0.0f;

    gemm_main(sb, acc, g_Xh, g_Xl,
              g_Wth + (size_t)z * 256 * ROW_WORDS, m0, n0, tid);

    const int w  = tid >> 5;
    const int L  = tid & 31;
    const int lr = L >> 2, lcq = L & 3;
    float b2[8][2];
    #pragma unroll
    for (int t = 0; t < 8; t++) {
        b2[t][0] = bias[n0 + 8 * t + lcq * 2];
        b2[t][1] = bias[n0 + 8 * t + lcq * 2 + 1];
    }
    const int bb = m0 >> 12;
    const int sbase = m0 & (S_ - 1);
    #pragma unroll
    for (int mt = 0; mt < 2; mt++) {
        #pragma unroll
        for (int half = 0; half < 2; half++) {
            int s = sbase + w * 32 + mt * 16 + lr + half * 8;
            size_t rw = ((size_t)(bb * H_ + h) * S_ + s) * 32 + lcq;
            #pragma unroll
            for (int t = 0; t < 8; t++) {
                float v0 = (acc[mt][t][half * 2 + 0] + b2[t][0]) * qs;
                float v1 = (acc[mt][t][half * 2 + 1] + b2[t][1]) * qs;
                u32 hi = cvt2(v1, v0);
                oh[rw + 4 * t] = hi;
                if (z == 0) {
                    float2 hf = unpk2(hi);
                    g_Ql[rw + 4 * t] = cvt2(v1 - hf.y, v0 - hf.x);
                }
            }
        }
    }
}

// ---------------------------------------------------------------------------
// Kernel 3: output projection (frozen).
// ---------------------------------------------------------------------------
__global__ void __launch_bounds__(128, 3) out_hmma(
    const float* __restrict__ bo, float* __restrict__ out)
{
    extern __shared__ char sm[];
    const u32 sb  = smem_u32(sm);
    const int tid = threadIdx.x;
    const int m0  = blockIdx.x * 128;
    const int n0  = blockIdx.y * 64;

    float acc[2][8][4];
    #pragma unroll
    for (int mt = 0; mt < 2; mt++)
        #pragma unroll
        for (int t = 0; t < 8; t++)
            #pragma unroll
            for (int e = 0; e < 4; e++) acc[mt][t][e] = 0.0f;

    gemm_main(sb, acc, g_Ah, g_Al,
              g_Wth + (size_t)3 * 256 * ROW_WORDS, m0, n0, tid);

    const int w  = tid >> 5;
    const int L  = tid & 31;
    const int lr = L >> 2, lcq = L & 3;
    float b2[8][2];
    #pragma unroll
    for (int t = 0; t < 8; t++) {
        b2[t][0] = bo[n0 + 8 * t + lcq * 2];
        b2[t][1] = bo[n0 + 8 * t + lcq * 2 + 1];
    }
    #pragma unroll
    for (int mt = 0; mt < 2; mt++) {
        #pragma unroll
        for (int half = 0; half < 2; half++) {
            int m = m0 + w * 32 + mt * 16 + lr + half * 8;
            float* orow = out + (size_t)m * D_ + n0 + lcq * 2;
            #pragma unroll
            for (int t = 0; t < 8; t++) {
                float2 v;
                v.x = acc[mt][t][half * 2 + 0] + b2[t][0];
                v.y = acc[mt][t][half * 2 + 1] + b2[t][1];
                *(float2*)&orow[8 * t] = v;
            }
        }
    }
}

// ---------------------------------------------------------------------------
// Kernel 2: flash attention. S 2-term, PV 1-term, split-KV x2.
// NEW: 3-stage KV ring, ONE __syncthreads per iteration, prefetch at loop top.
// Safety: at iter it, prefetch target buf[(it+2)%3] == buf[(it-1)%3]; every
// warp finished iter it-1's reads before passing this iter's barrier.
// grid (S/64, BH*2), block 128, 3 CTAs/SM (48KB smem).
// ---------------------------------------------------------------------------
#define BUF_STRIDE 16384
#define ATTN_SMEM  (3 * 16384)
#define ONES2 0x3C003C00u

__global__ void __launch_bounds__(128, 3) attn_kernel()
{
    extern __shared__ char sm[];
    const u32 sb  = smem_u32(sm);
    const int tid = threadIdx.x;
    const int w   = tid >> 5;
    const int L   = tid & 31;
    const int bh   = blockIdx.y >> 1;
    const int half = blockIdx.y & 1;
    const int q0  = blockIdx.x * 64;

    const size_t head = (size_t)bh * S_ * (DH_ / 2);
    const size_t koff = (size_t)half * 2048 * 32;
    const u32* Qh = g_Qh + head;        const u32* Ql = g_Ql + head;
    const u32* Kh = g_Kh + head + koff;
    const u32* Vh = g_Vh + head + koff;

    const int rt = L & 7;
    const int lb = (L >> 3) & 1;
    const int lc = L >> 4;

    // ---- prologue: stage Q through buf0 ----
    #pragma unroll
    for (int i = 0; i < 4; i++) {
        int idx = tid + i * 128;
        int r = idx >> 3, c = idx & 7;
        cp16(sb + swz(r, c),        Qh + (size_t)(q0 + r) * 32 + c * 4);
        cp16(sb + 8192 + swz(r, c), Ql + (size_t)(q0 + r) * 32 + c * 4);
    }
    CP_COMMIT();
    CP_WAIT(0);
    __syncthreads();

    u32 qh[4][4], ql[4][4];
    #pragma unroll
    for (int j = 0; j < 4; j++) {
        int row = w * 16 + rt + lb * 8;
        LDSM_A(qh[j], sb + swz(row, 2 * j + lc));
        LDSM_A(ql[j], sb + 8192 + swz(row, 2 * j + lc));
    }
    __syncthreads();   // Q fully read before buf0 reuse

    const u32* kvsrc[2] = {Kh, Vh};
    #pragma unroll
    for (int t0 = 0; t0 < 2; t0++) {
        u32 bufb = sb + t0 * BUF_STRIDE;
        #pragma unroll
        for (int m = 0; m < 2; m++)
            #pragma unroll
            for (int i = 0; i < 4; i++) {
                int idx = tid + i * 128;
                int r = idx >> 3, c = idx & 7;
                cp16(bufb + m * 8192 + swz(r, c),
                     kvsrc[m] + (size_t)(t0 * 64 + r) * 32 + c * 4);
            }
        CP_COMMIT();
    }

    float oacc[8][4];
    #pragma unroll
    for (int t = 0; t < 8; t++)
        #pragma unroll
        for (int e = 0; e < 4; e++) oacc[t][e] = 0.0f;
    float lacc[4] = {0.0f, 0.0f, 0.0f, 0.0f};
    float m_lo = -CUDART_INF_F, m_hi = -CUDART_INF_F;

    const int NT = 2048 / 64;
    int rb = 0, wb = 2;   // read-buffer / write-buffer ring indices
    for (int it = 0; it < NT; it++) {
        CP_WAIT(1);
        __syncthreads();   // ONLY barrier this iteration

        // prefetch it+2 into buf[(it+2)%3] (== buffer consumed at it-1)
        if (it + 2 < NT) {
            u32 bb2 = sb + wb * BUF_STRIDE;
            int j2 = (it + 2) * 64;
            #pragma unroll
            for (int m = 0; m < 2; m++)
                #pragma unroll
                for (int i = 0; i < 4; i++) {
                    int idx = tid + i * 128;
                    int r = idx >> 3, c = idx & 7;
                    cp16(bb2 + m * 8192 + swz(r, c),
                         kvsrc[m] + (size_t)(j2 + r) * 32 + c * 4);
                }
        }
        CP_COMMIT();

        const u32 bufb = sb + rb * BUF_STRIDE;
        const u32 aKH = bufb, aVH = bufb + 8192;
        rb = (rb + 1) % 3;
        wb = (wb + 1) % 3;

        // ---- S = Q K^T (2-term), pipelined K-frag loads ----
        float sacc[8][4];
        #pragma unroll
        for (int t = 0; t < 8; t++)
            #pragma unroll
            for (int e = 0; e < 4; e++) sacc[t][e] = 0.0f;

        u32 khf[2][4];
        LDSM_A(khf[0], aKH + swz(rt + lc * 8, lb));

        #pragma unroll
        for (int g = 0; g < 16; g++) {
            const int j = g >> 2, p = g & 3;
            const int cb = g & 1, nb = cb ^ 1;
            if (g + 1 < 16) {
                const int jn = (g + 1) >> 2, pn = (g + 1) & 3;
                int row = 16 * pn + rt + lc * 8;
                int ch  = 2 * jn + lb;
                LDSM_A(khf[nb], aKH + swz(row, ch));
            }
            mma16(sacc[2*p],   qh[j], khf[cb][0], khf[cb][1]);
            mma16(sacc[2*p+1], qh[j], khf[cb][2], khf[cb][3]);
            mma16(sacc[2*p],   ql[j], khf[cb][0], khf[cb][1]);
            mma16(sacc[2*p+1], ql[j], khf[cb][2], khf[cb][3]);
        }

        // ---- row max (log2 domain) ----
        float mlo = -CUDART_INF_F, mhi = -CUDART_INF_F;
        #pragma unroll
        for (int t = 0; t < 8; t++) {
            mlo = fmaxf(mlo, fmaxf(sacc[t][0], sacc[t][1]));
            mhi = fmaxf(mhi, fmaxf(sacc[t][2], sacc[t][3]));
        }
        mlo = fmaxf(mlo, __shfl_xor_sync(0xffffffffu, mlo, 1));
        mlo = fmaxf(mlo, __shfl_xor_sync(0xffffffffu, mlo, 2));
        mhi = fmaxf(mhi, __shfl_xor_sync(0xffffffffu, mhi, 1));
        mhi = fmaxf(mhi, __shfl_xor_sync(0xffffffffu, mhi, 2));

        float mnlo = fmaxf(m_lo, mlo), mnhi = fmaxf(m_hi, mhi);
        float clo = ex2f(m_lo - mnlo), chi = ex2f(m_hi - mnhi);
        m_lo = mnlo; m_hi = mnhi;

        #pragma unroll
        for (int t = 0; t < 8; t++) {
            oacc[t][0] *= clo; oacc[t][1] *= clo;
            oacc[t][2] *= chi; oacc[t][3] *= chi;
        }
        lacc[0] *= clo;
        lacc[2] *= chi;

        // ---- PV + l: P = ex2.f16x2(s - m); l via ones-column MMA ----
        u32 vhf[2][4];
        LDSM_AT(vhf[0], aVH + swz(rt + lb * 8, lc));

        #pragma unroll
        for (int j = 0; j < 4; j++) {
            u32 pa[4];
            #pragma unroll
            for (int tt = 0; tt < 2; tt++) {
                const float* sv = sacc[2 * j + tt];
                pa[2 * tt]     = ex2h2(cvt2(sv[1] - mnlo, sv[0] - mnlo));
                pa[2 * tt + 1] = ex2h2(cvt2(sv[3] - mnhi, sv[2] - mnhi));
            }
            mma16(lacc, pa, ONES2, ONES2);
            #pragma unroll
            for (int t = 0; t < 4; t++) {
                const int g = j * 4 + t;
                const int cb = g & 1, nb = cb ^ 1;
                if (g + 1 < 16) {
                    const int jn = (g + 1) >> 2, tn = (g + 1) & 3;
                    int row = 16 * jn + rt + lb * 8;
                    int ch  = 2 * tn + lc;
                    LDSM_AT(vhf[nb], aVH + swz(row, ch));
                }
                mma16(oacc[2*t],   pa, vhf[cb][0], vhf[cb][1]);
                mma16(oacc[2*t+1], pa, vhf[cb][2], vhf[cb][3]);
            }
        }
        // no trailing barrier: next iteration's barrier provides the hazard fence
    }

    // ---- epilogue: write UNNORMALIZED fp32 partials + (m,l) per row ----
    // lacc columns are all identical row sums -> each lane holds the full sum.
    const int rlo = q0 + w * 16 + (L >> 2);
    const size_t pbase = (size_t)(half * 16 + bh) * 4096;
    float* O0 = g_Op + (pbase + rlo)     * 64 + (L & 3) * 2;
    float* O1 = g_Op + (pbase + rlo + 8) * 64 + (L & 3) * 2;
    #pragma unroll
    for (int t = 0; t < 8; t++) {
        *(float2*)&O0[8 * t] = make_float2(oacc[t][0], oacc[t][1]);
        *(float2*)&O1[8 * t] = make_float2(oacc[t][2], oacc[t][3]);
    }
    if ((L & 3) == 0) {
        g_m[pbase + rlo]     = m_lo;  g_l[pbase + rlo]     = lacc[0];
        g_m[pbase + rlo + 8] = m_hi;  g_l[pbase + rlo + 8] = lacc[2];
    }
}

// ---------------------------------------------------------------------------
// Kernel 2b: combine split-KV halves (frozen).
// ---------------------------------------------------------------------------
__global__ void __launch_bounds__(256) combine_kernel()
{
    const int idx = blockIdx.x * 256 + threadIdx.x;
    const int bh  = idx >> 15;
    const int rem = idx & 32767;
    const int row = rem >> 3;
    const int q   = rem & 7;

    const int b0 = bh * 4096 + row;
    const int b1 = (16 + bh) * 4096 + row;
    const float m1 = g_m[b0], l1 = g_l[b0];
    const float m2 = g_m[b1], l2 = g_l[b1];
    const float ms = fmaxf(m1, m2);
    const float c1 = ex2f(m1 - ms), c2 = ex2f(m2 - ms);
    const float inv = 1.0f / (c1 * l1 + c2 * l2);
    const float s1 = c1 * inv, s2 = c2 * inv;

    const float4* p1 = (const float4*)(g_Op + (size_t)b0 * 64 + q * 8);
    const float4* p2 = (const float4*)(g_Op + (size_t)b1 * 64 + q * 8);
    float4 a0 = p1[0], a1 = p1[1];
    float4 d0 = p2[0], d1 = p2[1];
    float v[8];
    v[0] = s1 * a0.x + s2 * d0.x;  v[1] = s1 * a0.y + s2 * d0.y;
    v[2] = s1 * a0.z + s2 * d0.z;  v[3] = s1 * a0.w + s2 * d0.w;
    v[4] = s1 * a1.x + s2 * d1.x;  v[5] = s1 * a1.y + s2 * d1.y;
    v[6] = s1 * a1.z + s2 * d1.z;  v[7] = s1 * a1.w + s2 * d1.w;

    uint4 oh, ol;
    u32* ohp = (u32*)&oh; u32* olp = (u32*)&ol;
    #pragma unroll
    for (int i = 0; i < 4; i++) {
        u32 h = cvt2(v[2 * i + 1], v[2 * i]);
        float2 hf = unpk2(h);
        ohp[i] = h;
        olp[i] = cvt2(v[2 * i + 1] - hf.y, v[2 * i] - hf.x);
    }
    const size_t rw = ((size_t)((bh >> 2) * S_) + row) * ROW_WORDS
                      + (bh & 3) * 32 + q * 4;
    *(uint4*)(g_Ah + rw) = oh;
    *(uint4*)(g_Al + rw) = ol;
}

// ---------------------------------------------------------------------------
// Launch
// ---------------------------------------------------------------------------
extern "C" void kernel_launch(void* const* d_in, const int* in_sizes, int n_in,
                              void* d_out, int out_size)
{
    const float* X  = (const float*)d_in[0];
    const float* Wq = (const float*)d_in[1];
    const float* bq = (const float*)d_in[2];
    const float* Wk = (const float*)d_in[3];
    const float* bk = (const float*)d_in[4];
    const float* Wv = (const float*)d_in[5];
    const float* bv = (const float*)d_in[6];
    const float* Wo = (const float*)d_in[7];
    const float* bo = (const float*)d_in[8];
    float* out = (float*)d_out;

    cudaFuncSetAttribute(attn_kernel,
                         cudaFuncAttributeMaxDynamicSharedMemorySize, ATTN_SMEM);
    cudaFuncSetAttribute(qkv_hmma,
                         cudaFuncAttributeMaxDynamicSharedMemorySize, GEMM_SMEM);
    cudaFuncSetAttribute(out_hmma,
                         cudaFuncAttributeMaxDynamicSharedMemorySize, GEMM_SMEM);

    prep_kernel<<<(XWORDS + WWORDS + 255) / 256, 256>>>(X, Wq, Wk, Wv, Wo);
    qkv_hmma<<<dim3(MT_ / 128, H_, 3), 128, GEMM_SMEM>>>(bq, bk, bv);
    attn_kernel<<<dim3(S_ / 64, BH_ * 2), 128, ATTN_SMEM>>>();
    combine_kernel<<<2048, 256>>>();
    out_hmma<<<dim3(MT_ / 128, 4), 128, GEMM_SMEM>>>(bo, out);
}

// round 16
// speedup vs baseline: 2.0066x; 1.0089x over previous
#include <cuda_runtime.h>
#include <cuda_fp16.h>
#include <math_constants.h>

#define B_  4
#define S_  4096
#define D_  256
#define H_  4
#define DH_ 64
#define MT_ (B_ * S_)
#define BH_ (B_ * H_)
#define LOG2E 1.4426950408889634f

typedef unsigned int       u32;
typedef unsigned long long u64;

// ---------------------------------------------------------------------------
// Scratch (fp16; A-operands split hi/lo, B-operands hi only)
// ---------------------------------------------------------------------------
#define QKV_WORDS ((size_t)BH_ * S_ * (DH_ / 2))
#define ROW_WORDS (D_ / 2)
__device__ u32 g_Qh[QKV_WORDS];  __device__ u32 g_Ql[QKV_WORDS];
__device__ u32 g_Kh[QKV_WORDS];
__device__ u32 g_Vh[QKV_WORDS];
__device__ u32 g_Xh[(size_t)MT_ * ROW_WORDS];
__device__ u32 g_Xl[(size_t)MT_ * ROW_WORDS];
__device__ u32 g_Ah[(size_t)MT_ * ROW_WORDS];
__device__ u32 g_Al[(size_t)MT_ * ROW_WORDS];
__device__ u32 g_Wth[4 * 256 * ROW_WORDS];
// split-KV partials: fp16x2 packed, [half*16+bh][row][32 words]
__device__ u32  g_Op[(size_t)2 * 16 * 4096 * 32];
__device__ float g_m[2 * 16 * 4096];
__device__ float g_l[2 * 16 * 4096];

// ---------------------------------------------------------------------------
// PTX helpers (baseline PTX only)
// ---------------------------------------------------------------------------
__device__ __forceinline__ u32 smem_u32(const void* p) {
    u32 a;
    asm("{ .reg .u64 t; cvta.to.shared.u64 t, %1; cvt.u32.u64 %0, t; }"
        : "=r"(a) : "l"(p));
    return a;
}
__device__ __forceinline__ u32 cvt2(float a, float b) {   // {hi16=f16(a), lo16=f16(b)}
    u32 r;
    asm("cvt.rn.f16x2.f32 %0, %1, %2;" : "=r"(r) : "f"(a), "f"(b));
    return r;
}
__device__ __forceinline__ float2 unpk2(u32 w) {
    __half2 h = *reinterpret_cast<const __half2*>(&w);
    return __half22float2(h);
}
__device__ __forceinline__ float ex2f(float x) {
    float y; asm("ex2.approx.f32 %0, %1;" : "=f"(y) : "f"(x)); return y;
}
__device__ __forceinline__ u32 ex2h2(u32 x) {
    u32 y; asm("ex2.approx.f16x2 %0, %1;" : "=r"(y) : "r"(x)); return y;
}
__device__ __forceinline__ void mma16(float c[4], const u32 a[4], u32 b0, u32 b1) {
    asm volatile(
        "mma.sync.aligned.m16n8k16.row.col.f32.f16.f16.f32 "
        "{%0,%1,%2,%3},{%4,%5,%6,%7},{%8,%9},{%0,%1,%2,%3};"
        : "+f"(c[0]), "+f"(c[1]), "+f"(c[2]), "+f"(c[3])
        : "r"(a[0]), "r"(a[1]), "r"(a[2]), "r"(a[3]), "r"(b0), "r"(b1));
}
#define LDSM_X4(r0, r1, r2, r3, a) \
    asm volatile("ldmatrix.sync.aligned.m8n8.x4.shared.b16 {%0,%1,%2,%3}, [%4];" \
                 : "=r"(r0), "=r"(r1), "=r"(r2), "=r"(r3) : "r"(a))
#define LDSM_A(fr, a) LDSM_X4(fr[0], fr[1], fr[2], fr[3], a)
#define LDSM_X4T(r0, r1, r2, r3, a) \
    asm volatile("ldmatrix.sync.aligned.m8n8.x4.trans.shared.b16 {%0,%1,%2,%3}, [%4];" \
                 : "=r"(r0), "=r"(r1), "=r"(r2), "=r"(r3) : "r"(a))
#define LDSM_AT(fr, a) LDSM_X4T(fr[0], fr[1], fr[2], fr[3], a)
__device__ __forceinline__ void cp16(u32 dst, const void* src) {
    asm volatile("cp.async.cg.shared.global [%0], [%1], 16;" :: "r"(dst), "l"(src));
}
#define CP_COMMIT() asm volatile("cp.async.commit_group;" ::: "memory")
#define CP_WAIT(n)  asm volatile("cp.async.wait_group %0;" :: "n"(n) : "memory")

__device__ __forceinline__ u32 swz(int row, int chunk) {
    return (u32)(row * 128 + (((chunk ^ row) & 7) << 4));
}
__device__ __forceinline__ u32 swz64(int row, int chunk) {
    return (u32)(row * 64 + (((chunk ^ (row >> 1)) & 3) << 4));
}

// ---------------------------------------------------------------------------
// Kernel 0: prep — split X (hi/lo); transpose W (hi only).
// ---------------------------------------------------------------------------
#define XWORDS (2097152)
#define WWORDS (131072)
__global__ void __launch_bounds__(256) prep_kernel(
    const float* __restrict__ X,
    const float* __restrict__ Wq, const float* __restrict__ Wk,
    const float* __restrict__ Wv, const float* __restrict__ Wo)
{
    const int w = blockIdx.x * 256 + threadIdx.x;
    if (w < XWORDS) {
        float2 f = ((const float2*)X)[w];
        u32 hi = cvt2(f.y, f.x);
        float2 hf = unpk2(hi);
        g_Xh[w] = hi;
        g_Xl[w] = cvt2(f.y - hf.y, f.x - hf.x);
    } else if (w < XWORDS + WWORDS) {
        int u = w - XWORDS;
        int z = u >> 15, r = u & 32767;
        int n = r >> 7, kp = r & 127;
        const float* Wm = (z == 0) ? Wq : (z == 1) ? Wk : (z == 2) ? Wv : Wo;
        float f0 = Wm[(size_t)(2 * kp)     * 256 + n];
        float f1 = Wm[(size_t)(2 * kp + 1) * 256 + n];
        g_Wth[u] = cvt2(f1, f0);
    }
}

// ---------------------------------------------------------------------------
// HMMA GEMM core — 2-term, kb=32, 8 stages. NEW: 3-deep ring, one barrier per
// stage, prefetch at loop top (prefetch target == buffer consumed last stage).
// smem 3 x 20KB = 60KB, 2 CTAs/SM.
// ---------------------------------------------------------------------------
#define GB_AH 0
#define GB_AL 8192
#define GB_BH 16384
#define GBUF  20480
#define GEMM_SMEM (3 * GBUF)

__device__ __forceinline__ void gemm_stage(u32 sb, int bufi, int kb,
                                           const u32* Ah, const u32* Al,
                                           const u32* Bh,
                                           int m0, int n0, int tid)
{
    const u32 bufb = sb + bufi * GBUF;
    #pragma unroll
    for (int i = 0; i < 4; i++) {
        int idx = tid + i * 128;
        int r = idx >> 2, c = idx & 3;
        const size_t go = (size_t)(m0 + r) * ROW_WORDS + kb * 16 + c * 4;
        cp16(bufb + GB_AH + swz64(r, c), Ah + go);
        cp16(bufb + GB_AL + swz64(r, c), Al + go);
    }
    #pragma unroll
    for (int i = 0; i < 2; i++) {
        int idx = tid + i * 128;
        int r = idx >> 2, c = idx & 3;
        const size_t go = (size_t)(n0 + r) * ROW_WORDS + kb * 16 + c * 4;
        cp16(bufb + GB_BH + swz64(r, c), Bh + go);
    }
}

__device__ __forceinline__ void gemm_main(u32 sb, float acc[2][8][4],
                                          const u32* Ah, const u32* Al,
                                          const u32* Bh,
                                          int m0, int n0, int tid)
{
    const int w  = tid >> 5;
    const int L  = tid & 31;
    const int rt = L & 7;
    const int lb = (L >> 3) & 1;
    const int lc = L >> 4;

    gemm_stage(sb, 0, 0, Ah, Al, Bh, m0, n0, tid);
    CP_COMMIT();
    gemm_stage(sb, 1, 1, Ah, Al, Bh, m0, n0, tid);
    CP_COMMIT();

    int rb = 0, wbuf = 2;
    #pragma unroll 2
    for (int kb = 0; kb < 8; kb++) {
        CP_WAIT(1);
        __syncthreads();   // single barrier per stage

        if (kb + 2 < 8)
            gemm_stage(sb, wbuf, kb + 2, Ah, Al, Bh, m0, n0, tid);
        CP_COMMIT();

        const u32 bufb = sb + rb * GBUF;
        const u32 aAH = bufb + GB_AH, aAL = bufb + GB_AL, aBH = bufb + GB_BH;
        rb = (rb == 2) ? 0 : rb + 1;
        wbuf = (wbuf == 2) ? 0 : wbuf + 1;

        #pragma unroll
        for (int j = 0; j < 2; j++) {
            u32 ah[2][4], al[2][4];
            #pragma unroll
            for (int mt = 0; mt < 2; mt++) {
                int row = w * 32 + mt * 16 + rt + lb * 8;
                LDSM_A(ah[mt], aAH + swz64(row, 2 * j + lc));
                LDSM_A(al[mt], aAL + swz64(row, 2 * j + lc));
            }
            #pragma unroll
            for (int p = 0; p < 4; p++) {
                int row = 16 * p + rt + lc * 8;
                int ch  = 2 * j + lb;
                u32 bh0, bh1, bh2, bh3;
                LDSM_X4(bh0, bh1, bh2, bh3, aBH + swz64(row, ch));
                mma16(acc[0][2*p],   ah[0], bh0, bh1);
                mma16(acc[0][2*p+1], ah[0], bh2, bh3);
                mma16(acc[1][2*p],   ah[1], bh0, bh1);
                mma16(acc[1][2*p+1], ah[1], bh2, bh3);
                mma16(acc[0][2*p],   al[0], bh0, bh1);
                mma16(acc[0][2*p+1], al[0], bh2, bh3);
                mma16(acc[1][2*p],   al[1], bh0, bh1);
                mma16(acc[1][2*p+1], al[1], bh2, bh3);
            }
        }
        // no trailing barrier: next stage's barrier fences buffer reuse
    }
}

// ---------------------------------------------------------------------------
// Kernel 1: QKV projection. grid (MT/128, H, 3), block 128, 2 CTAs/SM.
// ---------------------------------------------------------------------------
__global__ void __launch_bounds__(128, 2) qkv_hmma(
    const float* __restrict__ bq, const float* __restrict__ bk,
    const float* __restrict__ bv)
{
    extern __shared__ char sm[];
    const u32 sb  = smem_u32(sm);
    const int tid = threadIdx.x;
    const int z   = blockIdx.z;
    const int h   = blockIdx.y;
    const int m0  = blockIdx.x * 128;
    const int n0  = h * 64;

    const float* bias = (z == 0) ? bq : (z == 1) ? bk : bv;
    u32* oh = (z == 0) ? g_Qh : (z == 1) ? g_Kh : g_Vh;
    const float qs = (z == 0) ? (0.125f * LOG2E) : 1.0f;

    float acc[2][8][4];
    #pragma unroll
    for (int mt = 0; mt < 2; mt++)
        #pragma unroll
        for (int t = 0; t < 8; t++)
            #pragma unroll
            for (int e = 0; e < 4; e++) acc[mt][t][e] = 0.0f;

    gemm_main(sb, acc, g_Xh, g_Xl,
              g_Wth + (size_t)z * 256 * ROW_WORDS, m0, n0, tid);

    const int w  = tid >> 5;
    const int L  = tid & 31;
    const int lr = L >> 2, lcq = L & 3;
    float b2[8][2];
    #pragma unroll
    for (int t = 0; t < 8; t++) {
        b2[t][0] = bias[n0 + 8 * t + lcq * 2];
        b2[t][1] = bias[n0 + 8 * t + lcq * 2 + 1];
    }
    const int bb = m0 >> 12;
    const int sbase = m0 & (S_ - 1);
    #pragma unroll
    for (int mt = 0; mt < 2; mt++) {
        #pragma unroll
        for (int half = 0; half < 2; half++) {
            int s = sbase + w * 32 + mt * 16 + lr + half * 8;
            size_t rw = ((size_t)(bb * H_ + h) * S_ + s) * 32 + lcq;
            #pragma unroll
            for (int t = 0; t < 8; t++) {
                float v0 = (acc[mt][t][half * 2 + 0] + b2[t][0]) * qs;
                float v1 = (acc[mt][t][half * 2 + 1] + b2[t][1]) * qs;
                u32 hi = cvt2(v1, v0);
                oh[rw + 4 * t] = hi;
                if (z == 0) {
                    float2 hf = unpk2(hi);
                    g_Ql[rw + 4 * t] = cvt2(v1 - hf.y, v0 - hf.x);
                }
            }
        }
    }
}

// ---------------------------------------------------------------------------
// Kernel 3: output projection. grid (MT/128, 4), block 128, 2 CTAs/SM.
// ---------------------------------------------------------------------------
__global__ void __launch_bounds__(128, 2) out_hmma(
    const float* __restrict__ bo, float* __restrict__ out)
{
    extern __shared__ char sm[];
    const u32 sb  = smem_u32(sm);
    const int tid = threadIdx.x;
    const int m0  = blockIdx.x * 128;
    const int n0  = blockIdx.y * 64;

    float acc[2][8][4];
    #pragma unroll
    for (int mt = 0; mt < 2; mt++)
        #pragma unroll
        for (int t = 0; t < 8; t++)
            #pragma unroll
            for (int e = 0; e < 4; e++) acc[mt][t][e] = 0.0f;

    gemm_main(sb, acc, g_Ah, g_Al,
              g_Wth + (size_t)3 * 256 * ROW_WORDS, m0, n0, tid);

    const int w  = tid >> 5;
    const int L  = tid & 31;
    const int lr = L >> 2, lcq = L & 3;
    float b2[8][2];
    #pragma unroll
    for (int t = 0; t < 8; t++) {
        b2[t][0] = bo[n0 + 8 * t + lcq * 2];
        b2[t][1] = bo[n0 + 8 * t + lcq * 2 + 1];
    }
    #pragma unroll
    for (int mt = 0; mt < 2; mt++) {
        #pragma unroll
        for (int half = 0; half < 2; half++) {
            int m = m0 + w * 32 + mt * 16 + lr + half * 8;
            float* orow = out + (size_t)m * D_ + n0 + lcq * 2;
            #pragma unroll
            for (int t = 0; t < 8; t++) {
                float2 v;
                v.x = acc[mt][t][half * 2 + 0] + b2[t][0];
                v.y = acc[mt][t][half * 2 + 1] + b2[t][1];
                *(float2*)&orow[8 * t] = v;
            }
        }
    }
}

// ---------------------------------------------------------------------------
// Kernel 2: flash attention (R15 core). NEW: fp16x2 packed partials.
// grid (S/64, BH*2), block 128, 3 CTAs/SM.
// ---------------------------------------------------------------------------
#define BUF_STRIDE 16384
#define ATTN_SMEM  (3 * 16384)
#define ONES2 0x3C003C00u

__global__ void __launch_bounds__(128, 3) attn_kernel()
{
    extern __shared__ char sm[];
    const u32 sb  = smem_u32(sm);
    const int tid = threadIdx.x;
    const int w   = tid >> 5;
    const int L   = tid & 31;
    const int bh   = blockIdx.y >> 1;
    const int half = blockIdx.y & 1;
    const int q0  = blockIdx.x * 64;

    const size_t head = (size_t)bh * S_ * (DH_ / 2);
    const size_t koff = (size_t)half * 2048 * 32;
    const u32* Qh = g_Qh + head;        const u32* Ql = g_Ql + head;
    const u32* Kh = g_Kh + head + koff;
    const u32* Vh = g_Vh + head + koff;

    const int rt = L & 7;
    const int lb = (L >> 3) & 1;
    const int lc = L >> 4;

    // ---- prologue: stage Q through buf0 ----
    #pragma unroll
    for (int i = 0; i < 4; i++) {
        int idx = tid + i * 128;
        int r = idx >> 3, c = idx & 7;
        cp16(sb + swz(r, c),        Qh + (size_t)(q0 + r) * 32 + c * 4);
        cp16(sb + 8192 + swz(r, c), Ql + (size_t)(q0 + r) * 32 + c * 4);
    }
    CP_COMMIT();
    CP_WAIT(0);
    __syncthreads();

    u32 qh[4][4], ql[4][4];
    #pragma unroll
    for (int j = 0; j < 4; j++) {
        int row = w * 16 + rt + lb * 8;
        LDSM_A(qh[j], sb + swz(row, 2 * j + lc));
        LDSM_A(ql[j], sb + 8192 + swz(row, 2 * j + lc));
    }
    __syncthreads();

    const u32* kvsrc[2] = {Kh, Vh};
    #pragma unroll
    for (int t0 = 0; t0 < 2; t0++) {
        u32 bufb = sb + t0 * BUF_STRIDE;
        #pragma unroll
        for (int m = 0; m < 2; m++)
            #pragma unroll
            for (int i = 0; i < 4; i++) {
                int idx = tid + i * 128;
                int r = idx >> 3, c = idx & 7;
                cp16(bufb + m * 8192 + swz(r, c),
                     kvsrc[m] + (size_t)(t0 * 64 + r) * 32 + c * 4);
            }
        CP_COMMIT();
    }

    float oacc[8][4];
    #pragma unroll
    for (int t = 0; t < 8; t++)
        #pragma unroll
        for (int e = 0; e < 4; e++) oacc[t][e] = 0.0f;
    float lacc[4] = {0.0f, 0.0f, 0.0f, 0.0f};
    float m_lo = -CUDART_INF_F, m_hi = -CUDART_INF_F;

    const int NT = 2048 / 64;
    int rb = 0, wbuf = 2;
    for (int it = 0; it < NT; it++) {
        CP_WAIT(1);
        __syncthreads();

        if (it + 2 < NT) {
            u32 bb2 = sb + wbuf * BUF_STRIDE;
            int j2 = (it + 2) * 64;
            #pragma unroll
            for (int m = 0; m < 2; m++)
                #pragma unroll
                for (int i = 0; i < 4; i++) {
                    int idx = tid + i * 128;
                    int r = idx >> 3, c = idx & 7;
                    cp16(bb2 + m * 8192 + swz(r, c),
                         kvsrc[m] + (size_t)(j2 + r) * 32 + c * 4);
                }
        }
        CP_COMMIT();

        const u32 bufb = sb + rb * BUF_STRIDE;
        const u32 aKH = bufb, aVH = bufb + 8192;
        rb = (rb == 2) ? 0 : rb + 1;
        wbuf = (wbuf == 2) ? 0 : wbuf + 1;

        // ---- S = Q K^T (2-term), pipelined K-frag loads ----
        float sacc[8][4];
        #pragma unroll
        for (int t = 0; t < 8; t++)
            #pragma unroll
            for (int e = 0; e < 4; e++) sacc[t][e] = 0.0f;

        u32 khf[2][4];
        LDSM_A(khf[0], aKH + swz(rt + lc * 8, lb));

        #pragma unroll
        for (int g = 0; g < 16; g++) {
            const int j = g >> 2, p = g & 3;
            const int cb = g & 1, nb = cb ^ 1;
            if (g + 1 < 16) {
                const int jn = (g + 1) >> 2, pn = (g + 1) & 3;
                int row = 16 * pn + rt + lc * 8;
                int ch  = 2 * jn + lb;
                LDSM_A(khf[nb], aKH + swz(row, ch));
            }
            mma16(sacc[2*p],   qh[j], khf[cb][0], khf[cb][1]);
            mma16(sacc[2*p+1], qh[j], khf[cb][2], khf[cb][3]);
            mma16(sacc[2*p],   ql[j], khf[cb][0], khf[cb][1]);
            mma16(sacc[2*p+1], ql[j], khf[cb][2], khf[cb][3]);
        }

        // ---- row max (log2 domain) ----
        float mlo = -CUDART_INF_F, mhi = -CUDART_INF_F;
        #pragma unroll
        for (int t = 0; t < 8; t++) {
            mlo = fmaxf(mlo, fmaxf(sacc[t][0], sacc[t][1]));
            mhi = fmaxf(mhi, fmaxf(sacc[t][2], sacc[t][3]));
        }
        mlo = fmaxf(mlo, __shfl_xor_sync(0xffffffffu, mlo, 1));
        mlo = fmaxf(mlo, __shfl_xor_sync(0xffffffffu, mlo, 2));
        mhi = fmaxf(mhi, __shfl_xor_sync(0xffffffffu, mhi, 1));
        mhi = fmaxf(mhi, __shfl_xor_sync(0xffffffffu, mhi, 2));

        float mnlo = fmaxf(m_lo, mlo), mnhi = fmaxf(m_hi, mhi);
        float clo = ex2f(m_lo - mnlo), chi = ex2f(m_hi - mnhi);
        m_lo = mnlo; m_hi = mnhi;

        #pragma unroll
        for (int t = 0; t < 8; t++) {
            oacc[t][0] *= clo; oacc[t][1] *= clo;
            oacc[t][2] *= chi; oacc[t][3] *= chi;
        }
        lacc[0] *= clo;
        lacc[2] *= chi;

        // ---- PV + l: P = ex2.f16x2(s - m); l via ones-column MMA ----
        u32 vhf[2][4];
        LDSM_AT(vhf[0], aVH + swz(rt + lb * 8, lc));

        #pragma unroll
        for (int j = 0; j < 4; j++) {
            u32 pa[4];
            #pragma unroll
            for (int tt = 0; tt < 2; tt++) {
                const float* sv = sacc[2 * j + tt];
                pa[2 * tt]     = ex2h2(cvt2(sv[1] - mnlo, sv[0] - mnlo));
                pa[2 * tt + 1] = ex2h2(cvt2(sv[3] - mnhi, sv[2] - mnhi));
            }
            mma16(lacc, pa, ONES2, ONES2);
            #pragma unroll
            for (int t = 0; t < 4; t++) {
                const int g = j * 4 + t;
                const int cb = g & 1, nb = cb ^ 1;
                if (g + 1 < 16) {
                    const int jn = (g + 1) >> 2, tn = (g + 1) & 3;
                    int row = 16 * jn + rt + lb * 8;
                    int ch  = 2 * tn + lc;
                    LDSM_AT(vhf[nb], aVH + swz(row, ch));
                }
                mma16(oacc[2*t],   pa, vhf[cb][0], vhf[cb][1]);
                mma16(oacc[2*t+1], pa, vhf[cb][2], vhf[cb][3]);
            }
        }
    }

    // ---- epilogue: write fp16x2 UNNORMALIZED partials + (m,l) per row ----
    const int rlo = q0 + w * 16 + (L >> 2);
    const size_t pbase = (size_t)(half * 16 + bh) * 4096;
    u32* O0 = g_Op + (pbase + rlo)     * 32 + (L & 3);
    u32* O1 = g_Op + (pbase + rlo + 8) * 32 + (L & 3);
    #pragma unroll
    for (int t = 0; t < 8; t++) {
        O0[4 * t] = cvt2(oacc[t][1], oacc[t][0]);
        O1[4 * t] = cvt2(oacc[t][3], oacc[t][2]);
    }
    if ((L & 3) == 0) {
        g_m[pbase + rlo]     = m_lo;  g_l[pbase + rlo]     = lacc[0];
        g_m[pbase + rlo + 8] = m_hi;  g_l[pbase + rlo + 8] = lacc[2];
    }
}

// ---------------------------------------------------------------------------
// Kernel 2b: combine fp16x2 split-KV halves -> fp16-split attention output.
// One thread per 8 columns (uint4 = 4 packed words per half).
// ---------------------------------------------------------------------------
__global__ void __launch_bounds__(256) combine_kernel()
{
    const int idx = blockIdx.x * 256 + threadIdx.x;   // < 524288
    const int bh  = idx >> 15;
    const int rem = idx & 32767;
    const int row = rem >> 3;
    const int q   = rem & 7;

    const int b0 = bh * 4096 + row;
    const int b1 = (16 + bh) * 4096 + row;
    const float m1 = g_m[b0], l1 = g_l[b0];
    const float m2 = g_m[b1], l2 = g_l[b1];
    const float ms = fmaxf(m1, m2);
    const float c1 = ex2f(m1 - ms), c2 = ex2f(m2 - ms);
    const float inv = 1.0f / (c1 * l1 + c2 * l2);
    const float s1 = c1 * inv, s2 = c2 * inv;

    uint4 w1 = *(const uint4*)(g_Op + (size_t)b0 * 32 + q * 4);
    uint4 w2 = *(const uint4*)(g_Op + (size_t)b1 * 32 + q * 4);
    const u32* w1p = (const u32*)&w1;
    const u32* w2p = (const u32*)&w2;

    uint4 oh, ol;
    u32* ohp = (u32*)&oh; u32* olp = (u32*)&ol;
    #pragma unroll
    for (int i = 0; i < 4; i++) {
        float2 a = unpk2(w1p[i]);
        float2 d = unpk2(w2p[i]);
        float v0 = s1 * a.x + s2 * d.x;
        float v1 = s1 * a.y + s2 * d.y;
        u32 h = cvt2(v1, v0);
        float2 hf = unpk2(h);
        ohp[i] = h;
        olp[i] = cvt2(v1 - hf.y, v0 - hf.x);
    }
    const size_t rw = ((size_t)((bh >> 2) * S_) + row) * ROW_WORDS
                      + (bh & 3) * 32 + q * 4;
    *(uint4*)(g_Ah + rw) = oh;
    *(uint4*)(g_Al + rw) = ol;
}

// ---------------------------------------------------------------------------
// Launch
// ---------------------------------------------------------------------------
extern "C" void kernel_launch(void* const* d_in, const int* in_sizes, int n_in,
                              void* d_out, int out_size)
{
    const float* X  = (const float*)d_in[0];
    const float* Wq = (const float*)d_in[1];
    const float* bq = (const float*)d_in[2];
    const float* Wk = (const float*)d_in[3];
    const float* bk = (const float*)d_in[4];
    const float* Wv = (const float*)d_in[5];
    const float* bv = (const float*)d_in[6];
    const float* Wo = (const float*)d_in[7];
    const float* bo = (const float*)d_in[8];
    float* out = (float*)d_out;

    cudaFuncSetAttribute(attn_kernel,
                         cudaFuncAttributeMaxDynamicSharedMemorySize, ATTN_SMEM);
    cudaFuncSetAttribute(qkv_hmma,
                         cudaFuncAttributeMaxDynamicSharedMemorySize, GEMM_SMEM);
    cudaFuncSetAttribute(out_hmma,
                         cudaFuncAttributeMaxDynamicSharedMemorySize, GEMM_SMEM);

    prep_kernel<<<(XWORDS + WWORDS + 255) / 256, 256>>>(X, Wq, Wk, Wv, Wo);
    qkv_hmma<<<dim3(MT_ / 128, H_, 3), 128, GEMM_SMEM>>>(bq, bk, bv);
    attn_kernel<<<dim3(S_ / 64, BH_ * 2), 128, ATTN_SMEM>>>();
    combine_kernel<<<2048, 256>>>();
    out_hmma<<<dim3(MT_ / 128, 4), 128, GEMM_SMEM>>>(bo, out);
}

// round 17
// speedup vs baseline: 2.0284x; 1.0108x over previous
#include <cuda_runtime.h>
#include <cuda_fp16.h>
#include <math_constants.h>

#define B_  4
#define S_  4096
#define D_  256
#define H_  4
#define DH_ 64
#define MT_ (B_ * S_)
#define BH_ (B_ * H_)
#define LOG2E 1.4426950408889634f

typedef unsigned int       u32;
typedef unsigned long long u64;

// ---------------------------------------------------------------------------
// Scratch (fp16; A-operands split hi/lo, B-operands hi only)
// ---------------------------------------------------------------------------
#define QKV_WORDS ((size_t)BH_ * S_ * (DH_ / 2))
#define ROW_WORDS (D_ / 2)
__device__ u32 g_Qh[QKV_WORDS];  __device__ u32 g_Ql[QKV_WORDS];
__device__ u32 g_Kh[QKV_WORDS];
__device__ u32 g_Vh[QKV_WORDS];
__device__ u32 g_Xh[(size_t)MT_ * ROW_WORDS];
__device__ u32 g_Xl[(size_t)MT_ * ROW_WORDS];
__device__ u32 g_Ah[(size_t)MT_ * ROW_WORDS];
__device__ u32 g_Al[(size_t)MT_ * ROW_WORDS];
__device__ u32 g_Wth[4 * 256 * ROW_WORDS];
// split-KV partials: fp16x2 packed
__device__ u32  g_Op[(size_t)2 * 16 * 4096 * 32];
__device__ float g_m[2 * 16 * 4096];
__device__ float g_l[2 * 16 * 4096];

// ---------------------------------------------------------------------------
// PTX helpers (baseline PTX only)
// ---------------------------------------------------------------------------
__device__ __forceinline__ u32 smem_u32(const void* p) {
    u32 a;
    asm("{ .reg .u64 t; cvta.to.shared.u64 t, %1; cvt.u32.u64 %0, t; }"
        : "=r"(a) : "l"(p));
    return a;
}
__device__ __forceinline__ u32 cvt2(float a, float b) {   // {hi16=f16(a), lo16=f16(b)}
    u32 r;
    asm("cvt.rn.f16x2.f32 %0, %1, %2;" : "=r"(r) : "f"(a), "f"(b));
    return r;
}
__device__ __forceinline__ float2 unpk2(u32 w) {
    __half2 h = *reinterpret_cast<const __half2*>(&w);
    return __half22float2(h);
}
__device__ __forceinline__ float ex2f(float x) {
    float y; asm("ex2.approx.f32 %0, %1;" : "=f"(y) : "f"(x)); return y;
}
__device__ __forceinline__ u32 ex2h2(u32 x) {
    u32 y; asm("ex2.approx.f16x2 %0, %1;" : "=r"(y) : "r"(x)); return y;
}
__device__ __forceinline__ void mma16(float c[4], const u32 a[4], u32 b0, u32 b1) {
    asm volatile(
        "mma.sync.aligned.m16n8k16.row.col.f32.f16.f16.f32 "
        "{%0,%1,%2,%3},{%4,%5,%6,%7},{%8,%9},{%0,%1,%2,%3};"
        : "+f"(c[0]), "+f"(c[1]), "+f"(c[2]), "+f"(c[3])
        : "r"(a[0]), "r"(a[1]), "r"(a[2]), "r"(a[3]), "r"(b0), "r"(b1));
}
#define LDSM_X4(r0, r1, r2, r3, a) \
    asm volatile("ldmatrix.sync.aligned.m8n8.x4.shared.b16 {%0,%1,%2,%3}, [%4];" \
                 : "=r"(r0), "=r"(r1), "=r"(r2), "=r"(r3) : "r"(a))
#define LDSM_A(fr, a) LDSM_X4(fr[0], fr[1], fr[2], fr[3], a)
#define LDSM_X4T(r0, r1, r2, r3, a) \
    asm volatile("ldmatrix.sync.aligned.m8n8.x4.trans.shared.b16 {%0,%1,%2,%3}, [%4];" \
                 : "=r"(r0), "=r"(r1), "=r"(r2), "=r"(r3) : "r"(a))
#define LDSM_AT(fr, a) LDSM_X4T(fr[0], fr[1], fr[2], fr[3], a)
__device__ __forceinline__ void cp16(u32 dst, const void* src) {
    asm volatile("cp.async.cg.shared.global [%0], [%1], 16;" :: "r"(dst), "l"(src));
}
#define CP_COMMIT() asm volatile("cp.async.commit_group;" ::: "memory")
#define CP_WAIT(n)  asm volatile("cp.async.wait_group %0;" :: "n"(n) : "memory")

__device__ __forceinline__ u32 swz(int row, int chunk) {
    return (u32)(row * 128 + (((chunk ^ row) & 7) << 4));
}
__device__ __forceinline__ u32 swz64(int row, int chunk) {
    return (u32)(row * 64 + (((chunk ^ (row >> 1)) & 3) << 4));
}

// ---------------------------------------------------------------------------
// Kernel 0: prep (frozen).
// ---------------------------------------------------------------------------
#define XWORDS (2097152)
#define WWORDS (131072)
__global__ void __launch_bounds__(256) prep_kernel(
    const float* __restrict__ X,
    const float* __restrict__ Wq, const float* __restrict__ Wk,
    const float* __restrict__ Wv, const float* __restrict__ Wo)
{
    const int w = blockIdx.x * 256 + threadIdx.x;
    if (w < XWORDS) {
        float2 f = ((const float2*)X)[w];
        u32 hi = cvt2(f.y, f.x);
        float2 hf = unpk2(hi);
        g_Xh[w] = hi;
        g_Xl[w] = cvt2(f.y - hf.y, f.x - hf.x);
    } else if (w < XWORDS + WWORDS) {
        int u = w - XWORDS;
        int z = u >> 15, r = u & 32767;
        int n = r >> 7, kp = r & 127;
        const float* Wm = (z == 0) ? Wq : (z == 1) ? Wk : (z == 2) ? Wv : Wo;
        float f0 = Wm[(size_t)(2 * kp)     * 256 + n];
        float f1 = Wm[(size_t)(2 * kp + 1) * 256 + n];
        g_Wth[u] = cvt2(f1, f0);
    }
}

// ---------------------------------------------------------------------------
// HMMA GEMM core (R16 frozen: 2-term, kb=32, 3-deep ring, 1 barrier/stage).
// ---------------------------------------------------------------------------
#define GB_AH 0
#define GB_AL 8192
#define GB_BH 16384
#define GBUF  20480
#define GEMM_SMEM (3 * GBUF)

__device__ __forceinline__ void gemm_stage(u32 sb, int bufi, int kb,
                                           const u32* Ah, const u32* Al,
                                           const u32* Bh,
                                           int m0, int n0, int tid)
{
    const u32 bufb = sb + bufi * GBUF;
    #pragma unroll
    for (int i = 0; i < 4; i++) {
        int idx = tid + i * 128;
        int r = idx >> 2, c = idx & 3;
        const size_t go = (size_t)(m0 + r) * ROW_WORDS + kb * 16 + c * 4;
        cp16(bufb + GB_AH + swz64(r, c), Ah + go);
        cp16(bufb + GB_AL + swz64(r, c), Al + go);
    }
    #pragma unroll
    for (int i = 0; i < 2; i++) {
        int idx = tid + i * 128;
        int r = idx >> 2, c = idx & 3;
        const size_t go = (size_t)(n0 + r) * ROW_WORDS + kb * 16 + c * 4;
        cp16(bufb + GB_BH + swz64(r, c), Bh + go);
    }
}

__device__ __forceinline__ void gemm_main(u32 sb, float acc[2][8][4],
                                          const u32* Ah, const u32* Al,
                                          const u32* Bh,
                                          int m0, int n0, int tid)
{
    const int w  = tid >> 5;
    const int L  = tid & 31;
    const int rt = L & 7;
    const int lb = (L >> 3) & 1;
    const int lc = L >> 4;

    gemm_stage(sb, 0, 0, Ah, Al, Bh, m0, n0, tid);
    CP_COMMIT();
    gemm_stage(sb, 1, 1, Ah, Al, Bh, m0, n0, tid);
    CP_COMMIT();

    int rb = 0, wbuf = 2;
    #pragma unroll 2
    for (int kb = 0; kb < 8; kb++) {
        CP_WAIT(1);
        __syncthreads();

        if (kb + 2 < 8)
            gemm_stage(sb, wbuf, kb + 2, Ah, Al, Bh, m0, n0, tid);
        CP_COMMIT();

        const u32 bufb = sb + rb * GBUF;
        const u32 aAH = bufb + GB_AH, aAL = bufb + GB_AL, aBH = bufb + GB_BH;
        rb = (rb == 2) ? 0 : rb + 1;
        wbuf = (wbuf == 2) ? 0 : wbuf + 1;

        #pragma unroll
        for (int j = 0; j < 2; j++) {
            u32 ah[2][4], al[2][4];
            #pragma unroll
            for (int mt = 0; mt < 2; mt++) {
                int row = w * 32 + mt * 16 + rt + lb * 8;
                LDSM_A(ah[mt], aAH + swz64(row, 2 * j + lc));
                LDSM_A(al[mt], aAL + swz64(row, 2 * j + lc));
            }
            #pragma unroll
            for (int p = 0; p < 4; p++) {
                int row = 16 * p + rt + lc * 8;
                int ch  = 2 * j + lb;
                u32 bh0, bh1, bh2, bh3;
                LDSM_X4(bh0, bh1, bh2, bh3, aBH + swz64(row, ch));
                mma16(acc[0][2*p],   ah[0], bh0, bh1);
                mma16(acc[0][2*p+1], ah[0], bh2, bh3);
                mma16(acc[1][2*p],   ah[1], bh0, bh1);
                mma16(acc[1][2*p+1], ah[1], bh2, bh3);
                mma16(acc[0][2*p],   al[0], bh0, bh1);
                mma16(acc[0][2*p+1], al[0], bh2, bh3);
                mma16(acc[1][2*p],   al[1], bh0, bh1);
                mma16(acc[1][2*p+1], al[1], bh2, bh3);
            }
        }
    }
}

// ---------------------------------------------------------------------------
// Kernel 1: QKV projection (frozen).
// ---------------------------------------------------------------------------
__global__ void __launch_bounds__(128, 2) qkv_hmma(
    const float* __restrict__ bq, const float* __restrict__ bk,
    const float* __restrict__ bv)
{
    extern __shared__ char sm[];
    const u32 sb  = smem_u32(sm);
    const int tid = threadIdx.x;
    const int z   = blockIdx.z;
    const int h   = blockIdx.y;
    const int m0  = blockIdx.x * 128;
    const int n0  = h * 64;

    const float* bias = (z == 0) ? bq : (z == 1) ? bk : bv;
    u32* oh = (z == 0) ? g_Qh : (z == 1) ? g_Kh : g_Vh;
    const float qs = (z == 0) ? (0.125f * LOG2E) : 1.0f;

    float acc[2][8][4];
    #pragma unroll
    for (int mt = 0; mt < 2; mt++)
        #pragma unroll
        for (int t = 0; t < 8; t++)
            #pragma unroll
            for (int e = 0; e < 4; e++) acc[mt][t][e] = 0.0f;

    gemm_main(sb, acc, g_Xh, g_Xl,
              g_Wth + (size_t)z * 256 * ROW_WORDS, m0, n0, tid);

    const int w  = tid >> 5;
    const int L  = tid & 31;
    const int lr = L >> 2, lcq = L & 3;
    float b2[8][2];
    #pragma unroll
    for (int t = 0; t < 8; t++) {
        b2[t][0] = bias[n0 + 8 * t + lcq * 2];
        b2[t][1] = bias[n0 + 8 * t + lcq * 2 + 1];
    }
    const int bb = m0 >> 12;
    const int sbase = m0 & (S_ - 1);
    #pragma unroll
    for (int mt = 0; mt < 2; mt++) {
        #pragma unroll
        for (int half = 0; half < 2; half++) {
            int s = sbase + w * 32 + mt * 16 + lr + half * 8;
            size_t rw = ((size_t)(bb * H_ + h) * S_ + s) * 32 + lcq;
            #pragma unroll
            for (int t = 0; t < 8; t++) {
                float v0 = (acc[mt][t][half * 2 + 0] + b2[t][0]) * qs;
                float v1 = (acc[mt][t][half * 2 + 1] + b2[t][1]) * qs;
                u32 hi = cvt2(v1, v0);
                oh[rw + 4 * t] = hi;
                if (z == 0) {
                    float2 hf = unpk2(hi);
                    g_Ql[rw + 4 * t] = cvt2(v1 - hf.y, v0 - hf.x);
                }
            }
        }
    }
}

// ---------------------------------------------------------------------------
// Kernel 3: output projection (frozen).
// ---------------------------------------------------------------------------
__global__ void __launch_bounds__(128, 2) out_hmma(
    const float* __restrict__ bo, float* __restrict__ out)
{
    extern __shared__ char sm[];
    const u32 sb  = smem_u32(sm);
    const int tid = threadIdx.x;
    const int m0  = blockIdx.x * 128;
    const int n0  = blockIdx.y * 64;

    float acc[2][8][4];
    #pragma unroll
    for (int mt = 0; mt < 2; mt++)
        #pragma unroll
        for (int t = 0; t < 8; t++)
            #pragma unroll
            for (int e = 0; e < 4; e++) acc[mt][t][e] = 0.0f;

    gemm_main(sb, acc, g_Ah, g_Al,
              g_Wth + (size_t)3 * 256 * ROW_WORDS, m0, n0, tid);

    const int w  = tid >> 5;
    const int L  = tid & 31;
    const int lr = L >> 2, lcq = L & 3;
    float b2[8][2];
    #pragma unroll
    for (int t = 0; t < 8; t++) {
        b2[t][0] = bo[n0 + 8 * t + lcq * 2];
        b2[t][1] = bo[n0 + 8 * t + lcq * 2 + 1];
    }
    #pragma unroll
    for (int mt = 0; mt < 2; mt++) {
        #pragma unroll
        for (int half = 0; half < 2; half++) {
            int m = m0 + w * 32 + mt * 16 + lr + half * 8;
            float* orow = out + (size_t)m * D_ + n0 + lcq * 2;
            #pragma unroll
            for (int t = 0; t < 8; t++) {
                float2 v;
                v.x = acc[mt][t][half * 2 + 0] + b2[t][0];
                v.y = acc[mt][t][half * 2 + 1] + b2[t][1];
                *(float2*)&orow[8 * t] = v;
            }
        }
    }
}

// ---------------------------------------------------------------------------
// Kernel 2: flash attention, mt2: BQ=128 via 4 warps x 32 rows.
// S 2-term, PV 1-term, split-KV x2, 3-deep KV ring, 1 barrier/iter.
// K/V fragments feed BOTH mt halves -> smem bytes per MAC halved.
// grid (S/128, BH*2), block 128, 2 CTAs/SM.
// ---------------------------------------------------------------------------
#define BUF_STRIDE 16384
#define ATTN_SMEM  (3 * 16384)
#define ONES2 0x3C003C00u

__global__ void __launch_bounds__(128, 2) attn_kernel()
{
    extern __shared__ char sm[];
    const u32 sb  = smem_u32(sm);
    const int tid = threadIdx.x;
    const int w   = tid >> 5;
    const int L   = tid & 31;
    const int bh   = blockIdx.y >> 1;
    const int half = blockIdx.y & 1;
    const int q0  = blockIdx.x * 128;

    const size_t head = (size_t)bh * S_ * (DH_ / 2);
    const size_t koff = (size_t)half * 2048 * 32;
    const u32* Qh = g_Qh + head;        const u32* Ql = g_Ql + head;
    const u32* Kh = g_Kh + head + koff;
    const u32* Vh = g_Vh + head + koff;

    const int rt = L & 7;
    const int lb = (L >> 3) & 1;
    const int lc = L >> 4;

    // ---- prologue: stage Q (hi->buf0, lo->buf1; 128 rows x 128B each) ----
    #pragma unroll
    for (int i = 0; i < 8; i++) {
        int idx = tid + i * 128;           // < 1024
        int r = idx >> 3, c = idx & 7;
        cp16(sb + swz(r, c),         Qh + (size_t)(q0 + r) * 32 + c * 4);
        cp16(sb + 16384 + swz(r, c), Ql + (size_t)(q0 + r) * 32 + c * 4);
    }
    CP_COMMIT();
    CP_WAIT(0);
    __syncthreads();

    u32 qh[2][4][4], ql[2][4][4];
    #pragma unroll
    for (int j = 0; j < 4; j++)
        #pragma unroll
        for (int mt = 0; mt < 2; mt++) {
            int row = w * 32 + mt * 16 + rt + lb * 8;
            LDSM_A(qh[mt][j], sb + swz(row, 2 * j + lc));
            LDSM_A(ql[mt][j], sb + 16384 + swz(row, 2 * j + lc));
        }
    __syncthreads();   // Q fully read before buffers reused for KV

    const u32* kvsrc[2] = {Kh, Vh};
    #pragma unroll
    for (int t0 = 0; t0 < 2; t0++) {
        u32 bufb = sb + t0 * BUF_STRIDE;
        #pragma unroll
        for (int m = 0; m < 2; m++)
            #pragma unroll
            for (int i = 0; i < 4; i++) {
                int idx = tid + i * 128;   // < 512
                int r = idx >> 3, c = idx & 7;
                cp16(bufb + m * 8192 + swz(r, c),
                     kvsrc[m] + (size_t)(t0 * 64 + r) * 32 + c * 4);
            }
        CP_COMMIT();
    }

    float oacc[2][8][4];
    #pragma unroll
    for (int mt = 0; mt < 2; mt++)
        #pragma unroll
        for (int t = 0; t < 8; t++)
            #pragma unroll
            for (int e = 0; e < 4; e++) oacc[mt][t][e] = 0.0f;
    float lacc[2][4] = {{0,0,0,0},{0,0,0,0}};
    float m_[2][2] = {{-CUDART_INF_F, -CUDART_INF_F},
                      {-CUDART_INF_F, -CUDART_INF_F}};

    const int NT = 2048 / 64;
    int rb = 0, wbuf = 2;
    for (int it = 0; it < NT; it++) {
        CP_WAIT(1);
        __syncthreads();   // single barrier per iteration

        if (it + 2 < NT) {
            u32 bb2 = sb + wbuf * BUF_STRIDE;
            int j2 = (it + 2) * 64;
            #pragma unroll
            for (int m = 0; m < 2; m++)
                #pragma unroll
                for (int i = 0; i < 4; i++) {
                    int idx = tid + i * 128;
                    int r = idx >> 3, c = idx & 7;
                    cp16(bb2 + m * 8192 + swz(r, c),
                         kvsrc[m] + (size_t)(j2 + r) * 32 + c * 4);
                }
        }
        CP_COMMIT();

        const u32 bufb = sb + rb * BUF_STRIDE;
        const u32 aKH = bufb, aVH = bufb + 8192;
        rb = (rb == 2) ? 0 : rb + 1;
        wbuf = (wbuf == 2) ? 0 : wbuf + 1;

        // ---- S = Q K^T (2-term, both mt share K frags) ----
        float sacc[2][8][4];
        #pragma unroll
        for (int mt = 0; mt < 2; mt++)
            #pragma unroll
            for (int t = 0; t < 8; t++)
                #pragma unroll
                for (int e = 0; e < 4; e++) sacc[mt][t][e] = 0.0f;

        u32 khf[2][4];
        LDSM_A(khf[0], aKH + swz(rt + lc * 8, lb));

        #pragma unroll
        for (int g = 0; g < 16; g++) {
            const int j = g >> 2, p = g & 3;
            const int cb = g & 1, nb = cb ^ 1;
            if (g + 1 < 16) {
                const int jn = (g + 1) >> 2, pn = (g + 1) & 3;
                int row = 16 * pn + rt + lc * 8;
                int ch  = 2 * jn + lb;
                LDSM_A(khf[nb], aKH + swz(row, ch));
            }
            mma16(sacc[0][2*p],   qh[0][j], khf[cb][0], khf[cb][1]);
            mma16(sacc[0][2*p+1], qh[0][j], khf[cb][2], khf[cb][3]);
            mma16(sacc[1][2*p],   qh[1][j], khf[cb][0], khf[cb][1]);
            mma16(sacc[1][2*p+1], qh[1][j], khf[cb][2], khf[cb][3]);
            mma16(sacc[0][2*p],   ql[0][j], khf[cb][0], khf[cb][1]);
            mma16(sacc[0][2*p+1], ql[0][j], khf[cb][2], khf[cb][3]);
            mma16(sacc[1][2*p],   ql[1][j], khf[cb][0], khf[cb][1]);
            mma16(sacc[1][2*p+1], ql[1][j], khf[cb][2], khf[cb][3]);
        }

        // ---- row max + rescale (log2 domain), per mt ----
        float mn[2][2];
        #pragma unroll
        for (int mt = 0; mt < 2; mt++) {
            float mlo = -CUDART_INF_F, mhi = -CUDART_INF_F;
            #pragma unroll
            for (int t = 0; t < 8; t++) {
                mlo = fmaxf(mlo, fmaxf(sacc[mt][t][0], sacc[mt][t][1]));
                mhi = fmaxf(mhi, fmaxf(sacc[mt][t][2], sacc[mt][t][3]));
            }
            mlo = fmaxf(mlo, __shfl_xor_sync(0xffffffffu, mlo, 1));
            mlo = fmaxf(mlo, __shfl_xor_sync(0xffffffffu, mlo, 2));
            mhi = fmaxf(mhi, __shfl_xor_sync(0xffffffffu, mhi, 1));
            mhi = fmaxf(mhi, __shfl_xor_sync(0xffffffffu, mhi, 2));

            float mnlo = fmaxf(m_[mt][0], mlo), mnhi = fmaxf(m_[mt][1], mhi);
            float clo = ex2f(m_[mt][0] - mnlo), chi = ex2f(m_[mt][1] - mnhi);
            m_[mt][0] = mnlo; m_[mt][1] = mnhi;
            mn[mt][0] = mnlo; mn[mt][1] = mnhi;

            #pragma unroll
            for (int t = 0; t < 8; t++) {
                oacc[mt][t][0] *= clo; oacc[mt][t][1] *= clo;
                oacc[mt][t][2] *= chi; oacc[mt][t][3] *= chi;
            }
            lacc[mt][0] *= clo;
            lacc[mt][2] *= chi;
        }

        // ---- PV + l: P = ex2.f16x2(s - m); both mt share V frags ----
        u32 vhf[2][4];
        LDSM_AT(vhf[0], aVH + swz(rt + lb * 8, lc));

        #pragma unroll
        for (int j = 0; j < 4; j++) {
            u32 pa[2][4];
            #pragma unroll
            for (int mt = 0; mt < 2; mt++) {
                #pragma unroll
                for (int tt = 0; tt < 2; tt++) {
                    const float* sv = sacc[mt][2 * j + tt];
                    pa[mt][2 * tt]     = ex2h2(cvt2(sv[1] - mn[mt][0], sv[0] - mn[mt][0]));
                    pa[mt][2 * tt + 1] = ex2h2(cvt2(sv[3] - mn[mt][1], sv[2] - mn[mt][1]));
                }
                mma16(lacc[mt], pa[mt], ONES2, ONES2);
            }
            #pragma unroll
            for (int t = 0; t < 4; t++) {
                const int g = j * 4 + t;
                const int cb = g & 1, nb = cb ^ 1;
                if (g + 1 < 16) {
                    const int jn = (g + 1) >> 2, tn = (g + 1) & 3;
                    int row = 16 * jn + rt + lb * 8;
                    int ch  = 2 * tn + lc;
                    LDSM_AT(vhf[nb], aVH + swz(row, ch));
                }
                mma16(oacc[0][2*t],   pa[0], vhf[cb][0], vhf[cb][1]);
                mma16(oacc[0][2*t+1], pa[0], vhf[cb][2], vhf[cb][3]);
                mma16(oacc[1][2*t],   pa[1], vhf[cb][0], vhf[cb][1]);
                mma16(oacc[1][2*t+1], pa[1], vhf[cb][2], vhf[cb][3]);
            }
        }
    }

    // ---- epilogue: fp16x2 UNNORMALIZED partials + (m,l) per row, per mt ----
    const size_t pbase = (size_t)(half * 16 + bh) * 4096;
    #pragma unroll
    for (int mt = 0; mt < 2; mt++) {
        const int rlo = q0 + w * 32 + mt * 16 + (L >> 2);
        u32* O0 = g_Op + (pbase + rlo)     * 32 + (L & 3);
        u32* O1 = g_Op + (pbase + rlo + 8) * 32 + (L & 3);
        #pragma unroll
        for (int t = 0; t < 8; t++) {
            O0[4 * t] = cvt2(oacc[mt][t][1], oacc[mt][t][0]);
            O1[4 * t] = cvt2(oacc[mt][t][3], oacc[mt][t][2]);
        }
        if ((L & 3) == 0) {
            g_m[pbase + rlo]     = m_[mt][0];  g_l[pbase + rlo]     = lacc[mt][0];
            g_m[pbase + rlo + 8] = m_[mt][1];  g_l[pbase + rlo + 8] = lacc[mt][2];
        }
    }
}

// ---------------------------------------------------------------------------
// Kernel 2b: combine fp16x2 split-KV halves (frozen).
// ---------------------------------------------------------------------------
__global__ void __launch_bounds__(256) combine_kernel()
{
    const int idx = blockIdx.x * 256 + threadIdx.x;
    const int bh  = idx >> 15;
    const int rem = idx & 32767;
    const int row = rem >> 3;
    const int q   = rem & 7;

    const int b0 = bh * 4096 + row;
    const int b1 = (16 + bh) * 4096 + row;
    const float m1 = g_m[b0], l1 = g_l[b0];
    const float m2 = g_m[b1], l2 = g_l[b1];
    const float ms = fmaxf(m1, m2);
    const float c1 = ex2f(m1 - ms), c2 = ex2f(m2 - ms);
    const float inv = 1.0f / (c1 * l1 + c2 * l2);
    const float s1 = c1 * inv, s2 = c2 * inv;

    uint4 w1 = *(const uint4*)(g_Op + (size_t)b0 * 32 + q * 4);
    uint4 w2 = *(const uint4*)(g_Op + (size_t)b1 * 32 + q * 4);
    const u32* w1p = (const u32*)&w1;
    const u32* w2p = (const u32*)&w2;

    uint4 oh, ol;
    u32* ohp = (u32*)&oh; u32* olp = (u32*)&ol;
    #pragma unroll
    for (int i = 0; i < 4; i++) {
        float2 a = unpk2(w1p[i]);
        float2 d = unpk2(w2p[i]);
        float v0 = s1 * a.x + s2 * d.x;
        float v1 = s1 * a.y + s2 * d.y;
        u32 h = cvt2(v1, v0);
        float2 hf = unpk2(h);
        ohp[i] = h;
        olp[i] = cvt2(v1 - hf.y, v0 - hf.x);
    }
    const size_t rw = ((size_t)((bh >> 2) * S_) + row) * ROW_WORDS
                      + (bh & 3) * 32 + q * 4;
    *(uint4*)(g_Ah + rw) = oh;
    *(uint4*)(g_Al + rw) = ol;
}

// ---------------------------------------------------------------------------
// Launch
// ---------------------------------------------------------------------------
extern "C" void kernel_launch(void* const* d_in, const int* in_sizes, int n_in,
                              void* d_out, int out_size)
{
    const float* X  = (const float*)d_in[0];
    const float* Wq = (const float*)d_in[1];
    const float* bq = (const float*)d_in[2];
    const float* Wk = (const float*)d_in[3];
    const float* bk = (const float*)d_in[4];
    const float* Wv = (const float*)d_in[5];
    const float* bv = (const float*)d_in[6];
    const float* Wo = (const float*)d_in[7];
    const float* bo = (const float*)d_in[8];
    float* out = (float*)d_out;

    cudaFuncSetAttribute(attn_kernel,
                         cudaFuncAttributeMaxDynamicSharedMemorySize, ATTN_SMEM);
    cudaFuncSetAttribute(qkv_hmma,
                         cudaFuncAttributeMaxDynamicSharedMemorySize, GEMM_SMEM);
    cudaFuncSetAttribute(out_hmma,
                         cudaFuncAttributeMaxDynamicSharedMemorySize, GEMM_SMEM);

    prep_kernel<<<(XWORDS + WWORDS + 255) / 256, 256>>>(X, Wq, Wk, Wv, Wo);
    qkv_hmma<<<dim3(MT_ / 128, H_, 3), 128, GEMM_SMEM>>>(bq, bk, bv);
    attn_kernel<<<dim3(S_ / 128, BH_ * 2), 128, ATTN_SMEM>>>();
    combine_kernel<<<2048, 256>>>();
    out_hmma<<<dim3(MT_ / 128, 4), 128, GEMM_SMEM>>>(bo, out);
}